// round 8
// baseline (speedup 1.0000x reference)
#include <cuda_runtime.h>
#include <cuda_bf16.h>
#include <cstdint>
#include <math.h>

// ---------------------------------------------------------------------------
// Problem constants
// ---------------------------------------------------------------------------
#define D_MODEL 1024
#define NHEADS  16
#define HDIM    64
#define WINDOW  256
#define BATCH   2
#define SEQ     2048
#define M_TOT   (BATCH * SEQ)     // 4096
#define KCAT    3072              // 3 * D_MODEL (hi|hi|lo split GEMM)
#define GCHUNK  64                // bf16 per K chunk (= one 128B SW128 row)
#define NCH     (KCAT / GCHUNK)   // 48

// ---------------------------------------------------------------------------
// Scratch (no cudaMalloc allowed)
// ---------------------------------------------------------------------------
__device__ __nv_bfloat16 g_acat[(size_t)M_TOT * KCAT];          // [4096][3072]
__device__ __nv_bfloat16 g_bcat[4][(size_t)D_MODEL * KCAT];     // [1024 n][3072 k]
__device__ __nv_bfloat16 g_qh[(size_t)M_TOT * D_MODEL];
__device__ __nv_bfloat16 g_ql[(size_t)M_TOT * D_MODEL];
__device__ __nv_bfloat16 g_kh[(size_t)M_TOT * D_MODEL];
__device__ __nv_bfloat16 g_kl[(size_t)M_TOT * D_MODEL];
__device__ __nv_bfloat16 g_vh[(size_t)M_TOT * D_MODEL];
__device__ __nv_bfloat16 g_vl[(size_t)M_TOT * D_MODEL];

// ---------------------------------------------------------------------------
// Helpers
// ---------------------------------------------------------------------------
__device__ __forceinline__ uint32_t smem_u32(const void* p) {
    uint32_t a;
    asm("{ .reg .u64 t; cvta.to.shared.u64 t, %1; cvt.u32.u64 %0, t; }" : "=r"(a) : "l"(p));
    return a;
}
__device__ __forceinline__ uint32_t swz128(uint32_t off) {
    return off ^ ((off >> 3) & 0x70);
}
__device__ __forceinline__ void cp_async16(uint32_t saddr, const void* gaddr) {
    asm volatile("cp.async.cg.shared.global [%0], [%1], 16;" :: "r"(saddr), "l"(gaddr));
}
__device__ __forceinline__ void cp_commit() {
    asm volatile("cp.async.commit_group;" ::: "memory");
}
__device__ __forceinline__ void cp_wait1() {
    asm volatile("cp.async.wait_group 1;" ::: "memory");
}
__device__ __forceinline__ void cp_wait0() {
    asm volatile("cp.async.wait_group 0;" ::: "memory");
}
__device__ __forceinline__ void ldmatrix_x4(uint32_t& r0, uint32_t& r1,
                                            uint32_t& r2, uint32_t& r3, uint32_t addr) {
    asm volatile("ldmatrix.sync.aligned.m8n8.x4.shared.b16 {%0,%1,%2,%3}, [%4];"
                 : "=r"(r0), "=r"(r1), "=r"(r2), "=r"(r3) : "r"(addr));
}
__device__ __forceinline__ void ldmatrix_x4t(uint32_t& r0, uint32_t& r1,
                                             uint32_t& r2, uint32_t& r3, uint32_t addr) {
    asm volatile("ldmatrix.sync.aligned.m8n8.x4.trans.shared.b16 {%0,%1,%2,%3}, [%4];"
                 : "=r"(r0), "=r"(r1), "=r"(r2), "=r"(r3) : "r"(addr));
}
__device__ __forceinline__ void mma16816(float* d, const uint32_t* a,
                                         uint32_t b0, uint32_t b1) {
    asm volatile(
        "mma.sync.aligned.m16n8k16.row.col.f32.bf16.bf16.f32 "
        "{%0,%1,%2,%3}, {%4,%5,%6,%7}, {%8,%9}, {%0,%1,%2,%3};"
        : "+f"(d[0]), "+f"(d[1]), "+f"(d[2]), "+f"(d[3])
        : "r"(a[0]), "r"(a[1]), "r"(a[2]), "r"(a[3]), "r"(b0), "r"(b1));
}
__device__ __forceinline__ uint32_t packbf(float a, float b) {
    uint16_t ua = __bfloat16_as_ushort(__float2bfloat16(a));
    uint16_t ub = __bfloat16_as_ushort(__float2bfloat16(b));
    return (uint32_t)ua | ((uint32_t)ub << 16);
}

// ---------------------------------------------------------------------------
// convA: src [M,1024] fp32 -> dst [M,3072] bf16 = [hi | hi | lo]
// ---------------------------------------------------------------------------
__global__ __launch_bounds__(256) void convA_kernel(const float* __restrict__ src,
                                                    __nv_bfloat16* __restrict__ dst)
{
    int idx = blockIdx.x * blockDim.x + threadIdx.x;
    float4 v = reinterpret_cast<const float4*>(src)[idx];
    int row = idx >> 8;
    int c4  = idx & 255;

    __nv_bfloat16 hx = __float2bfloat16(v.x), hy = __float2bfloat16(v.y);
    __nv_bfloat16 hz = __float2bfloat16(v.z), hw = __float2bfloat16(v.w);
    __nv_bfloat16 lx = __float2bfloat16(v.x - __bfloat162float(hx));
    __nv_bfloat16 ly = __float2bfloat16(v.y - __bfloat162float(hy));
    __nv_bfloat16 lz = __float2bfloat16(v.z - __bfloat162float(hz));
    __nv_bfloat16 lw = __float2bfloat16(v.w - __bfloat162float(hw));

    __nv_bfloat16* r = dst + (size_t)row * KCAT;
    __nv_bfloat162 h0; h0.x = hx; h0.y = hy;
    __nv_bfloat162 h1; h1.x = hz; h1.y = hw;
    __nv_bfloat162 l0; l0.x = lx; l0.y = ly;
    __nv_bfloat162 l1; l1.x = lz; l1.y = lw;
    __nv_bfloat162* p0 = reinterpret_cast<__nv_bfloat162*>(r) + c4 * 2;
    p0[0] = h0; p0[1] = h1;
    __nv_bfloat162* p1 = reinterpret_cast<__nv_bfloat162*>(r + D_MODEL) + c4 * 2;
    p1[0] = h0; p1[1] = h1;
    __nv_bfloat162* p2 = reinterpret_cast<__nv_bfloat162*>(r + 2 * D_MODEL) + c4 * 2;
    p2[0] = l0; p2[1] = l1;
}

// ---------------------------------------------------------------------------
// convW (all 4 weights, blockIdx.z selects): W[k][n] -> B[n][3072k] = [hi|lo|hi]
// ---------------------------------------------------------------------------
__global__ __launch_bounds__(256) void convW4_kernel(
    const float* __restrict__ W0, const float* __restrict__ W1,
    const float* __restrict__ W2, const float* __restrict__ W3,
    __nv_bfloat16* __restrict__ Bbase)
{
    __shared__ float tile[32][33];
    const float* W = (blockIdx.z == 0) ? W0 : (blockIdx.z == 1) ? W1
                     : (blockIdx.z == 2) ? W2 : W3;
    __nv_bfloat16* B = Bbase + (size_t)blockIdx.z * D_MODEL * KCAT;

    int n0 = blockIdx.x * 32;
    int k0 = blockIdx.y * 32;
    int tx = threadIdx.x, ty = threadIdx.y;   // (32, 8)

#pragma unroll
    for (int i = 0; i < 32; i += 8)
        tile[ty + i][tx] = W[(size_t)(k0 + ty + i) * D_MODEL + n0 + tx];
    __syncthreads();

#pragma unroll
    for (int i = 0; i < 32; i += 8) {
        int n = n0 + ty + i;
        int k = k0 + tx;
        float v = tile[tx][ty + i];
        __nv_bfloat16 hi = __float2bfloat16(v);
        __nv_bfloat16 lo = __float2bfloat16(v - __bfloat162float(hi));
        __nv_bfloat16* r = B + (size_t)n * KCAT;
        r[k]               = hi;
        r[D_MODEL + k]     = lo;
        r[2 * D_MODEL + k] = hi;
    }
}

// ---------------------------------------------------------------------------
// GEMM mainloop, CTA tile 128x256, 8 warps (2m x 4n) of 64x64 each.
// 3-stage cp.async pipeline, ONE barrier per chunk (wait->sync->load->compute).
// Stage s: A @ s*49152 (16K), B @ s*49152+16384 (32K).
// ---------------------------------------------------------------------------
#define GSTAGE 49152
#define GEMM_SMEM_BYTES (3 * GSTAGE + 1024)

__device__ __forceinline__ void gemm_mainloop(
    const __nv_bfloat16* __restrict__ A, const __nv_bfloat16* __restrict__ B,
    int m0, int n0, uint32_t tile_base, float (&acc)[4][8][4])
{
    const int tid = threadIdx.x;
    const int lane = tid & 31;
    const int wid = tid >> 5;
    const int warp_m = wid >> 2;     // 0..1
    const int warp_n = wid & 3;      // 0..3

#pragma unroll
    for (int i = 0; i < 4; i++)
#pragma unroll
        for (int j = 0; j < 8; j++)
#pragma unroll
            for (int r = 0; r < 4; r++) acc[i][j][r] = 0.0f;

    auto load_chunk = [&](int ch, int s) {
        const int kc = ch * GCHUNK;
        const uint32_t sa = tile_base + s * GSTAGE;
        const uint32_t sb = sa + 16384;
#pragma unroll
        for (int it = 0; it < 4; it++) {            // A: 128 rows x 128B
            int idx = it * 256 + tid;
            int row = idx >> 3;
            int seg = (idx & 7) << 4;
            uint32_t sw = swz128((uint32_t)(row * 128 + seg));
            cp_async16(sa + sw,
                       reinterpret_cast<const char*>(A + (size_t)(m0 + row) * KCAT + kc) + seg);
        }
#pragma unroll
        for (int it = 0; it < 8; it++) {            // B: 256 rows x 128B
            int idx = it * 256 + tid;
            int row = idx >> 3;
            int seg = (idx & 7) << 4;
            uint32_t sw = swz128((uint32_t)(row * 128 + seg));
            cp_async16(sb + sw,
                       reinterpret_cast<const char*>(B + (size_t)(n0 + row) * KCAT + kc) + seg);
        }
        cp_commit();
    };

    load_chunk(0, 0);
    load_chunk(1, 1);

    int scur = 0, snext = 2;
    for (int ch = 0; ch < NCH; ch++) {
        if (ch + 1 < NCH) cp_wait1(); else cp_wait0();
        __syncthreads();                       // all warps done reading stage snext
        if (ch + 2 < NCH) load_chunk(ch + 2, snext);

        const uint32_t baseA = tile_base + scur * GSTAGE;
        const uint32_t baseB = baseA + 16384;

#pragma unroll
        for (int step = 0; step < 4; step++) {
            uint32_t afr[4][4];
#pragma unroll
            for (int mt = 0; mt < 4; mt++) {
                int row = warp_m * 64 + mt * 16 + (lane & 15);
                int kb  = step * 32 + ((lane >> 4) << 4);
                uint32_t addr = baseA + swz128((uint32_t)(row * 128 + kb));
                ldmatrix_x4(afr[mt][0], afr[mt][1], afr[mt][2], afr[mt][3], addr);
            }
            uint32_t bfr[16];
#pragma unroll
            for (int jp = 0; jp < 4; jp++) {
                int nrow = warp_n * 64 + jp * 16 + ((lane >> 4) & 1) * 8 + (lane & 7);
                int kb   = step * 32 + ((lane >> 3) & 1) * 16;
                uint32_t addr = baseB + swz128((uint32_t)(nrow * 128 + kb));
                ldmatrix_x4(bfr[jp * 4 + 0], bfr[jp * 4 + 1],
                            bfr[jp * 4 + 2], bfr[jp * 4 + 3], addr);
            }
#pragma unroll
            for (int mt = 0; mt < 4; mt++)
#pragma unroll
                for (int nt = 0; nt < 8; nt++)
                    mma16816(acc[mt][nt], afr[mt],
                             bfr[(nt >> 1) * 4 + (nt & 1) * 2],
                             bfr[(nt >> 1) * 4 + (nt & 1) * 2 + 1]);
        }

        scur = (scur == 2) ? 0 : scur + 1;
        snext = (snext == 2) ? 0 : snext + 1;
    }
}

// ---------------------------------------------------------------------------
// QKV GEMM: one launch for all three projections.
// blockIdx.x: [0..11] -> matid = x>>2, n-tile = x&3 (256 wide). Split hi/lo out.
// ---------------------------------------------------------------------------
__global__ __launch_bounds__(256, 1) void qkv_mma_kernel(
    const __nv_bfloat16* __restrict__ A, const __nv_bfloat16* __restrict__ Bc,
    const float* __restrict__ bq, const float* __restrict__ bk, const float* __restrict__ bv,
    __nv_bfloat16* __restrict__ qh, __nv_bfloat16* __restrict__ ql,
    __nv_bfloat16* __restrict__ kh, __nv_bfloat16* __restrict__ kl,
    __nv_bfloat16* __restrict__ vh, __nv_bfloat16* __restrict__ vl)
{
    extern __shared__ char dynsmem[];
    uint32_t tile_base = (smem_u32(dynsmem) + 1023) & ~1023u;

    const int matid = blockIdx.x >> 2;
    const int n0 = (blockIdx.x & 3) * 256;
    const int m0 = blockIdx.y * 128;
    const __nv_bfloat16* B = Bc + (size_t)matid * D_MODEL * KCAT;
    const float* bias = (matid == 0) ? bq : (matid == 1) ? bk : bv;
    __nv_bfloat16* Oh = (matid == 0) ? qh : (matid == 1) ? kh : vh;
    __nv_bfloat16* Ol = (matid == 0) ? ql : (matid == 1) ? kl : vl;
    const float scale = (matid == 0) ? 0.125f : 1.0f;

    float acc[4][8][4];
    gemm_mainloop(A, B, m0, n0, tile_base, acc);

    const int lane = threadIdx.x & 31;
    const int wid = threadIdx.x >> 5;
    const int warp_m = wid >> 2, warp_n = wid & 3;
#pragma unroll
    for (int mt = 0; mt < 4; mt++) {
        int row = m0 + warp_m * 64 + mt * 16 + (lane >> 2);
#pragma unroll
        for (int nt = 0; nt < 8; nt++) {
            int col = n0 + warp_n * 64 + nt * 8 + (lane & 3) * 2;
            float b0 = bias[col], b1 = bias[col + 1];
            float v00 = (acc[mt][nt][0] + b0) * scale;
            float v01 = (acc[mt][nt][1] + b1) * scale;
            float v10 = (acc[mt][nt][2] + b0) * scale;
            float v11 = (acc[mt][nt][3] + b1) * scale;
            uint32_t h0 = packbf(v00, v01);
            uint32_t h1 = packbf(v10, v11);
            float r00 = v00 - __bfloat162float(__ushort_as_bfloat16((uint16_t)(h0 & 0xFFFF)));
            float r01 = v01 - __bfloat162float(__ushort_as_bfloat16((uint16_t)(h0 >> 16)));
            float r10 = v10 - __bfloat162float(__ushort_as_bfloat16((uint16_t)(h1 & 0xFFFF)));
            float r11 = v11 - __bfloat162float(__ushort_as_bfloat16((uint16_t)(h1 >> 16)));
            *reinterpret_cast<uint32_t*>(Oh + (size_t)row * D_MODEL + col) = h0;
            *reinterpret_cast<uint32_t*>(Oh + (size_t)(row + 8) * D_MODEL + col) = h1;
            *reinterpret_cast<uint32_t*>(Ol + (size_t)row * D_MODEL + col) = packbf(r00, r01);
            *reinterpret_cast<uint32_t*>(Ol + (size_t)(row + 8) * D_MODEL + col) = packbf(r10, r11);
        }
    }
}

// ---------------------------------------------------------------------------
// Output projection GEMM (fp32 epilogue)
// ---------------------------------------------------------------------------
__global__ __launch_bounds__(256, 1) void oproj_mma_kernel(
    const __nv_bfloat16* __restrict__ A, const __nv_bfloat16* __restrict__ B,
    const float* __restrict__ bias, float* __restrict__ C)
{
    extern __shared__ char dynsmem[];
    uint32_t tile_base = (smem_u32(dynsmem) + 1023) & ~1023u;

    const int n0 = blockIdx.x * 256;
    const int m0 = blockIdx.y * 128;

    float acc[4][8][4];
    gemm_mainloop(A, B, m0, n0, tile_base, acc);

    const int lane = threadIdx.x & 31;
    const int wid = threadIdx.x >> 5;
    const int warp_m = wid >> 2, warp_n = wid & 3;
#pragma unroll
    for (int mt = 0; mt < 4; mt++) {
        int row = m0 + warp_m * 64 + mt * 16 + (lane >> 2);
#pragma unroll
        for (int nt = 0; nt < 8; nt++) {
            int col = n0 + warp_n * 64 + nt * 8 + (lane & 3) * 2;
            float b0 = bias[col], b1 = bias[col + 1];
            float2 w0; w0.x = acc[mt][nt][0] + b0; w0.y = acc[mt][nt][1] + b1;
            float2 w1; w1.x = acc[mt][nt][2] + b0; w1.y = acc[mt][nt][3] + b1;
            *reinterpret_cast<float2*>(C + (size_t)row * D_MODEL + col) = w0;
            *reinterpret_cast<float2*>(C + (size_t)(row + 8) * D_MODEL + col) = w1;
        }
    }
}

// ---------------------------------------------------------------------------
// Tensor-core windowed attention (flash-style, split bf16 precision).
// CTA: 128 q rows x (head, batch). 4 warps x 32 rows. Key chunks of 64.
// Writes output directly into acat [hi | hi | lo] layout.
// ---------------------------------------------------------------------------
#define ATT_SMEM (96 * 1024 + 1024)

__global__ __launch_bounds__(128) void attn_tc_kernel(
    const __nv_bfloat16* __restrict__ qh, const __nv_bfloat16* __restrict__ ql,
    const __nv_bfloat16* __restrict__ kh, const __nv_bfloat16* __restrict__ kl,
    const __nv_bfloat16* __restrict__ vh, const __nv_bfloat16* __restrict__ vl,
    __nv_bfloat16* __restrict__ acat)
{
    extern __shared__ char dynsmem[];
    uint32_t base = (smem_u32(dynsmem) + 1023) & ~1023u;
    const uint32_t QHs = base;
    const uint32_t QLs = base + 16384;
    const uint32_t KV0 = base + 32768;
    const uint32_t KV1 = base + 65536;

    const int tid = threadIdx.x, wid = tid >> 5, lane = tid & 31;
    const int q0 = blockIdx.x * 128;
    const int h  = blockIdx.y;
    const int b  = blockIdx.z;
    const size_t rowbase = (size_t)b * SEQ + q0;
    const int hoff = h * HDIM;

    {
        const char* qhp = reinterpret_cast<const char*>(qh + rowbase * D_MODEL + hoff);
        const char* qlp = reinterpret_cast<const char*>(ql + rowbase * D_MODEL + hoff);
#pragma unroll
        for (int it = 0; it < 8; it++) {
            int idx = it * 128 + tid;
            int row = idx >> 3;
            int seg = (idx & 7) << 4;
            uint32_t sw = swz128((uint32_t)(row * 128 + seg));
            cp_async16(QHs + sw, qhp + (size_t)row * 2048 + seg);
            cp_async16(QLs + sw, qlp + (size_t)row * 2048 + seg);
        }
        cp_commit();
    }

    int c0 = q0 - WINDOW; if (c0 < 0) c0 = 0;
    const int nch = (q0 + 128 - c0) >> 6;

    auto load_kv = [&](int c, uint32_t kvb) {
        const char* sp0 = reinterpret_cast<const char*>(kh + ((size_t)b * SEQ + c) * D_MODEL + hoff);
        const char* sp1 = reinterpret_cast<const char*>(kl + ((size_t)b * SEQ + c) * D_MODEL + hoff);
        const char* sp2 = reinterpret_cast<const char*>(vh + ((size_t)b * SEQ + c) * D_MODEL + hoff);
        const char* sp3 = reinterpret_cast<const char*>(vl + ((size_t)b * SEQ + c) * D_MODEL + hoff);
#pragma unroll
        for (int it = 0; it < 4; it++) {
            int idx = it * 128 + tid;
            int row = idx >> 3;
            int seg = (idx & 7) << 4;
            uint32_t sw = swz128((uint32_t)(row * 128 + seg));
            size_t go = (size_t)row * 2048 + seg;
            cp_async16(kvb + 0     + sw, sp0 + go);
            cp_async16(kvb + 8192  + sw, sp1 + go);
            cp_async16(kvb + 16384 + sw, sp2 + go);
            cp_async16(kvb + 24576 + sw, sp3 + go);
        }
        cp_commit();
    };

    load_kv(c0, KV0);

    float O[2][8][4];
#pragma unroll
    for (int mt = 0; mt < 2; mt++)
#pragma unroll
        for (int nt = 0; nt < 8; nt++)
#pragma unroll
            for (int r = 0; r < 4; r++) O[mt][nt][r] = 0.0f;
    float mrow[2][2] = {{-1e30f, -1e30f}, {-1e30f, -1e30f}};
    float lrow[2][2] = {{0.f, 0.f}, {0.f, 0.f}};

    const float NEGINF = __int_as_float(0xff800000);

    for (int ch = 0; ch < nch; ch++) {
        const uint32_t kvb = (ch & 1) ? KV1 : KV0;
        if (ch + 1 < nch) {
            load_kv(c0 + (ch + 1) * 64, (ch & 1) ? KV0 : KV1);
            cp_wait1();
        } else {
            cp_wait0();
        }
        __syncthreads();

        const int c = c0 + ch * 64;

        float S[2][8][4];
#pragma unroll
        for (int mt = 0; mt < 2; mt++)
#pragma unroll
            for (int nt = 0; nt < 8; nt++)
#pragma unroll
                for (int r = 0; r < 4; r++) S[mt][nt][r] = 0.0f;

#pragma unroll
        for (int kt = 0; kt < 4; kt++) {
            uint32_t qa[2][4], qla[2][4];
#pragma unroll
            for (int mt = 0; mt < 2; mt++) {
                int row = wid * 32 + mt * 16 + (lane & 15);
                int kb  = kt * 32 + ((lane >> 4) << 4);
                uint32_t sw = swz128((uint32_t)(row * 128 + kb));
                ldmatrix_x4(qa[mt][0], qa[mt][1], qa[mt][2], qa[mt][3], QHs + sw);
                ldmatrix_x4(qla[mt][0], qla[mt][1], qla[mt][2], qla[mt][3], QLs + sw);
            }
#pragma unroll
            for (int np = 0; np < 4; np++) {
                int nr = np * 16 + ((lane >> 4) & 1) * 8 + (lane & 7);
                int kb = kt * 32 + ((lane >> 3) & 1) * 16;
                uint32_t sw = swz128((uint32_t)(nr * 128 + kb));
                uint32_t kf[4], klf[4];
                ldmatrix_x4(kf[0], kf[1], kf[2], kf[3], kvb + 0 + sw);
                ldmatrix_x4(klf[0], klf[1], klf[2], klf[3], kvb + 8192 + sw);
#pragma unroll
                for (int mt = 0; mt < 2; mt++)
#pragma unroll
                    for (int half = 0; half < 2; half++) {
                        int nt = np * 2 + half;
                        mma16816(S[mt][nt], qa[mt],  kf[half * 2],  kf[half * 2 + 1]);
                        mma16816(S[mt][nt], qa[mt],  klf[half * 2], klf[half * 2 + 1]);
                        mma16816(S[mt][nt], qla[mt], kf[half * 2],  kf[half * 2 + 1]);
                    }
            }
        }

        uint32_t Phi[2][4][4], Plo[2][4][4];
#pragma unroll
        for (int mt = 0; mt < 2; mt++) {
            int i0 = q0 + wid * 32 + mt * 16 + (lane >> 2);
            int i1 = i0 + 8;
#pragma unroll
            for (int nt = 0; nt < 8; nt++) {
                int j = c + nt * 8 + (lane & 3) * 2;
                if (j     > i0 || j     < i0 - WINDOW) S[mt][nt][0] = NEGINF;
                if (j + 1 > i0 || j + 1 < i0 - WINDOW) S[mt][nt][1] = NEGINF;
                if (j     > i1 || j     < i1 - WINDOW) S[mt][nt][2] = NEGINF;
                if (j + 1 > i1 || j + 1 < i1 - WINDOW) S[mt][nt][3] = NEGINF;
            }
#pragma unroll
            for (int half = 0; half < 2; half++) {
                float cm = NEGINF;
#pragma unroll
                for (int nt = 0; nt < 8; nt++)
                    cm = fmaxf(cm, fmaxf(S[mt][nt][half * 2], S[mt][nt][half * 2 + 1]));
                cm = fmaxf(cm, __shfl_xor_sync(0xffffffffu, cm, 1));
                cm = fmaxf(cm, __shfl_xor_sync(0xffffffffu, cm, 2));
                float mold = mrow[mt][half];
                float mnew = fmaxf(mold, cm);
                float corr = __expf(mold - mnew);
                mrow[mt][half] = mnew;
                float psum = 0.0f;
#pragma unroll
                for (int nt = 0; nt < 8; nt++) {
                    float p0 = __expf(S[mt][nt][half * 2]     - mnew);
                    float p1 = __expf(S[mt][nt][half * 2 + 1] - mnew);
                    psum += p0 + p1;
                    O[mt][nt][half * 2]     *= corr;
                    O[mt][nt][half * 2 + 1] *= corr;
                    uint32_t hp = packbf(p0, p1);
                    float r0 = p0 - __bfloat162float(__ushort_as_bfloat16((uint16_t)(hp & 0xFFFF)));
                    float r1 = p1 - __bfloat162float(__ushort_as_bfloat16((uint16_t)(hp >> 16)));
                    int kt = nt >> 1, hh = nt & 1;
                    Phi[mt][kt][hh * 2 + half] = hp;
                    Plo[mt][kt][hh * 2 + half] = packbf(r0, r1);
                }
                psum += __shfl_xor_sync(0xffffffffu, psum, 1);
                psum += __shfl_xor_sync(0xffffffffu, psum, 2);
                lrow[mt][half] = lrow[mt][half] * corr + psum;
            }
        }

#pragma unroll
        for (int kt = 0; kt < 4; kt++) {
#pragma unroll
            for (int np = 0; np < 4; np++) {
                int g = lane >> 3;
                int key = kt * 16 + (g & 1) * 8 + (lane & 7);
                int nb  = np * 32 + ((g >> 1) << 4);
                uint32_t sw = swz128((uint32_t)(key * 128 + nb));
                uint32_t vf[4], vlf[4];
                ldmatrix_x4t(vf[0], vf[1], vf[2], vf[3], kvb + 16384 + sw);
                ldmatrix_x4t(vlf[0], vlf[1], vlf[2], vlf[3], kvb + 24576 + sw);
#pragma unroll
                for (int mt = 0; mt < 2; mt++)
#pragma unroll
                    for (int half = 0; half < 2; half++) {
                        int nt = np * 2 + half;
                        mma16816(O[mt][nt], Phi[mt][kt], vf[half * 2],  vf[half * 2 + 1]);
                        mma16816(O[mt][nt], Phi[mt][kt], vlf[half * 2], vlf[half * 2 + 1]);
                        mma16816(O[mt][nt], Plo[mt][kt], vf[half * 2],  vf[half * 2 + 1]);
                    }
            }
        }
        __syncthreads();
    }

#pragma unroll
    for (int mt = 0; mt < 2; mt++) {
        size_t rA = rowbase + wid * 32 + mt * 16 + (lane >> 2);
        size_t rB = rA + 8;
        float inv0 = 1.0f / lrow[mt][0];
        float inv1 = 1.0f / lrow[mt][1];
#pragma unroll
        for (int nt = 0; nt < 8; nt++) {
            int col = hoff + nt * 8 + (lane & 3) * 2;
            float o00 = O[mt][nt][0] * inv0, o01 = O[mt][nt][1] * inv0;
            float o10 = O[mt][nt][2] * inv1, o11 = O[mt][nt][3] * inv1;
            uint32_t hA = packbf(o00, o01);
            uint32_t hB = packbf(o10, o11);
            float a0 = o00 - __bfloat162float(__ushort_as_bfloat16((uint16_t)(hA & 0xFFFF)));
            float a1 = o01 - __bfloat162float(__ushort_as_bfloat16((uint16_t)(hA >> 16)));
            float b0 = o10 - __bfloat162float(__ushort_as_bfloat16((uint16_t)(hB & 0xFFFF)));
            float b1 = o11 - __bfloat162float(__ushort_as_bfloat16((uint16_t)(hB >> 16)));
            uint32_t lA = packbf(a0, a1);
            uint32_t lB = packbf(b0, b1);
            __nv_bfloat16* pA = acat + rA * KCAT + col;
            __nv_bfloat16* pB = acat + rB * KCAT + col;
            *reinterpret_cast<uint32_t*>(pA) = hA;
            *reinterpret_cast<uint32_t*>(pA + D_MODEL) = hA;
            *reinterpret_cast<uint32_t*>(pA + 2 * D_MODEL) = lA;
            *reinterpret_cast<uint32_t*>(pB) = hB;
            *reinterpret_cast<uint32_t*>(pB + D_MODEL) = hB;
            *reinterpret_cast<uint32_t*>(pB + 2 * D_MODEL) = lB;
        }
    }
}

// ---------------------------------------------------------------------------
// Launch.  Inputs: x, Wq, bq, Wk, bk, Wv, bv, Wo, bo
// ---------------------------------------------------------------------------
extern "C" void kernel_launch(void* const* d_in, const int* in_sizes, int n_in,
                              void* d_out, int out_size)
{
    const float* x  = (const float*)d_in[0];
    const float* Wq = (const float*)d_in[1];
    const float* bq = (const float*)d_in[2];
    const float* Wk = (const float*)d_in[3];
    const float* bk = (const float*)d_in[4];
    const float* Wv = (const float*)d_in[5];
    const float* bv = (const float*)d_in[6];
    const float* Wo = (const float*)d_in[7];
    const float* bo = (const float*)d_in[8];
    float* out = (float*)d_out;

    __nv_bfloat16 *acat, *bcat, *qh, *ql, *kh, *kl, *vh, *vl;
    cudaGetSymbolAddress((void**)&acat, g_acat);
    cudaGetSymbolAddress((void**)&bcat, g_bcat);
    cudaGetSymbolAddress((void**)&qh, g_qh);
    cudaGetSymbolAddress((void**)&ql, g_ql);
    cudaGetSymbolAddress((void**)&kh, g_kh);
    cudaGetSymbolAddress((void**)&kl, g_kl);
    cudaGetSymbolAddress((void**)&vh, g_vh);
    cudaGetSymbolAddress((void**)&vl, g_vl);

    cudaFuncSetAttribute(qkv_mma_kernel,
                         cudaFuncAttributeMaxDynamicSharedMemorySize, GEMM_SMEM_BYTES);
    cudaFuncSetAttribute(oproj_mma_kernel,
                         cudaFuncAttributeMaxDynamicSharedMemorySize, GEMM_SMEM_BYTES);
    cudaFuncSetAttribute(attn_tc_kernel,
                         cudaFuncAttributeMaxDynamicSharedMemorySize, ATT_SMEM);

    const size_t WSTRIDE = (size_t)D_MODEL * KCAT;

    convA_kernel<<<M_TOT * D_MODEL / 4 / 256, 256>>>(x, acat);
    dim3 cw_grid(32, 32, 4), cw_blk(32, 8);
    convW4_kernel<<<cw_grid, cw_blk>>>(Wq, Wk, Wv, Wo, bcat);

    // fused QKV projections -> split bf16 (Q pre-scaled by 0.125)
    dim3 qkv_grid(12, 32);
    qkv_mma_kernel<<<qkv_grid, 256, GEMM_SMEM_BYTES>>>(acat, bcat, bq, bk, bv,
                                                       qh, ql, kh, kl, vh, vl);

    // tensor-core windowed attention -> writes acat [hi|hi|lo] directly
    dim3 attn_grid(SEQ / 128, NHEADS, BATCH);    // (16, 16, 2)
    attn_tc_kernel<<<attn_grid, 128, ATT_SMEM>>>(qh, ql, kh, kl, vh, vl, acat);

    // output projection -> fp32
    dim3 o_grid(4, 32);
    oproj_mma_kernel<<<o_grid, 256, GEMM_SMEM_BYTES>>>(acat, bcat + 3 * WSTRIDE, bo, out);
}

// round 9
// speedup vs baseline: 1.0335x; 1.0335x over previous
#include <cuda_runtime.h>
#include <cuda_bf16.h>
#include <cstdint>
#include <math.h>

// ---------------------------------------------------------------------------
// Problem constants
// ---------------------------------------------------------------------------
#define D_MODEL 1024
#define NHEADS  16
#define HDIM    64
#define WINDOW  256
#define BATCH   2
#define SEQ     2048
#define M_TOT   (BATCH * SEQ)     // 4096
#define ACAT_W  2048              // [hi | lo] layout width
#define NPROD   48                // 16 k-chunks x 3 products (AhBh, AhBl, AlBh)

// ---------------------------------------------------------------------------
// Scratch (no cudaMalloc allowed)
// ---------------------------------------------------------------------------
__device__ __nv_bfloat16 g_acat[(size_t)M_TOT * ACAT_W];        // [4096][2048]
__device__ __nv_bfloat16 g_bcat[4][(size_t)D_MODEL * ACAT_W];   // [1024 n][2048 k]
__device__ __nv_bfloat16 g_qh[(size_t)M_TOT * D_MODEL];
__device__ __nv_bfloat16 g_ql[(size_t)M_TOT * D_MODEL];
__device__ __nv_bfloat16 g_kh[(size_t)M_TOT * D_MODEL];
__device__ __nv_bfloat16 g_kl[(size_t)M_TOT * D_MODEL];
__device__ __nv_bfloat16 g_vh[(size_t)M_TOT * D_MODEL];
__device__ __nv_bfloat16 g_vl[(size_t)M_TOT * D_MODEL];

// ---------------------------------------------------------------------------
// Helpers
// ---------------------------------------------------------------------------
__device__ __forceinline__ uint32_t smem_u32(const void* p) {
    uint32_t a;
    asm("{ .reg .u64 t; cvta.to.shared.u64 t, %1; cvt.u32.u64 %0, t; }" : "=r"(a) : "l"(p));
    return a;
}
__device__ __forceinline__ uint32_t swz128(uint32_t off) {
    return off ^ ((off >> 3) & 0x70);
}
__device__ __forceinline__ void cp_async16(uint32_t saddr, const void* gaddr) {
    asm volatile("cp.async.cg.shared.global [%0], [%1], 16;" :: "r"(saddr), "l"(gaddr));
}
__device__ __forceinline__ void cp_commit() {
    asm volatile("cp.async.commit_group;" ::: "memory");
}
__device__ __forceinline__ void cp_wait1() {
    asm volatile("cp.async.wait_group 1;" ::: "memory");
}
__device__ __forceinline__ void cp_wait0() {
    asm volatile("cp.async.wait_group 0;" ::: "memory");
}
__device__ __forceinline__ void ldmatrix_x4(uint32_t& r0, uint32_t& r1,
                                            uint32_t& r2, uint32_t& r3, uint32_t addr) {
    asm volatile("ldmatrix.sync.aligned.m8n8.x4.shared.b16 {%0,%1,%2,%3}, [%4];"
                 : "=r"(r0), "=r"(r1), "=r"(r2), "=r"(r3) : "r"(addr));
}
__device__ __forceinline__ void ldmatrix_x4t(uint32_t& r0, uint32_t& r1,
                                             uint32_t& r2, uint32_t& r3, uint32_t addr) {
    asm volatile("ldmatrix.sync.aligned.m8n8.x4.trans.shared.b16 {%0,%1,%2,%3}, [%4];"
                 : "=r"(r0), "=r"(r1), "=r"(r2), "=r"(r3) : "r"(addr));
}
__device__ __forceinline__ void mma16816(float* d, const uint32_t* a,
                                         uint32_t b0, uint32_t b1) {
    asm volatile(
        "mma.sync.aligned.m16n8k16.row.col.f32.bf16.bf16.f32 "
        "{%0,%1,%2,%3}, {%4,%5,%6,%7}, {%8,%9}, {%0,%1,%2,%3};"
        : "+f"(d[0]), "+f"(d[1]), "+f"(d[2]), "+f"(d[3])
        : "r"(a[0]), "r"(a[1]), "r"(a[2]), "r"(a[3]), "r"(b0), "r"(b1));
}
__device__ __forceinline__ uint32_t packbf(float a, float b) {
    uint16_t ua = __bfloat16_as_ushort(__float2bfloat16(a));
    uint16_t ub = __bfloat16_as_ushort(__float2bfloat16(b));
    return (uint32_t)ua | ((uint32_t)ub << 16);
}

// ---------------------------------------------------------------------------
// convA: src [M,1024] fp32 -> dst [M,2048] bf16 = [hi | lo]
// ---------------------------------------------------------------------------
__global__ __launch_bounds__(256) void convA_kernel(const float* __restrict__ src,
                                                    __nv_bfloat16* __restrict__ dst)
{
    int idx = blockIdx.x * blockDim.x + threadIdx.x;
    float4 v = reinterpret_cast<const float4*>(src)[idx];
    int row = idx >> 8;
    int c4  = idx & 255;

    __nv_bfloat16 hx = __float2bfloat16(v.x), hy = __float2bfloat16(v.y);
    __nv_bfloat16 hz = __float2bfloat16(v.z), hw = __float2bfloat16(v.w);
    __nv_bfloat16 lx = __float2bfloat16(v.x - __bfloat162float(hx));
    __nv_bfloat16 ly = __float2bfloat16(v.y - __bfloat162float(hy));
    __nv_bfloat16 lz = __float2bfloat16(v.z - __bfloat162float(hz));
    __nv_bfloat16 lw = __float2bfloat16(v.w - __bfloat162float(hw));

    __nv_bfloat16* r = dst + (size_t)row * ACAT_W;
    __nv_bfloat162 h0; h0.x = hx; h0.y = hy;
    __nv_bfloat162 h1; h1.x = hz; h1.y = hw;
    __nv_bfloat162 l0; l0.x = lx; l0.y = ly;
    __nv_bfloat162 l1; l1.x = lz; l1.y = lw;
    __nv_bfloat162* p0 = reinterpret_cast<__nv_bfloat162*>(r) + c4 * 2;
    p0[0] = h0; p0[1] = h1;
    __nv_bfloat162* p1 = reinterpret_cast<__nv_bfloat162*>(r + D_MODEL) + c4 * 2;
    p1[0] = l0; p1[1] = l1;
}

// ---------------------------------------------------------------------------
// convW (all 4 weights, blockIdx.z selects): W[k][n] -> B[n][2048] = [hi | lo]
// ---------------------------------------------------------------------------
__global__ __launch_bounds__(256) void convW4_kernel(
    const float* __restrict__ W0, const float* __restrict__ W1,
    const float* __restrict__ W2, const float* __restrict__ W3,
    __nv_bfloat16* __restrict__ Bbase)
{
    __shared__ float tile[32][33];
    const float* W = (blockIdx.z == 0) ? W0 : (blockIdx.z == 1) ? W1
                     : (blockIdx.z == 2) ? W2 : W3;
    __nv_bfloat16* B = Bbase + (size_t)blockIdx.z * D_MODEL * ACAT_W;

    int n0 = blockIdx.x * 32;
    int k0 = blockIdx.y * 32;
    int tx = threadIdx.x, ty = threadIdx.y;   // (32, 8)

#pragma unroll
    for (int i = 0; i < 32; i += 8)
        tile[ty + i][tx] = W[(size_t)(k0 + ty + i) * D_MODEL + n0 + tx];
    __syncthreads();

#pragma unroll
    for (int i = 0; i < 32; i += 8) {
        int n = n0 + ty + i;
        int k = k0 + tx;
        float v = tile[tx][ty + i];
        __nv_bfloat16 hi = __float2bfloat16(v);
        __nv_bfloat16 lo = __float2bfloat16(v - __bfloat162float(hi));
        __nv_bfloat16* r = B + (size_t)n * ACAT_W;
        r[k]           = hi;
        r[D_MODEL + k] = lo;
    }
}

// ---------------------------------------------------------------------------
// GEMM mainloop, CTA tile 128x128, 8 warps (2m x 4n) of 64x32 each.
// Product schedule per k-chunk (64 K elems): (Ah*Bh), (Ah*Bl), (Al*Bh).
// Each product loads at most one NEW 16KB tile. A-ring x3, B-ring x4.
// One barrier per product: wait -> sync -> load(p+2) -> compute.
// ---------------------------------------------------------------------------
#define GEMM_SMEM_BYTES (7 * 16384 + 1024)   // 3 A slots + 4 B slots + align

__device__ __forceinline__ void load_tile128(uint32_t dst, const __nv_bfloat16* src,
                                             int row0, int col0, int tid)
{
    // 128 rows x 64 bf16 (128B per row), SW128 swizzle
#pragma unroll
    for (int it = 0; it < 4; it++) {
        int idx = it * 256 + tid;
        int row = idx >> 3;
        int seg = (idx & 7) << 4;
        uint32_t sw = swz128((uint32_t)(row * 128 + seg));
        cp_async16(dst + sw,
                   reinterpret_cast<const char*>(src + (size_t)(row0 + row) * ACAT_W + col0) + seg);
    }
}

__device__ __forceinline__ void gemm_mainloop(
    const __nv_bfloat16* __restrict__ A, const __nv_bfloat16* __restrict__ B,
    int m0, int n0, uint32_t base, float (&acc)[4][4][4])
{
    const int tid = threadIdx.x;
    const int lane = tid & 31;
    const int wid = tid >> 5;
    const int warp_m = wid >> 2;     // 0..1
    const int warp_n = wid & 3;      // 0..3
    const uint32_t abase = base;             // 3 x 16KB
    const uint32_t bbase = base + 49152;     // 4 x 16KB

#pragma unroll
    for (int i = 0; i < 4; i++)
#pragma unroll
        for (int j = 0; j < 4; j++)
#pragma unroll
            for (int r = 0; r < 4; r++) acc[i][j][r] = 0.0f;

    auto loadp = [&](int p) {
        int k = p / 3, t = p - 3 * k;
        if (t == 0) {
            load_tile128(abase + ((2 * k) % 3) * 16384, A, m0, k * 64, tid);
            load_tile128(bbase + ((2 * k) & 3) * 16384, B, n0, k * 64, tid);
        } else if (t == 1) {
            load_tile128(bbase + ((2 * k + 1) & 3) * 16384, B, n0, D_MODEL + k * 64, tid);
        } else {
            load_tile128(abase + ((2 * k + 1) % 3) * 16384, A, m0, D_MODEL + k * 64, tid);
        }
        cp_commit();
    };

    loadp(0);
    loadp(1);

    for (int p = 0; p < NPROD; p++) {
        if (p + 1 < NPROD) cp_wait1(); else cp_wait0();
        __syncthreads();
        if (p + 2 < NPROD) loadp(p + 2);

        const int k = p / 3, t = p - 3 * k;
        const uint32_t baseA = abase + ((2 * k + (t == 2 ? 1 : 0)) % 3) * 16384;
        const uint32_t baseB = bbase + ((2 * k + (t == 1 ? 1 : 0)) & 3) * 16384;

#pragma unroll
        for (int step = 0; step < 4; step++) {
            uint32_t afr[4][4];
#pragma unroll
            for (int mt = 0; mt < 4; mt++) {
                int row = warp_m * 64 + mt * 16 + (lane & 15);
                int kb  = step * 32 + ((lane >> 4) << 4);
                uint32_t addr = baseA + swz128((uint32_t)(row * 128 + kb));
                ldmatrix_x4(afr[mt][0], afr[mt][1], afr[mt][2], afr[mt][3], addr);
            }
            uint32_t bfr[8];
#pragma unroll
            for (int jp = 0; jp < 2; jp++) {
                int nrow = warp_n * 32 + jp * 16 + ((lane >> 4) & 1) * 8 + (lane & 7);
                int kb   = step * 32 + ((lane >> 3) & 1) * 16;
                uint32_t addr = baseB + swz128((uint32_t)(nrow * 128 + kb));
                ldmatrix_x4(bfr[jp * 4 + 0], bfr[jp * 4 + 1],
                            bfr[jp * 4 + 2], bfr[jp * 4 + 3], addr);
            }
#pragma unroll
            for (int mt = 0; mt < 4; mt++)
#pragma unroll
                for (int nt = 0; nt < 4; nt++)
                    mma16816(acc[mt][nt], afr[mt], bfr[nt * 2], bfr[nt * 2 + 1]);
        }
    }
}

// ---------------------------------------------------------------------------
// QKV GEMM: one launch for all three projections.
// blockIdx.x: [0..23] -> matid = x>>3, n-tile = x&7. Split bf16 hi/lo output.
// ---------------------------------------------------------------------------
__global__ __launch_bounds__(256, 2) void qkv_mma_kernel(
    const __nv_bfloat16* __restrict__ A, const __nv_bfloat16* __restrict__ Bc,
    const float* __restrict__ bq, const float* __restrict__ bk, const float* __restrict__ bv,
    __nv_bfloat16* __restrict__ qh, __nv_bfloat16* __restrict__ ql,
    __nv_bfloat16* __restrict__ kh, __nv_bfloat16* __restrict__ kl,
    __nv_bfloat16* __restrict__ vh, __nv_bfloat16* __restrict__ vl)
{
    extern __shared__ char dynsmem[];
    uint32_t tile_base = (smem_u32(dynsmem) + 1023) & ~1023u;

    const int matid = blockIdx.x >> 3;
    const int n0 = (blockIdx.x & 7) * 128;
    const int m0 = blockIdx.y * 128;
    const __nv_bfloat16* B = Bc + (size_t)matid * D_MODEL * ACAT_W;
    const float* bias = (matid == 0) ? bq : (matid == 1) ? bk : bv;
    __nv_bfloat16* Oh = (matid == 0) ? qh : (matid == 1) ? kh : vh;
    __nv_bfloat16* Ol = (matid == 0) ? ql : (matid == 1) ? kl : vl;
    const float scale = (matid == 0) ? 0.125f : 1.0f;

    float acc[4][4][4];
    gemm_mainloop(A, B, m0, n0, tile_base, acc);

    const int lane = threadIdx.x & 31;
    const int wid = threadIdx.x >> 5;
    const int warp_m = wid >> 2, warp_n = wid & 3;
#pragma unroll
    for (int mt = 0; mt < 4; mt++) {
        int row = m0 + warp_m * 64 + mt * 16 + (lane >> 2);
#pragma unroll
        for (int nt = 0; nt < 4; nt++) {
            int col = n0 + warp_n * 32 + nt * 8 + (lane & 3) * 2;
            float b0 = bias[col], b1 = bias[col + 1];
            float v00 = (acc[mt][nt][0] + b0) * scale;
            float v01 = (acc[mt][nt][1] + b1) * scale;
            float v10 = (acc[mt][nt][2] + b0) * scale;
            float v11 = (acc[mt][nt][3] + b1) * scale;
            uint32_t h0 = packbf(v00, v01);
            uint32_t h1 = packbf(v10, v11);
            float r00 = v00 - __bfloat162float(__ushort_as_bfloat16((uint16_t)(h0 & 0xFFFF)));
            float r01 = v01 - __bfloat162float(__ushort_as_bfloat16((uint16_t)(h0 >> 16)));
            float r10 = v10 - __bfloat162float(__ushort_as_bfloat16((uint16_t)(h1 & 0xFFFF)));
            float r11 = v11 - __bfloat162float(__ushort_as_bfloat16((uint16_t)(h1 >> 16)));
            *reinterpret_cast<uint32_t*>(Oh + (size_t)row * D_MODEL + col) = h0;
            *reinterpret_cast<uint32_t*>(Oh + (size_t)(row + 8) * D_MODEL + col) = h1;
            *reinterpret_cast<uint32_t*>(Ol + (size_t)row * D_MODEL + col) = packbf(r00, r01);
            *reinterpret_cast<uint32_t*>(Ol + (size_t)(row + 8) * D_MODEL + col) = packbf(r10, r11);
        }
    }
}

// ---------------------------------------------------------------------------
// Output projection GEMM (fp32 epilogue)
// ---------------------------------------------------------------------------
__global__ __launch_bounds__(256, 2) void oproj_mma_kernel(
    const __nv_bfloat16* __restrict__ A, const __nv_bfloat16* __restrict__ B,
    const float* __restrict__ bias, float* __restrict__ C)
{
    extern __shared__ char dynsmem[];
    uint32_t tile_base = (smem_u32(dynsmem) + 1023) & ~1023u;

    const int n0 = blockIdx.x * 128;
    const int m0 = blockIdx.y * 128;

    float acc[4][4][4];
    gemm_mainloop(A, B, m0, n0, tile_base, acc);

    const int lane = threadIdx.x & 31;
    const int wid = threadIdx.x >> 5;
    const int warp_m = wid >> 2, warp_n = wid & 3;
#pragma unroll
    for (int mt = 0; mt < 4; mt++) {
        int row = m0 + warp_m * 64 + mt * 16 + (lane >> 2);
#pragma unroll
        for (int nt = 0; nt < 4; nt++) {
            int col = n0 + warp_n * 32 + nt * 8 + (lane & 3) * 2;
            float b0 = bias[col], b1 = bias[col + 1];
            float2 w0; w0.x = acc[mt][nt][0] + b0; w0.y = acc[mt][nt][1] + b1;
            float2 w1; w1.x = acc[mt][nt][2] + b0; w1.y = acc[mt][nt][3] + b1;
            *reinterpret_cast<float2*>(C + (size_t)row * D_MODEL + col) = w0;
            *reinterpret_cast<float2*>(C + (size_t)(row + 8) * D_MODEL + col) = w1;
        }
    }
}

// ---------------------------------------------------------------------------
// Tensor-core windowed attention (flash-style, split bf16 precision).
// CTA: 128 q rows x (head, batch). 4 warps x 32 rows. Key chunks of 64.
// Writes output directly into acat [hi | lo] layout.
// ---------------------------------------------------------------------------
#define ATT_SMEM (96 * 1024 + 1024)

__global__ __launch_bounds__(128) void attn_tc_kernel(
    const __nv_bfloat16* __restrict__ qh, const __nv_bfloat16* __restrict__ ql,
    const __nv_bfloat16* __restrict__ kh, const __nv_bfloat16* __restrict__ kl,
    const __nv_bfloat16* __restrict__ vh, const __nv_bfloat16* __restrict__ vl,
    __nv_bfloat16* __restrict__ acat)
{
    extern __shared__ char dynsmem[];
    uint32_t base = (smem_u32(dynsmem) + 1023) & ~1023u;
    const uint32_t QHs = base;
    const uint32_t QLs = base + 16384;
    const uint32_t KV0 = base + 32768;
    const uint32_t KV1 = base + 65536;

    const int tid = threadIdx.x, wid = tid >> 5, lane = tid & 31;
    const int q0 = blockIdx.x * 128;
    const int h  = blockIdx.y;
    const int b  = blockIdx.z;
    const size_t rowbase = (size_t)b * SEQ + q0;
    const int hoff = h * HDIM;

    {
        const char* qhp = reinterpret_cast<const char*>(qh + rowbase * D_MODEL + hoff);
        const char* qlp = reinterpret_cast<const char*>(ql + rowbase * D_MODEL + hoff);
#pragma unroll
        for (int it = 0; it < 8; it++) {
            int idx = it * 128 + tid;
            int row = idx >> 3;
            int seg = (idx & 7) << 4;
            uint32_t sw = swz128((uint32_t)(row * 128 + seg));
            cp_async16(QHs + sw, qhp + (size_t)row * 2048 + seg);
            cp_async16(QLs + sw, qlp + (size_t)row * 2048 + seg);
        }
        cp_commit();
    }

    int c0 = q0 - WINDOW; if (c0 < 0) c0 = 0;
    const int nch = (q0 + 128 - c0) >> 6;

    auto load_kv = [&](int c, uint32_t kvb) {
        const char* sp0 = reinterpret_cast<const char*>(kh + ((size_t)b * SEQ + c) * D_MODEL + hoff);
        const char* sp1 = reinterpret_cast<const char*>(kl + ((size_t)b * SEQ + c) * D_MODEL + hoff);
        const char* sp2 = reinterpret_cast<const char*>(vh + ((size_t)b * SEQ + c) * D_MODEL + hoff);
        const char* sp3 = reinterpret_cast<const char*>(vl + ((size_t)b * SEQ + c) * D_MODEL + hoff);
#pragma unroll
        for (int it = 0; it < 4; it++) {
            int idx = it * 128 + tid;
            int row = idx >> 3;
            int seg = (idx & 7) << 4;
            uint32_t sw = swz128((uint32_t)(row * 128 + seg));
            size_t go = (size_t)row * 2048 + seg;
            cp_async16(kvb + 0     + sw, sp0 + go);
            cp_async16(kvb + 8192  + sw, sp1 + go);
            cp_async16(kvb + 16384 + sw, sp2 + go);
            cp_async16(kvb + 24576 + sw, sp3 + go);
        }
        cp_commit();
    };

    load_kv(c0, KV0);

    float O[2][8][4];
#pragma unroll
    for (int mt = 0; mt < 2; mt++)
#pragma unroll
        for (int nt = 0; nt < 8; nt++)
#pragma unroll
            for (int r = 0; r < 4; r++) O[mt][nt][r] = 0.0f;
    float mrow[2][2] = {{-1e30f, -1e30f}, {-1e30f, -1e30f}};
    float lrow[2][2] = {{0.f, 0.f}, {0.f, 0.f}};

    const float NEGINF = __int_as_float(0xff800000);

    for (int ch = 0; ch < nch; ch++) {
        const uint32_t kvb = (ch & 1) ? KV1 : KV0;
        if (ch + 1 < nch) {
            load_kv(c0 + (ch + 1) * 64, (ch & 1) ? KV0 : KV1);
            cp_wait1();
        } else {
            cp_wait0();
        }
        __syncthreads();

        const int c = c0 + ch * 64;

        float S[2][8][4];
#pragma unroll
        for (int mt = 0; mt < 2; mt++)
#pragma unroll
            for (int nt = 0; nt < 8; nt++)
#pragma unroll
                for (int r = 0; r < 4; r++) S[mt][nt][r] = 0.0f;

#pragma unroll
        for (int kt = 0; kt < 4; kt++) {
            uint32_t qa[2][4], qla[2][4];
#pragma unroll
            for (int mt = 0; mt < 2; mt++) {
                int row = wid * 32 + mt * 16 + (lane & 15);
                int kb  = kt * 32 + ((lane >> 4) << 4);
                uint32_t sw = swz128((uint32_t)(row * 128 + kb));
                ldmatrix_x4(qa[mt][0], qa[mt][1], qa[mt][2], qa[mt][3], QHs + sw);
                ldmatrix_x4(qla[mt][0], qla[mt][1], qla[mt][2], qla[mt][3], QLs + sw);
            }
#pragma unroll
            for (int np = 0; np < 4; np++) {
                int nr = np * 16 + ((lane >> 4) & 1) * 8 + (lane & 7);
                int kb = kt * 32 + ((lane >> 3) & 1) * 16;
                uint32_t sw = swz128((uint32_t)(nr * 128 + kb));
                uint32_t kf[4], klf[4];
                ldmatrix_x4(kf[0], kf[1], kf[2], kf[3], kvb + 0 + sw);
                ldmatrix_x4(klf[0], klf[1], klf[2], klf[3], kvb + 8192 + sw);
#pragma unroll
                for (int mt = 0; mt < 2; mt++)
#pragma unroll
                    for (int half = 0; half < 2; half++) {
                        int nt = np * 2 + half;
                        mma16816(S[mt][nt], qa[mt],  kf[half * 2],  kf[half * 2 + 1]);
                        mma16816(S[mt][nt], qa[mt],  klf[half * 2], klf[half * 2 + 1]);
                        mma16816(S[mt][nt], qla[mt], kf[half * 2],  kf[half * 2 + 1]);
                    }
            }
        }

        uint32_t Phi[2][4][4], Plo[2][4][4];
#pragma unroll
        for (int mt = 0; mt < 2; mt++) {
            int i0 = q0 + wid * 32 + mt * 16 + (lane >> 2);
            int i1 = i0 + 8;
#pragma unroll
            for (int nt = 0; nt < 8; nt++) {
                int j = c + nt * 8 + (lane & 3) * 2;
                if (j     > i0 || j     < i0 - WINDOW) S[mt][nt][0] = NEGINF;
                if (j + 1 > i0 || j + 1 < i0 - WINDOW) S[mt][nt][1] = NEGINF;
                if (j     > i1 || j     < i1 - WINDOW) S[mt][nt][2] = NEGINF;
                if (j + 1 > i1 || j + 1 < i1 - WINDOW) S[mt][nt][3] = NEGINF;
            }
#pragma unroll
            for (int half = 0; half < 2; half++) {
                float cm = NEGINF;
#pragma unroll
                for (int nt = 0; nt < 8; nt++)
                    cm = fmaxf(cm, fmaxf(S[mt][nt][half * 2], S[mt][nt][half * 2 + 1]));
                cm = fmaxf(cm, __shfl_xor_sync(0xffffffffu, cm, 1));
                cm = fmaxf(cm, __shfl_xor_sync(0xffffffffu, cm, 2));
                float mold = mrow[mt][half];
                float mnew = fmaxf(mold, cm);
                float corr = __expf(mold - mnew);
                mrow[mt][half] = mnew;
                float psum = 0.0f;
#pragma unroll
                for (int nt = 0; nt < 8; nt++) {
                    float p0 = __expf(S[mt][nt][half * 2]     - mnew);
                    float p1 = __expf(S[mt][nt][half * 2 + 1] - mnew);
                    psum += p0 + p1;
                    O[mt][nt][half * 2]     *= corr;
                    O[mt][nt][half * 2 + 1] *= corr;
                    uint32_t hp = packbf(p0, p1);
                    float r0 = p0 - __bfloat162float(__ushort_as_bfloat16((uint16_t)(hp & 0xFFFF)));
                    float r1 = p1 - __bfloat162float(__ushort_as_bfloat16((uint16_t)(hp >> 16)));
                    int kt = nt >> 1, hh = nt & 1;
                    Phi[mt][kt][hh * 2 + half] = hp;
                    Plo[mt][kt][hh * 2 + half] = packbf(r0, r1);
                }
                psum += __shfl_xor_sync(0xffffffffu, psum, 1);
                psum += __shfl_xor_sync(0xffffffffu, psum, 2);
                lrow[mt][half] = lrow[mt][half] * corr + psum;
            }
        }

#pragma unroll
        for (int kt = 0; kt < 4; kt++) {
#pragma unroll
            for (int np = 0; np < 4; np++) {
                int g = lane >> 3;
                int key = kt * 16 + (g & 1) * 8 + (lane & 7);
                int nb  = np * 32 + ((g >> 1) << 4);
                uint32_t sw = swz128((uint32_t)(key * 128 + nb));
                uint32_t vf[4], vlf[4];
                ldmatrix_x4t(vf[0], vf[1], vf[2], vf[3], kvb + 16384 + sw);
                ldmatrix_x4t(vlf[0], vlf[1], vlf[2], vlf[3], kvb + 24576 + sw);
#pragma unroll
                for (int mt = 0; mt < 2; mt++)
#pragma unroll
                    for (int half = 0; half < 2; half++) {
                        int nt = np * 2 + half;
                        mma16816(O[mt][nt], Phi[mt][kt], vf[half * 2],  vf[half * 2 + 1]);
                        mma16816(O[mt][nt], Phi[mt][kt], vlf[half * 2], vlf[half * 2 + 1]);
                        mma16816(O[mt][nt], Plo[mt][kt], vf[half * 2],  vf[half * 2 + 1]);
                    }
            }
        }
        __syncthreads();
    }

    // normalize + write acat [hi | lo]
#pragma unroll
    for (int mt = 0; mt < 2; mt++) {
        size_t rA = rowbase + wid * 32 + mt * 16 + (lane >> 2);
        size_t rB = rA + 8;
        float inv0 = 1.0f / lrow[mt][0];
        float inv1 = 1.0f / lrow[mt][1];
#pragma unroll
        for (int nt = 0; nt < 8; nt++) {
            int col = hoff + nt * 8 + (lane & 3) * 2;
            float o00 = O[mt][nt][0] * inv0, o01 = O[mt][nt][1] * inv0;
            float o10 = O[mt][nt][2] * inv1, o11 = O[mt][nt][3] * inv1;
            uint32_t hA = packbf(o00, o01);
            uint32_t hB = packbf(o10, o11);
            float a0 = o00 - __bfloat162float(__ushort_as_bfloat16((uint16_t)(hA & 0xFFFF)));
            float a1 = o01 - __bfloat162float(__ushort_as_bfloat16((uint16_t)(hA >> 16)));
            float b0 = o10 - __bfloat162float(__ushort_as_bfloat16((uint16_t)(hB & 0xFFFF)));
            float b1 = o11 - __bfloat162float(__ushort_as_bfloat16((uint16_t)(hB >> 16)));
            __nv_bfloat16* pA = acat + rA * ACAT_W + col;
            __nv_bfloat16* pB = acat + rB * ACAT_W + col;
            *reinterpret_cast<uint32_t*>(pA) = hA;
            *reinterpret_cast<uint32_t*>(pA + D_MODEL) = packbf(a0, a1);
            *reinterpret_cast<uint32_t*>(pB) = hB;
            *reinterpret_cast<uint32_t*>(pB + D_MODEL) = packbf(b0, b1);
        }
    }
}

// ---------------------------------------------------------------------------
// Launch.  Inputs: x, Wq, bq, Wk, bk, Wv, bv, Wo, bo
// ---------------------------------------------------------------------------
extern "C" void kernel_launch(void* const* d_in, const int* in_sizes, int n_in,
                              void* d_out, int out_size)
{
    const float* x  = (const float*)d_in[0];
    const float* Wq = (const float*)d_in[1];
    const float* bq = (const float*)d_in[2];
    const float* Wk = (const float*)d_in[3];
    const float* bk = (const float*)d_in[4];
    const float* Wv = (const float*)d_in[5];
    const float* bv = (const float*)d_in[6];
    const float* Wo = (const float*)d_in[7];
    const float* bo = (const float*)d_in[8];
    float* out = (float*)d_out;

    __nv_bfloat16 *acat, *bcat, *qh, *ql, *kh, *kl, *vh, *vl;
    cudaGetSymbolAddress((void**)&acat, g_acat);
    cudaGetSymbolAddress((void**)&bcat, g_bcat);
    cudaGetSymbolAddress((void**)&qh, g_qh);
    cudaGetSymbolAddress((void**)&ql, g_ql);
    cudaGetSymbolAddress((void**)&kh, g_kh);
    cudaGetSymbolAddress((void**)&kl, g_kl);
    cudaGetSymbolAddress((void**)&vh, g_vh);
    cudaGetSymbolAddress((void**)&vl, g_vl);

    cudaFuncSetAttribute(qkv_mma_kernel,
                         cudaFuncAttributeMaxDynamicSharedMemorySize, GEMM_SMEM_BYTES);
    cudaFuncSetAttribute(oproj_mma_kernel,
                         cudaFuncAttributeMaxDynamicSharedMemorySize, GEMM_SMEM_BYTES);
    cudaFuncSetAttribute(attn_tc_kernel,
                         cudaFuncAttributeMaxDynamicSharedMemorySize, ATT_SMEM);

    const size_t WSTRIDE = (size_t)D_MODEL * ACAT_W;

    convA_kernel<<<M_TOT * D_MODEL / 4 / 256, 256>>>(x, acat);
    dim3 cw_grid(32, 32, 4), cw_blk(32, 8);
    convW4_kernel<<<cw_grid, cw_blk>>>(Wq, Wk, Wv, Wo, bcat);

    // fused QKV projections -> split bf16 (Q pre-scaled by 0.125)
    dim3 qkv_grid(24, 32);
    qkv_mma_kernel<<<qkv_grid, 256, GEMM_SMEM_BYTES>>>(acat, bcat, bq, bk, bv,
                                                       qh, ql, kh, kl, vh, vl);

    // tensor-core windowed attention -> writes acat [hi|lo] directly
    dim3 attn_grid(SEQ / 128, NHEADS, BATCH);    // (16, 16, 2)
    attn_tc_kernel<<<attn_grid, 128, ATT_SMEM>>>(qh, ql, kh, kl, vh, vl, acat);

    // output projection -> fp32
    dim3 o_grid(8, 32);
    oproj_mma_kernel<<<o_grid, 256, GEMM_SMEM_BYTES>>>(acat, bcat + 3 * WSTRIDE, bo, out);
}

// round 10
// speedup vs baseline: 1.5475x; 1.4973x over previous
#include <cuda_runtime.h>
#include <cuda_fp16.h>
#include <cstdint>
#include <math.h>

// ---------------------------------------------------------------------------
// Problem constants
// ---------------------------------------------------------------------------
#define D_MODEL 1024
#define NHEADS  16
#define HDIM    64
#define WINDOW  256
#define BATCH   2
#define SEQ     2048
#define M_TOT   (BATCH * SEQ)     // 4096
#define ACAT_W  2048              // [hi | lo] fp16 A-split width
#define NPROD   32                // 16 k-chunks x 2 products (Ah*W, Al*W)

// ---------------------------------------------------------------------------
// Scratch (no cudaMalloc allowed)
// ---------------------------------------------------------------------------
__device__ __half g_acat[(size_t)M_TOT * ACAT_W];        // [4096][2048] fp16
__device__ __half g_bcat[4][(size_t)D_MODEL * D_MODEL];  // [1024 n][1024 k] fp16
__device__ __half g_q16[(size_t)M_TOT * D_MODEL];
__device__ __half g_k16[(size_t)M_TOT * D_MODEL];
__device__ __half g_v16[(size_t)M_TOT * D_MODEL];

// ---------------------------------------------------------------------------
// Helpers
// ---------------------------------------------------------------------------
__device__ __forceinline__ uint32_t smem_u32(const void* p) {
    uint32_t a;
    asm("{ .reg .u64 t; cvta.to.shared.u64 t, %1; cvt.u32.u64 %0, t; }" : "=r"(a) : "l"(p));
    return a;
}
__device__ __forceinline__ uint32_t swz128(uint32_t off) {
    return off ^ ((off >> 3) & 0x70);
}
__device__ __forceinline__ void cp_async16(uint32_t saddr, const void* gaddr) {
    asm volatile("cp.async.cg.shared.global [%0], [%1], 16;" :: "r"(saddr), "l"(gaddr));
}
__device__ __forceinline__ void cp_commit() {
    asm volatile("cp.async.commit_group;" ::: "memory");
}
__device__ __forceinline__ void cp_wait1() {
    asm volatile("cp.async.wait_group 1;" ::: "memory");
}
__device__ __forceinline__ void cp_wait0() {
    asm volatile("cp.async.wait_group 0;" ::: "memory");
}
__device__ __forceinline__ void ldmatrix_x4(uint32_t& r0, uint32_t& r1,
                                            uint32_t& r2, uint32_t& r3, uint32_t addr) {
    asm volatile("ldmatrix.sync.aligned.m8n8.x4.shared.b16 {%0,%1,%2,%3}, [%4];"
                 : "=r"(r0), "=r"(r1), "=r"(r2), "=r"(r3) : "r"(addr));
}
__device__ __forceinline__ void ldmatrix_x4t(uint32_t& r0, uint32_t& r1,
                                             uint32_t& r2, uint32_t& r3, uint32_t addr) {
    asm volatile("ldmatrix.sync.aligned.m8n8.x4.trans.shared.b16 {%0,%1,%2,%3}, [%4];"
                 : "=r"(r0), "=r"(r1), "=r"(r2), "=r"(r3) : "r"(addr));
}
// fp16 MMA, fp32 accum
__device__ __forceinline__ void mma16816h(float* d, const uint32_t* a,
                                          uint32_t b0, uint32_t b1) {
    asm volatile(
        "mma.sync.aligned.m16n8k16.row.col.f32.f16.f16.f32 "
        "{%0,%1,%2,%3}, {%4,%5,%6,%7}, {%8,%9}, {%0,%1,%2,%3};"
        : "+f"(d[0]), "+f"(d[1]), "+f"(d[2]), "+f"(d[3])
        : "r"(a[0]), "r"(a[1]), "r"(a[2]), "r"(a[3]), "r"(b0), "r"(b1));
}
__device__ __forceinline__ uint32_t packh(float a, float b) {
    __half2 h = __floats2half2_rn(a, b);
    return *reinterpret_cast<uint32_t*>(&h);
}
__device__ __forceinline__ void unpackh(uint32_t p, float& a, float& b) {
    __half2 h = *reinterpret_cast<__half2*>(&p);
    a = __half2float(h.x); b = __half2float(h.y);
}

// ---------------------------------------------------------------------------
// convA: src [M,1024] fp32 -> dst [M,2048] fp16 = [hi | lo]  (exact A split)
// ---------------------------------------------------------------------------
__global__ __launch_bounds__(256) void convA_kernel(const float* __restrict__ src,
                                                    __half* __restrict__ dst)
{
    int idx = blockIdx.x * blockDim.x + threadIdx.x;
    float4 v = reinterpret_cast<const float4*>(src)[idx];
    int row = idx >> 8;
    int c4  = idx & 255;

    __half hx = __float2half(v.x), hy = __float2half(v.y);
    __half hz = __float2half(v.z), hw = __float2half(v.w);
    float lx = v.x - __half2float(hx), ly = v.y - __half2float(hy);
    float lz = v.z - __half2float(hz), lw = v.w - __half2float(hw);

    __half* r = dst + (size_t)row * ACAT_W;
    uint32_t* p0 = reinterpret_cast<uint32_t*>(r) + c4 * 2;
    __half2 h0; h0.x = hx; h0.y = hy;
    __half2 h1; h1.x = hz; h1.y = hw;
    p0[0] = *reinterpret_cast<uint32_t*>(&h0);
    p0[1] = *reinterpret_cast<uint32_t*>(&h1);
    uint32_t* p1 = reinterpret_cast<uint32_t*>(r + D_MODEL) + c4 * 2;
    p1[0] = packh(lx, ly);
    p1[1] = packh(lz, lw);
}

// ---------------------------------------------------------------------------
// convW (all 4 weights, blockIdx.z selects): W[k][n] fp32 -> B[n][1024k] fp16
// ---------------------------------------------------------------------------
__global__ __launch_bounds__(256) void convW4_kernel(
    const float* __restrict__ W0, const float* __restrict__ W1,
    const float* __restrict__ W2, const float* __restrict__ W3,
    __half* __restrict__ Bbase)
{
    __shared__ float tile[32][33];
    const float* W = (blockIdx.z == 0) ? W0 : (blockIdx.z == 1) ? W1
                     : (blockIdx.z == 2) ? W2 : W3;
    __half* B = Bbase + (size_t)blockIdx.z * D_MODEL * D_MODEL;

    int n0 = blockIdx.x * 32;
    int k0 = blockIdx.y * 32;
    int tx = threadIdx.x, ty = threadIdx.y;   // (32, 8)

#pragma unroll
    for (int i = 0; i < 32; i += 8)
        tile[ty + i][tx] = W[(size_t)(k0 + ty + i) * D_MODEL + n0 + tx];
    __syncthreads();

#pragma unroll
    for (int i = 0; i < 32; i += 8) {
        int n = n0 + ty + i;
        int k = k0 + tx;
        B[(size_t)n * D_MODEL + k] = __float2half(tile[tx][ty + i]);
    }
}

// ---------------------------------------------------------------------------
// GEMM mainloop, CTA tile 128x128, 8 warps (2m x 4n) of 64x32 each.
// fp16 2-term: products per k-chunk: (Ah*W), (Al*W). W tile shared.
// A-ring x3 (16KB), W-ring x2 (16KB). One barrier per product.
// ---------------------------------------------------------------------------
#define GEMM_SMEM_BYTES (5 * 16384 + 1024)

__device__ __forceinline__ void load_tile128(uint32_t dst, const __half* src,
                                             int row0, int col0, int stride, int tid)
{
    // 128 rows x 64 fp16 (128B per row), SW128 swizzle
#pragma unroll
    for (int it = 0; it < 4; it++) {
        int idx = it * 256 + tid;
        int row = idx >> 3;
        int seg = (idx & 7) << 4;
        uint32_t sw = swz128((uint32_t)(row * 128 + seg));
        cp_async16(dst + sw,
                   reinterpret_cast<const char*>(src + (size_t)(row0 + row) * stride + col0) + seg);
    }
}

__device__ __forceinline__ void gemm_mainloop(
    const __half* __restrict__ A, const __half* __restrict__ B,
    int m0, int n0, uint32_t base, float (&acc)[4][4][4])
{
    const int tid = threadIdx.x;
    const int lane = tid & 31;
    const int wid = tid >> 5;
    const int warp_m = wid >> 2;     // 0..1
    const int warp_n = wid & 3;      // 0..3
    const uint32_t abase = base;             // 3 x 16KB
    const uint32_t wbase = base + 49152;     // 2 x 16KB

#pragma unroll
    for (int i = 0; i < 4; i++)
#pragma unroll
        for (int j = 0; j < 4; j++)
#pragma unroll
            for (int r = 0; r < 4; r++) acc[i][j][r] = 0.0f;

    auto loadp = [&](int p) {
        int k = p >> 1, t = p & 1;
        load_tile128(abase + (p % 3) * 16384, A, m0, t * D_MODEL + k * 64, ACAT_W, tid);
        if (t == 0)
            load_tile128(wbase + (k & 1) * 16384, B, n0, k * 64, D_MODEL, tid);
        cp_commit();
    };

    loadp(0);
    loadp(1);

    for (int p = 0; p < NPROD; p++) {
        if (p + 1 < NPROD) cp_wait1(); else cp_wait0();
        __syncthreads();
        if (p + 2 < NPROD) loadp(p + 2);

        const uint32_t baseA = abase + (p % 3) * 16384;
        const uint32_t baseB = wbase + ((p >> 1) & 1) * 16384;

#pragma unroll
        for (int step = 0; step < 4; step++) {
            uint32_t afr[4][4];
#pragma unroll
            for (int mt = 0; mt < 4; mt++) {
                int row = warp_m * 64 + mt * 16 + (lane & 15);
                int kb  = step * 32 + ((lane >> 4) << 4);
                uint32_t addr = baseA + swz128((uint32_t)(row * 128 + kb));
                ldmatrix_x4(afr[mt][0], afr[mt][1], afr[mt][2], afr[mt][3], addr);
            }
            uint32_t bfr[8];
#pragma unroll
            for (int jp = 0; jp < 2; jp++) {
                int nrow = warp_n * 32 + jp * 16 + ((lane >> 4) & 1) * 8 + (lane & 7);
                int kb   = step * 32 + ((lane >> 3) & 1) * 16;
                uint32_t addr = baseB + swz128((uint32_t)(nrow * 128 + kb));
                ldmatrix_x4(bfr[jp * 4 + 0], bfr[jp * 4 + 1],
                            bfr[jp * 4 + 2], bfr[jp * 4 + 3], addr);
            }
#pragma unroll
            for (int mt = 0; mt < 4; mt++)
#pragma unroll
                for (int nt = 0; nt < 4; nt++)
                    mma16816h(acc[mt][nt], afr[mt], bfr[nt * 2], bfr[nt * 2 + 1]);
        }
    }
}

// ---------------------------------------------------------------------------
// QKV GEMM: one launch for all three projections.
// blockIdx.x: [0..23] -> matid = x>>3, n-tile = x&7. fp16 single output.
// ---------------------------------------------------------------------------
__global__ __launch_bounds__(256, 2) void qkv_mma_kernel(
    const __half* __restrict__ A, const __half* __restrict__ Bc,
    const float* __restrict__ bq, const float* __restrict__ bk, const float* __restrict__ bv,
    __half* __restrict__ q16, __half* __restrict__ k16, __half* __restrict__ v16)
{
    extern __shared__ char dynsmem[];
    uint32_t tile_base = (smem_u32(dynsmem) + 1023) & ~1023u;

    const int matid = blockIdx.x >> 3;
    const int n0 = (blockIdx.x & 7) * 128;
    const int m0 = blockIdx.y * 128;
    const __half* B = Bc + (size_t)matid * D_MODEL * D_MODEL;
    const float* bias = (matid == 0) ? bq : (matid == 1) ? bk : bv;
    __half* O = (matid == 0) ? q16 : (matid == 1) ? k16 : v16;
    const float scale = (matid == 0) ? 0.125f : 1.0f;

    float acc[4][4][4];
    gemm_mainloop(A, B, m0, n0, tile_base, acc);

    const int lane = threadIdx.x & 31;
    const int wid = threadIdx.x >> 5;
    const int warp_m = wid >> 2, warp_n = wid & 3;
#pragma unroll
    for (int mt = 0; mt < 4; mt++) {
        int row = m0 + warp_m * 64 + mt * 16 + (lane >> 2);
#pragma unroll
        for (int nt = 0; nt < 4; nt++) {
            int col = n0 + warp_n * 32 + nt * 8 + (lane & 3) * 2;
            float b0 = bias[col], b1 = bias[col + 1];
            *reinterpret_cast<uint32_t*>(O + (size_t)row * D_MODEL + col) =
                packh((acc[mt][nt][0] + b0) * scale, (acc[mt][nt][1] + b1) * scale);
            *reinterpret_cast<uint32_t*>(O + (size_t)(row + 8) * D_MODEL + col) =
                packh((acc[mt][nt][2] + b0) * scale, (acc[mt][nt][3] + b1) * scale);
        }
    }
}

// ---------------------------------------------------------------------------
// Output projection GEMM (fp32 epilogue)
// ---------------------------------------------------------------------------
__global__ __launch_bounds__(256, 2) void oproj_mma_kernel(
    const __half* __restrict__ A, const __half* __restrict__ B,
    const float* __restrict__ bias, float* __restrict__ C)
{
    extern __shared__ char dynsmem[];
    uint32_t tile_base = (smem_u32(dynsmem) + 1023) & ~1023u;

    const int n0 = blockIdx.x * 128;
    const int m0 = blockIdx.y * 128;

    float acc[4][4][4];
    gemm_mainloop(A, B, m0, n0, tile_base, acc);

    const int lane = threadIdx.x & 31;
    const int wid = threadIdx.x >> 5;
    const int warp_m = wid >> 2, warp_n = wid & 3;
#pragma unroll
    for (int mt = 0; mt < 4; mt++) {
        int row = m0 + warp_m * 64 + mt * 16 + (lane >> 2);
#pragma unroll
        for (int nt = 0; nt < 4; nt++) {
            int col = n0 + warp_n * 32 + nt * 8 + (lane & 3) * 2;
            float b0 = bias[col], b1 = bias[col + 1];
            float2 w0; w0.x = acc[mt][nt][0] + b0; w0.y = acc[mt][nt][1] + b1;
            float2 w1; w1.x = acc[mt][nt][2] + b0; w1.y = acc[mt][nt][3] + b1;
            *reinterpret_cast<float2*>(C + (size_t)row * D_MODEL + col) = w0;
            *reinterpret_cast<float2*>(C + (size_t)(row + 8) * D_MODEL + col) = w1;
        }
    }
}

// ---------------------------------------------------------------------------
// Tensor-core windowed attention (flash-style, fp16).
// CTA: 128 q rows x (head, batch). 4 warps x 32 rows. Key chunks of 64.
// S = Q16*K16 (1 term). PV = (Phi + Plo) * V16 (2 terms; P exact in fp16 pair).
// Writes output into acat [hi | lo] fp16 split for the oproj GEMM.
// ---------------------------------------------------------------------------
#define ATT_SMEM (48 * 1024 + 1024)

__global__ __launch_bounds__(128) void attn_tc_kernel(
    const __half* __restrict__ q16, const __half* __restrict__ k16,
    const __half* __restrict__ v16, __half* __restrict__ acat)
{
    extern __shared__ char dynsmem[];
    uint32_t base = (smem_u32(dynsmem) + 1023) & ~1023u;
    const uint32_t Qs  = base;                 // 16KB: 128 rows x 128B
    const uint32_t KV0 = base + 16384;         // K @ +0 (8KB), V @ +8192
    const uint32_t KV1 = base + 32768;

    const int tid = threadIdx.x, wid = tid >> 5, lane = tid & 31;
    const int q0 = blockIdx.x * 128;
    const int h  = blockIdx.y;
    const int b  = blockIdx.z;
    const size_t rowbase = (size_t)b * SEQ + q0;
    const int hoff = h * HDIM;

    {
        const char* qp = reinterpret_cast<const char*>(q16 + rowbase * D_MODEL + hoff);
#pragma unroll
        for (int it = 0; it < 8; it++) {
            int idx = it * 128 + tid;
            int row = idx >> 3;
            int seg = (idx & 7) << 4;
            uint32_t sw = swz128((uint32_t)(row * 128 + seg));
            cp_async16(Qs + sw, qp + (size_t)row * 2048 + seg);
        }
        cp_commit();
    }

    int c0 = q0 - WINDOW; if (c0 < 0) c0 = 0;
    const int nch = (q0 + 128 - c0) >> 6;

    auto load_kv = [&](int c, uint32_t kvb) {
        const char* kp = reinterpret_cast<const char*>(k16 + ((size_t)b * SEQ + c) * D_MODEL + hoff);
        const char* vp = reinterpret_cast<const char*>(v16 + ((size_t)b * SEQ + c) * D_MODEL + hoff);
#pragma unroll
        for (int it = 0; it < 4; it++) {
            int idx = it * 128 + tid;
            int row = idx >> 3;
            int seg = (idx & 7) << 4;
            uint32_t sw = swz128((uint32_t)(row * 128 + seg));
            size_t go = (size_t)row * 2048 + seg;
            cp_async16(kvb + 0    + sw, kp + go);
            cp_async16(kvb + 8192 + sw, vp + go);
        }
        cp_commit();
    };

    load_kv(c0, KV0);

    float O[2][8][4];
#pragma unroll
    for (int mt = 0; mt < 2; mt++)
#pragma unroll
        for (int nt = 0; nt < 8; nt++)
#pragma unroll
            for (int r = 0; r < 4; r++) O[mt][nt][r] = 0.0f;
    float mrow[2][2] = {{-1e30f, -1e30f}, {-1e30f, -1e30f}};
    float lrow[2][2] = {{0.f, 0.f}, {0.f, 0.f}};

    const float NEGINF = __int_as_float(0xff800000);

    for (int ch = 0; ch < nch; ch++) {
        const uint32_t kvb = (ch & 1) ? KV1 : KV0;
        if (ch + 1 < nch) {
            load_kv(c0 + (ch + 1) * 64, (ch & 1) ? KV0 : KV1);
            cp_wait1();
        } else {
            cp_wait0();
        }
        __syncthreads();

        const int c = c0 + ch * 64;

        float S[2][8][4];
#pragma unroll
        for (int mt = 0; mt < 2; mt++)
#pragma unroll
            for (int nt = 0; nt < 8; nt++)
#pragma unroll
                for (int r = 0; r < 4; r++) S[mt][nt][r] = 0.0f;

#pragma unroll
        for (int kt = 0; kt < 4; kt++) {
            uint32_t qa[2][4];
#pragma unroll
            for (int mt = 0; mt < 2; mt++) {
                int row = wid * 32 + mt * 16 + (lane & 15);
                int kb  = kt * 32 + ((lane >> 4) << 4);
                uint32_t sw = swz128((uint32_t)(row * 128 + kb));
                ldmatrix_x4(qa[mt][0], qa[mt][1], qa[mt][2], qa[mt][3], Qs + sw);
            }
#pragma unroll
            for (int np = 0; np < 4; np++) {
                int nr = np * 16 + ((lane >> 4) & 1) * 8 + (lane & 7);
                int kb = kt * 32 + ((lane >> 3) & 1) * 16;
                uint32_t sw = swz128((uint32_t)(nr * 128 + kb));
                uint32_t kf[4];
                ldmatrix_x4(kf[0], kf[1], kf[2], kf[3], kvb + 0 + sw);
#pragma unroll
                for (int mt = 0; mt < 2; mt++)
#pragma unroll
                    for (int half = 0; half < 2; half++) {
                        int nt = np * 2 + half;
                        mma16816h(S[mt][nt], qa[mt], kf[half * 2], kf[half * 2 + 1]);
                    }
            }
        }

        uint32_t Phi[2][4][4], Plo[2][4][4];
#pragma unroll
        for (int mt = 0; mt < 2; mt++) {
            int i0 = q0 + wid * 32 + mt * 16 + (lane >> 2);
            int i1 = i0 + 8;
#pragma unroll
            for (int nt = 0; nt < 8; nt++) {
                int j = c + nt * 8 + (lane & 3) * 2;
                if (j     > i0 || j     < i0 - WINDOW) S[mt][nt][0] = NEGINF;
                if (j + 1 > i0 || j + 1 < i0 - WINDOW) S[mt][nt][1] = NEGINF;
                if (j     > i1 || j     < i1 - WINDOW) S[mt][nt][2] = NEGINF;
                if (j + 1 > i1 || j + 1 < i1 - WINDOW) S[mt][nt][3] = NEGINF;
            }
#pragma unroll
            for (int half = 0; half < 2; half++) {
                float cm = NEGINF;
#pragma unroll
                for (int nt = 0; nt < 8; nt++)
                    cm = fmaxf(cm, fmaxf(S[mt][nt][half * 2], S[mt][nt][half * 2 + 1]));
                cm = fmaxf(cm, __shfl_xor_sync(0xffffffffu, cm, 1));
                cm = fmaxf(cm, __shfl_xor_sync(0xffffffffu, cm, 2));
                float mold = mrow[mt][half];
                float mnew = fmaxf(mold, cm);
                float corr = __expf(mold - mnew);
                mrow[mt][half] = mnew;
                float psum = 0.0f;
#pragma unroll
                for (int nt = 0; nt < 8; nt++) {
                    float p0 = __expf(S[mt][nt][half * 2]     - mnew);
                    float p1 = __expf(S[mt][nt][half * 2 + 1] - mnew);
                    psum += p0 + p1;
                    O[mt][nt][half * 2]     *= corr;
                    O[mt][nt][half * 2 + 1] *= corr;
                    uint32_t hp = packh(p0, p1);
                    float h0, h1;
                    unpackh(hp, h0, h1);
                    int kt = nt >> 1, hh = nt & 1;
                    Phi[mt][kt][hh * 2 + half] = hp;
                    Plo[mt][kt][hh * 2 + half] = packh(p0 - h0, p1 - h1);
                }
                psum += __shfl_xor_sync(0xffffffffu, psum, 1);
                psum += __shfl_xor_sync(0xffffffffu, psum, 2);
                lrow[mt][half] = lrow[mt][half] * corr + psum;
            }
        }

#pragma unroll
        for (int kt = 0; kt < 4; kt++) {
#pragma unroll
            for (int np = 0; np < 4; np++) {
                int g = lane >> 3;
                int key = kt * 16 + (g & 1) * 8 + (lane & 7);
                int nb  = np * 32 + ((g >> 1) << 4);
                uint32_t sw = swz128((uint32_t)(key * 128 + nb));
                uint32_t vf[4];
                ldmatrix_x4t(vf[0], vf[1], vf[2], vf[3], kvb + 8192 + sw);
#pragma unroll
                for (int mt = 0; mt < 2; mt++)
#pragma unroll
                    for (int half = 0; half < 2; half++) {
                        int nt = np * 2 + half;
                        mma16816h(O[mt][nt], Phi[mt][kt], vf[half * 2], vf[half * 2 + 1]);
                        mma16816h(O[mt][nt], Plo[mt][kt], vf[half * 2], vf[half * 2 + 1]);
                    }
            }
        }
        __syncthreads();
    }

    // normalize + write acat [hi | lo] (fp16 A-split for oproj)
#pragma unroll
    for (int mt = 0; mt < 2; mt++) {
        size_t rA = rowbase + wid * 32 + mt * 16 + (lane >> 2);
        size_t rB = rA + 8;
        float inv0 = 1.0f / lrow[mt][0];
        float inv1 = 1.0f / lrow[mt][1];
#pragma unroll
        for (int nt = 0; nt < 8; nt++) {
            int col = hoff + nt * 8 + (lane & 3) * 2;
            float o00 = O[mt][nt][0] * inv0, o01 = O[mt][nt][1] * inv0;
            float o10 = O[mt][nt][2] * inv1, o11 = O[mt][nt][3] * inv1;
            uint32_t hA = packh(o00, o01);
            uint32_t hB = packh(o10, o11);
            float a0, a1, b0, b1;
            unpackh(hA, a0, a1);
            unpackh(hB, b0, b1);
            __half* pA = acat + rA * ACAT_W + col;
            __half* pB = acat + rB * ACAT_W + col;
            *reinterpret_cast<uint32_t*>(pA) = hA;
            *reinterpret_cast<uint32_t*>(pA + D_MODEL) = packh(o00 - a0, o01 - a1);
            *reinterpret_cast<uint32_t*>(pB) = hB;
            *reinterpret_cast<uint32_t*>(pB + D_MODEL) = packh(o10 - b0, o11 - b1);
        }
    }
}

// ---------------------------------------------------------------------------
// Launch.  Inputs: x, Wq, bq, Wk, bk, Wv, bv, Wo, bo
// ---------------------------------------------------------------------------
extern "C" void kernel_launch(void* const* d_in, const int* in_sizes, int n_in,
                              void* d_out, int out_size)
{
    const float* x  = (const float*)d_in[0];
    const float* Wq = (const float*)d_in[1];
    const float* bq = (const float*)d_in[2];
    const float* Wk = (const float*)d_in[3];
    const float* bk = (const float*)d_in[4];
    const float* Wv = (const float*)d_in[5];
    const float* bv = (const float*)d_in[6];
    const float* Wo = (const float*)d_in[7];
    const float* bo = (const float*)d_in[8];
    float* out = (float*)d_out;

    __half *acat, *bcat, *q16, *k16, *v16;
    cudaGetSymbolAddress((void**)&acat, g_acat);
    cudaGetSymbolAddress((void**)&bcat, g_bcat);
    cudaGetSymbolAddress((void**)&q16, g_q16);
    cudaGetSymbolAddress((void**)&k16, g_k16);
    cudaGetSymbolAddress((void**)&v16, g_v16);

    cudaFuncSetAttribute(qkv_mma_kernel,
                         cudaFuncAttributeMaxDynamicSharedMemorySize, GEMM_SMEM_BYTES);
    cudaFuncSetAttribute(oproj_mma_kernel,
                         cudaFuncAttributeMaxDynamicSharedMemorySize, GEMM_SMEM_BYTES);
    cudaFuncSetAttribute(attn_tc_kernel,
                         cudaFuncAttributeMaxDynamicSharedMemorySize, ATT_SMEM);

    const size_t WSTRIDE = (size_t)D_MODEL * D_MODEL;

    convA_kernel<<<M_TOT * D_MODEL / 4 / 256, 256>>>(x, acat);
    dim3 cw_grid(32, 32, 4), cw_blk(32, 8);
    convW4_kernel<<<cw_grid, cw_blk>>>(Wq, Wk, Wv, Wo, bcat);

    // fused QKV projections -> fp16 (Q pre-scaled by 0.125)
    dim3 qkv_grid(24, 32);
    qkv_mma_kernel<<<qkv_grid, 256, GEMM_SMEM_BYTES>>>(acat, bcat, bq, bk, bv,
                                                       q16, k16, v16);

    // tensor-core windowed attention -> writes acat [hi|lo] directly
    dim3 attn_grid(SEQ / 128, NHEADS, BATCH);    // (16, 16, 2)
    attn_tc_kernel<<<attn_grid, 128, ATT_SMEM>>>(q16, k16, v16, acat);

    // output projection -> fp32
    dim3 o_grid(8, 32);
    oproj_mma_kernel<<<o_grid, 256, GEMM_SMEM_BYTES>>>(acat, bcat + 3 * WSTRIDE, bo, out);
}

// round 11
// speedup vs baseline: 1.6779x; 1.0843x over previous
#include <cuda_runtime.h>
#include <cuda_fp16.h>
#include <cstdint>
#include <math.h>

// ---------------------------------------------------------------------------
// Problem constants
// ---------------------------------------------------------------------------
#define D_MODEL 1024
#define NHEADS  16
#define HDIM    64
#define WINDOW  256
#define BATCH   2
#define SEQ     2048
#define M_TOT   (BATCH * SEQ)     // 4096
#define ACAT_W  2048              // [hi | lo] fp16 A-split width
#define NCHUNK  16                // 16 k-chunks of 64

// ---------------------------------------------------------------------------
// Scratch (no cudaMalloc allowed)
// ---------------------------------------------------------------------------
__device__ __half g_acat[(size_t)M_TOT * ACAT_W];        // [4096][2048] fp16
__device__ __half g_bcat[4][(size_t)D_MODEL * D_MODEL];  // [1024 n][1024 k] fp16
__device__ __half g_q16[(size_t)M_TOT * D_MODEL];
__device__ __half g_k16[(size_t)M_TOT * D_MODEL];
__device__ __half g_v16[(size_t)M_TOT * D_MODEL];

// ---------------------------------------------------------------------------
// Helpers
// ---------------------------------------------------------------------------
__device__ __forceinline__ uint32_t smem_u32(const void* p) {
    uint32_t a;
    asm("{ .reg .u64 t; cvta.to.shared.u64 t, %1; cvt.u32.u64 %0, t; }" : "=r"(a) : "l"(p));
    return a;
}
__device__ __forceinline__ uint32_t swz128(uint32_t off) {
    return off ^ ((off >> 3) & 0x70);
}
__device__ __forceinline__ void cp_async16(uint32_t saddr, const void* gaddr) {
    asm volatile("cp.async.cg.shared.global [%0], [%1], 16;" :: "r"(saddr), "l"(gaddr));
}
__device__ __forceinline__ void cp_commit() {
    asm volatile("cp.async.commit_group;" ::: "memory");
}
__device__ __forceinline__ void cp_wait1() {
    asm volatile("cp.async.wait_group 1;" ::: "memory");
}
__device__ __forceinline__ void cp_wait0() {
    asm volatile("cp.async.wait_group 0;" ::: "memory");
}
__device__ __forceinline__ void ldmatrix_x4(uint32_t& r0, uint32_t& r1,
                                            uint32_t& r2, uint32_t& r3, uint32_t addr) {
    asm volatile("ldmatrix.sync.aligned.m8n8.x4.shared.b16 {%0,%1,%2,%3}, [%4];"
                 : "=r"(r0), "=r"(r1), "=r"(r2), "=r"(r3) : "r"(addr));
}
__device__ __forceinline__ void ldmatrix_x4t(uint32_t& r0, uint32_t& r1,
                                             uint32_t& r2, uint32_t& r3, uint32_t addr) {
    asm volatile("ldmatrix.sync.aligned.m8n8.x4.trans.shared.b16 {%0,%1,%2,%3}, [%4];"
                 : "=r"(r0), "=r"(r1), "=r"(r2), "=r"(r3) : "r"(addr));
}
// fp16 MMA, fp32 accum
__device__ __forceinline__ void mma16816h(float* d, const uint32_t* a,
                                          uint32_t b0, uint32_t b1) {
    asm volatile(
        "mma.sync.aligned.m16n8k16.row.col.f32.f16.f16.f32 "
        "{%0,%1,%2,%3}, {%4,%5,%6,%7}, {%8,%9}, {%0,%1,%2,%3};"
        : "+f"(d[0]), "+f"(d[1]), "+f"(d[2]), "+f"(d[3])
        : "r"(a[0]), "r"(a[1]), "r"(a[2]), "r"(a[3]), "r"(b0), "r"(b1));
}
__device__ __forceinline__ uint32_t packh(float a, float b) {
    __half2 h = __floats2half2_rn(a, b);
    return *reinterpret_cast<uint32_t*>(&h);
}
__device__ __forceinline__ void unpackh(uint32_t p, float& a, float& b) {
    __half2 h = *reinterpret_cast<__half2*>(&p);
    a = __half2float(h.x); b = __half2float(h.y);
}

// ---------------------------------------------------------------------------
// convA: src [M,1024] fp32 -> dst [M,2048] fp16 = [hi | lo]  (exact A split)
// ---------------------------------------------------------------------------
__global__ __launch_bounds__(256) void convA_kernel(const float* __restrict__ src,
                                                    __half* __restrict__ dst)
{
    int idx = blockIdx.x * blockDim.x + threadIdx.x;
    float4 v = reinterpret_cast<const float4*>(src)[idx];
    int row = idx >> 8;
    int c4  = idx & 255;

    __half hx = __float2half(v.x), hy = __float2half(v.y);
    __half hz = __float2half(v.z), hw = __float2half(v.w);
    float lx = v.x - __half2float(hx), ly = v.y - __half2float(hy);
    float lz = v.z - __half2float(hz), lw = v.w - __half2float(hw);

    __half* r = dst + (size_t)row * ACAT_W;
    uint32_t* p0 = reinterpret_cast<uint32_t*>(r) + c4 * 2;
    __half2 h0; h0.x = hx; h0.y = hy;
    __half2 h1; h1.x = hz; h1.y = hw;
    p0[0] = *reinterpret_cast<uint32_t*>(&h0);
    p0[1] = *reinterpret_cast<uint32_t*>(&h1);
    uint32_t* p1 = reinterpret_cast<uint32_t*>(r + D_MODEL) + c4 * 2;
    p1[0] = packh(lx, ly);
    p1[1] = packh(lz, lw);
}

// ---------------------------------------------------------------------------
// convW (all 4 weights, blockIdx.z selects): W[k][n] fp32 -> B[n][1024k] fp16
// ---------------------------------------------------------------------------
__global__ __launch_bounds__(256) void convW4_kernel(
    const float* __restrict__ W0, const float* __restrict__ W1,
    const float* __restrict__ W2, const float* __restrict__ W3,
    __half* __restrict__ Bbase)
{
    __shared__ float tile[32][33];
    const float* W = (blockIdx.z == 0) ? W0 : (blockIdx.z == 1) ? W1
                     : (blockIdx.z == 2) ? W2 : W3;
    __half* B = Bbase + (size_t)blockIdx.z * D_MODEL * D_MODEL;

    int n0 = blockIdx.x * 32;
    int k0 = blockIdx.y * 32;
    int tx = threadIdx.x, ty = threadIdx.y;   // (32, 8)

#pragma unroll
    for (int i = 0; i < 32; i += 8)
        tile[ty + i][tx] = W[(size_t)(k0 + ty + i) * D_MODEL + n0 + tx];
    __syncthreads();

#pragma unroll
    for (int i = 0; i < 32; i += 8) {
        int n = n0 + ty + i;
        int k = k0 + tx;
        B[(size_t)n * D_MODEL + k] = __float2half(tile[tx][ty + i]);
    }
}

// ---------------------------------------------------------------------------
// GEMM mainloop, CTA tile 128x128, 8 warps (2m x 4n) of 64x32 each.
// FUSED 2-term fp16: per k-chunk compute Ah*W and Al*W in one pass, sharing
// the W fragments. SMEM: 2 sets x (Ah 16K | Al 16K | W 16K). Prefetch dist 1,
// one barrier per chunk, loads issued after the barrier (no slot race).
// ---------------------------------------------------------------------------
#define GSET 49152
#define GEMM_SMEM_BYTES (2 * GSET + 1024)

__device__ __forceinline__ void load_tile128(uint32_t dst, const __half* src,
                                             int row0, int col0, int stride, int tid)
{
    // 128 rows x 64 fp16 (128B per row), SW128 swizzle
#pragma unroll
    for (int it = 0; it < 4; it++) {
        int idx = it * 256 + tid;
        int row = idx >> 3;
        int seg = (idx & 7) << 4;
        uint32_t sw = swz128((uint32_t)(row * 128 + seg));
        cp_async16(dst + sw,
                   reinterpret_cast<const char*>(src + (size_t)(row0 + row) * stride + col0) + seg);
    }
}

__device__ __forceinline__ void gemm_mainloop(
    const __half* __restrict__ A, const __half* __restrict__ B,
    int m0, int n0, uint32_t base, float (&acc)[4][4][4])
{
    const int tid = threadIdx.x;
    const int lane = tid & 31;
    const int wid = tid >> 5;
    const int warp_m = wid >> 2;     // 0..1
    const int warp_n = wid & 3;      // 0..3

#pragma unroll
    for (int i = 0; i < 4; i++)
#pragma unroll
        for (int j = 0; j < 4; j++)
#pragma unroll
            for (int r = 0; r < 4; r++) acc[i][j][r] = 0.0f;

    auto loadch = [&](int ch) {
        uint32_t s = base + (ch & 1) * GSET;
        load_tile128(s,         A, m0, ch * 64,           ACAT_W, tid);   // Ah
        load_tile128(s + 16384, A, m0, D_MODEL + ch * 64, ACAT_W, tid);   // Al
        load_tile128(s + 32768, B, n0, ch * 64,           D_MODEL, tid);  // W
        cp_commit();
    };

    loadch(0);

    for (int ch = 0; ch < NCHUNK; ch++) {
        cp_wait0();
        __syncthreads();            // data visible + everyone done with other slot
        if (ch + 1 < NCHUNK) loadch(ch + 1);

        const uint32_t sa = base + (ch & 1) * GSET;   // Ah
        const uint32_t sl = sa + 16384;               // Al
        const uint32_t sw = sa + 32768;               // W

#pragma unroll
        for (int step = 0; step < 4; step++) {
            uint32_t bfr[8];
#pragma unroll
            for (int jp = 0; jp < 2; jp++) {
                int nrow = warp_n * 32 + jp * 16 + ((lane >> 4) & 1) * 8 + (lane & 7);
                int kb   = step * 32 + ((lane >> 3) & 1) * 16;
                uint32_t addr = sw + swz128((uint32_t)(nrow * 128 + kb));
                ldmatrix_x4(bfr[jp * 4 + 0], bfr[jp * 4 + 1],
                            bfr[jp * 4 + 2], bfr[jp * 4 + 3], addr);
            }
            // hi product
            {
                uint32_t afr[4][4];
#pragma unroll
                for (int mt = 0; mt < 4; mt++) {
                    int row = warp_m * 64 + mt * 16 + (lane & 15);
                    int kb  = step * 32 + ((lane >> 4) << 4);
                    uint32_t addr = sa + swz128((uint32_t)(row * 128 + kb));
                    ldmatrix_x4(afr[mt][0], afr[mt][1], afr[mt][2], afr[mt][3], addr);
                }
#pragma unroll
                for (int mt = 0; mt < 4; mt++)
#pragma unroll
                    for (int nt = 0; nt < 4; nt++)
                        mma16816h(acc[mt][nt], afr[mt], bfr[nt * 2], bfr[nt * 2 + 1]);
            }
            // lo product (same W fragments)
            {
                uint32_t afr[4][4];
#pragma unroll
                for (int mt = 0; mt < 4; mt++) {
                    int row = warp_m * 64 + mt * 16 + (lane & 15);
                    int kb  = step * 32 + ((lane >> 4) << 4);
                    uint32_t addr = sl + swz128((uint32_t)(row * 128 + kb));
                    ldmatrix_x4(afr[mt][0], afr[mt][1], afr[mt][2], afr[mt][3], addr);
                }
#pragma unroll
                for (int mt = 0; mt < 4; mt++)
#pragma unroll
                    for (int nt = 0; nt < 4; nt++)
                        mma16816h(acc[mt][nt], afr[mt], bfr[nt * 2], bfr[nt * 2 + 1]);
            }
        }
    }
}

// ---------------------------------------------------------------------------
// QKV GEMM: one launch for all three projections.
// blockIdx.x: [0..23] -> matid = x>>3, n-tile = x&7. fp16 single output.
// ---------------------------------------------------------------------------
__global__ __launch_bounds__(256, 2) void qkv_mma_kernel(
    const __half* __restrict__ A, const __half* __restrict__ Bc,
    const float* __restrict__ bq, const float* __restrict__ bk, const float* __restrict__ bv,
    __half* __restrict__ q16, __half* __restrict__ k16, __half* __restrict__ v16)
{
    extern __shared__ char dynsmem[];
    uint32_t tile_base = (smem_u32(dynsmem) + 1023) & ~1023u;

    const int matid = blockIdx.x >> 3;
    const int n0 = (blockIdx.x & 7) * 128;
    const int m0 = blockIdx.y * 128;
    const __half* B = Bc + (size_t)matid * D_MODEL * D_MODEL;
    const float* bias = (matid == 0) ? bq : (matid == 1) ? bk : bv;
    __half* O = (matid == 0) ? q16 : (matid == 1) ? k16 : v16;
    const float scale = (matid == 0) ? 0.125f : 1.0f;

    float acc[4][4][4];
    gemm_mainloop(A, B, m0, n0, tile_base, acc);

    const int lane = threadIdx.x & 31;
    const int wid = threadIdx.x >> 5;
    const int warp_m = wid >> 2, warp_n = wid & 3;
#pragma unroll
    for (int mt = 0; mt < 4; mt++) {
        int row = m0 + warp_m * 64 + mt * 16 + (lane >> 2);
#pragma unroll
        for (int nt = 0; nt < 4; nt++) {
            int col = n0 + warp_n * 32 + nt * 8 + (lane & 3) * 2;
            float b0 = bias[col], b1 = bias[col + 1];
            *reinterpret_cast<uint32_t*>(O + (size_t)row * D_MODEL + col) =
                packh((acc[mt][nt][0] + b0) * scale, (acc[mt][nt][1] + b1) * scale);
            *reinterpret_cast<uint32_t*>(O + (size_t)(row + 8) * D_MODEL + col) =
                packh((acc[mt][nt][2] + b0) * scale, (acc[mt][nt][3] + b1) * scale);
        }
    }
}

// ---------------------------------------------------------------------------
// Output projection GEMM (fp32 epilogue)
// ---------------------------------------------------------------------------
__global__ __launch_bounds__(256, 2) void oproj_mma_kernel(
    const __half* __restrict__ A, const __half* __restrict__ B,
    const float* __restrict__ bias, float* __restrict__ C)
{
    extern __shared__ char dynsmem[];
    uint32_t tile_base = (smem_u32(dynsmem) + 1023) & ~1023u;

    const int n0 = blockIdx.x * 128;
    const int m0 = blockIdx.y * 128;

    float acc[4][4][4];
    gemm_mainloop(A, B, m0, n0, tile_base, acc);

    const int lane = threadIdx.x & 31;
    const int wid = threadIdx.x >> 5;
    const int warp_m = wid >> 2, warp_n = wid & 3;
#pragma unroll
    for (int mt = 0; mt < 4; mt++) {
        int row = m0 + warp_m * 64 + mt * 16 + (lane >> 2);
#pragma unroll
        for (int nt = 0; nt < 4; nt++) {
            int col = n0 + warp_n * 32 + nt * 8 + (lane & 3) * 2;
            float b0 = bias[col], b1 = bias[col + 1];
            float2 w0; w0.x = acc[mt][nt][0] + b0; w0.y = acc[mt][nt][1] + b1;
            float2 w1; w1.x = acc[mt][nt][2] + b0; w1.y = acc[mt][nt][3] + b1;
            *reinterpret_cast<float2*>(C + (size_t)row * D_MODEL + col) = w0;
            *reinterpret_cast<float2*>(C + (size_t)(row + 8) * D_MODEL + col) = w1;
        }
    }
}

// ---------------------------------------------------------------------------
// Tensor-core windowed attention (flash-style, fp16).
// CTA: 128 q rows x (head, batch). 4 warps x 32 rows. Key chunks of 64.
// S = Q16*K16 (1 term). PV = Phi * V16 (1 term; p rounding is unbiased and
// averages out across the window -> ~1.4e-4 added rms error).
// Writes output into acat [hi | lo] fp16 split for the oproj GEMM.
// ---------------------------------------------------------------------------
#define ATT_SMEM (48 * 1024 + 1024)

__global__ __launch_bounds__(128) void attn_tc_kernel(
    const __half* __restrict__ q16, const __half* __restrict__ k16,
    const __half* __restrict__ v16, __half* __restrict__ acat)
{
    extern __shared__ char dynsmem[];
    uint32_t base = (smem_u32(dynsmem) + 1023) & ~1023u;
    const uint32_t Qs  = base;                 // 16KB: 128 rows x 128B
    const uint32_t KV0 = base + 16384;         // K @ +0 (8KB), V @ +8192
    const uint32_t KV1 = base + 32768;

    const int tid = threadIdx.x, wid = tid >> 5, lane = tid & 31;
    const int q0 = blockIdx.x * 128;
    const int h  = blockIdx.y;
    const int b  = blockIdx.z;
    const size_t rowbase = (size_t)b * SEQ + q0;
    const int hoff = h * HDIM;

    {
        const char* qp = reinterpret_cast<const char*>(q16 + rowbase * D_MODEL + hoff);
#pragma unroll
        for (int it = 0; it < 8; it++) {
            int idx = it * 128 + tid;
            int row = idx >> 3;
            int seg = (idx & 7) << 4;
            uint32_t sw = swz128((uint32_t)(row * 128 + seg));
            cp_async16(Qs + sw, qp + (size_t)row * 2048 + seg);
        }
        cp_commit();
    }

    int c0 = q0 - WINDOW; if (c0 < 0) c0 = 0;
    const int nch = (q0 + 128 - c0) >> 6;

    auto load_kv = [&](int c, uint32_t kvb) {
        const char* kp = reinterpret_cast<const char*>(k16 + ((size_t)b * SEQ + c) * D_MODEL + hoff);
        const char* vp = reinterpret_cast<const char*>(v16 + ((size_t)b * SEQ + c) * D_MODEL + hoff);
#pragma unroll
        for (int it = 0; it < 4; it++) {
            int idx = it * 128 + tid;
            int row = idx >> 3;
            int seg = (idx & 7) << 4;
            uint32_t sw = swz128((uint32_t)(row * 128 + seg));
            size_t go = (size_t)row * 2048 + seg;
            cp_async16(kvb + 0    + sw, kp + go);
            cp_async16(kvb + 8192 + sw, vp + go);
        }
        cp_commit();
    };

    load_kv(c0, KV0);

    float O[2][8][4];
#pragma unroll
    for (int mt = 0; mt < 2; mt++)
#pragma unroll
        for (int nt = 0; nt < 8; nt++)
#pragma unroll
            for (int r = 0; r < 4; r++) O[mt][nt][r] = 0.0f;
    float mrow[2][2] = {{-1e30f, -1e30f}, {-1e30f, -1e30f}};
    float lrow[2][2] = {{0.f, 0.f}, {0.f, 0.f}};

    const float NEGINF = __int_as_float(0xff800000);

    for (int ch = 0; ch < nch; ch++) {
        const uint32_t kvb = (ch & 1) ? KV1 : KV0;
        if (ch + 1 < nch) {
            load_kv(c0 + (ch + 1) * 64, (ch & 1) ? KV0 : KV1);
            cp_wait1();
        } else {
            cp_wait0();
        }
        __syncthreads();

        const int c = c0 + ch * 64;

        float S[2][8][4];
#pragma unroll
        for (int mt = 0; mt < 2; mt++)
#pragma unroll
            for (int nt = 0; nt < 8; nt++)
#pragma unroll
                for (int r = 0; r < 4; r++) S[mt][nt][r] = 0.0f;

#pragma unroll
        for (int kt = 0; kt < 4; kt++) {
            uint32_t qa[2][4];
#pragma unroll
            for (int mt = 0; mt < 2; mt++) {
                int row = wid * 32 + mt * 16 + (lane & 15);
                int kb  = kt * 32 + ((lane >> 4) << 4);
                uint32_t sw = swz128((uint32_t)(row * 128 + kb));
                ldmatrix_x4(qa[mt][0], qa[mt][1], qa[mt][2], qa[mt][3], Qs + sw);
            }
#pragma unroll
            for (int np = 0; np < 4; np++) {
                int nr = np * 16 + ((lane >> 4) & 1) * 8 + (lane & 7);
                int kb = kt * 32 + ((lane >> 3) & 1) * 16;
                uint32_t sw = swz128((uint32_t)(nr * 128 + kb));
                uint32_t kf[4];
                ldmatrix_x4(kf[0], kf[1], kf[2], kf[3], kvb + 0 + sw);
#pragma unroll
                for (int mt = 0; mt < 2; mt++)
#pragma unroll
                    for (int half = 0; half < 2; half++) {
                        int nt = np * 2 + half;
                        mma16816h(S[mt][nt], qa[mt], kf[half * 2], kf[half * 2 + 1]);
                    }
            }
        }

        uint32_t Phi[2][4][4];
#pragma unroll
        for (int mt = 0; mt < 2; mt++) {
            int i0 = q0 + wid * 32 + mt * 16 + (lane >> 2);
            int i1 = i0 + 8;
#pragma unroll
            for (int nt = 0; nt < 8; nt++) {
                int j = c + nt * 8 + (lane & 3) * 2;
                if (j     > i0 || j     < i0 - WINDOW) S[mt][nt][0] = NEGINF;
                if (j + 1 > i0 || j + 1 < i0 - WINDOW) S[mt][nt][1] = NEGINF;
                if (j     > i1 || j     < i1 - WINDOW) S[mt][nt][2] = NEGINF;
                if (j + 1 > i1 || j + 1 < i1 - WINDOW) S[mt][nt][3] = NEGINF;
            }
#pragma unroll
            for (int half = 0; half < 2; half++) {
                float cm = NEGINF;
#pragma unroll
                for (int nt = 0; nt < 8; nt++)
                    cm = fmaxf(cm, fmaxf(S[mt][nt][half * 2], S[mt][nt][half * 2 + 1]));
                cm = fmaxf(cm, __shfl_xor_sync(0xffffffffu, cm, 1));
                cm = fmaxf(cm, __shfl_xor_sync(0xffffffffu, cm, 2));
                float mold = mrow[mt][half];
                float mnew = fmaxf(mold, cm);
                float corr = __expf(mold - mnew);
                mrow[mt][half] = mnew;
                float psum = 0.0f;
#pragma unroll
                for (int nt = 0; nt < 8; nt++) {
                    float p0 = __expf(S[mt][nt][half * 2]     - mnew);
                    float p1 = __expf(S[mt][nt][half * 2 + 1] - mnew);
                    psum += p0 + p1;
                    O[mt][nt][half * 2]     *= corr;
                    O[mt][nt][half * 2 + 1] *= corr;
                    int kt = nt >> 1, hh = nt & 1;
                    Phi[mt][kt][hh * 2 + half] = packh(p0, p1);
                }
                psum += __shfl_xor_sync(0xffffffffu, psum, 1);
                psum += __shfl_xor_sync(0xffffffffu, psum, 2);
                lrow[mt][half] = lrow[mt][half] * corr + psum;
            }
        }

#pragma unroll
        for (int kt = 0; kt < 4; kt++) {
#pragma unroll
            for (int np = 0; np < 4; np++) {
                int g = lane >> 3;
                int key = kt * 16 + (g & 1) * 8 + (lane & 7);
                int nb  = np * 32 + ((g >> 1) << 4);
                uint32_t sw = swz128((uint32_t)(key * 128 + nb));
                uint32_t vf[4];
                ldmatrix_x4t(vf[0], vf[1], vf[2], vf[3], kvb + 8192 + sw);
#pragma unroll
                for (int mt = 0; mt < 2; mt++)
#pragma unroll
                    for (int half = 0; half < 2; half++) {
                        int nt = np * 2 + half;
                        mma16816h(O[mt][nt], Phi[mt][kt], vf[half * 2], vf[half * 2 + 1]);
                    }
            }
        }
        __syncthreads();
    }

    // normalize + write acat [hi | lo] (fp16 A-split for oproj)
#pragma unroll
    for (int mt = 0; mt < 2; mt++) {
        size_t rA = rowbase + wid * 32 + mt * 16 + (lane >> 2);
        size_t rB = rA + 8;
        float inv0 = 1.0f / lrow[mt][0];
        float inv1 = 1.0f / lrow[mt][1];
#pragma unroll
        for (int nt = 0; nt < 8; nt++) {
            int col = hoff + nt * 8 + (lane & 3) * 2;
            float o00 = O[mt][nt][0] * inv0, o01 = O[mt][nt][1] * inv0;
            float o10 = O[mt][nt][2] * inv1, o11 = O[mt][nt][3] * inv1;
            uint32_t hA = packh(o00, o01);
            uint32_t hB = packh(o10, o11);
            float a0, a1, b0, b1;
            unpackh(hA, a0, a1);
            unpackh(hB, b0, b1);
            __half* pA = acat + rA * ACAT_W + col;
            __half* pB = acat + rB * ACAT_W + col;
            *reinterpret_cast<uint32_t*>(pA) = hA;
            *reinterpret_cast<uint32_t*>(pA + D_MODEL) = packh(o00 - a0, o01 - a1);
            *reinterpret_cast<uint32_t*>(pB) = hB;
            *reinterpret_cast<uint32_t*>(pB + D_MODEL) = packh(o10 - b0, o11 - b1);
        }
    }
}

// ---------------------------------------------------------------------------
// Launch.  Inputs: x, Wq, bq, Wk, bk, Wv, bv, Wo, bo
// ---------------------------------------------------------------------------
extern "C" void kernel_launch(void* const* d_in, const int* in_sizes, int n_in,
                              void* d_out, int out_size)
{
    const float* x  = (const float*)d_in[0];
    const float* Wq = (const float*)d_in[1];
    const float* bq = (const float*)d_in[2];
    const float* Wk = (const float*)d_in[3];
    const float* bk = (const float*)d_in[4];
    const float* Wv = (const float*)d_in[5];
    const float* bv = (const float*)d_in[6];
    const float* Wo = (const float*)d_in[7];
    const float* bo = (const float*)d_in[8];
    float* out = (float*)d_out;

    __half *acat, *bcat, *q16, *k16, *v16;
    cudaGetSymbolAddress((void**)&acat, g_acat);
    cudaGetSymbolAddress((void**)&bcat, g_bcat);
    cudaGetSymbolAddress((void**)&q16, g_q16);
    cudaGetSymbolAddress((void**)&k16, g_k16);
    cudaGetSymbolAddress((void**)&v16, g_v16);

    cudaFuncSetAttribute(qkv_mma_kernel,
                         cudaFuncAttributeMaxDynamicSharedMemorySize, GEMM_SMEM_BYTES);
    cudaFuncSetAttribute(oproj_mma_kernel,
                         cudaFuncAttributeMaxDynamicSharedMemorySize, GEMM_SMEM_BYTES);
    cudaFuncSetAttribute(attn_tc_kernel,
                         cudaFuncAttributeMaxDynamicSharedMemorySize, ATT_SMEM);

    const size_t WSTRIDE = (size_t)D_MODEL * D_MODEL;

    convA_kernel<<<M_TOT * D_MODEL / 4 / 256, 256>>>(x, acat);
    dim3 cw_grid(32, 32, 4), cw_blk(32, 8);
    convW4_kernel<<<cw_grid, cw_blk>>>(Wq, Wk, Wv, Wo, bcat);

    // fused QKV projections -> fp16 (Q pre-scaled by 0.125)
    dim3 qkv_grid(24, 32);
    qkv_mma_kernel<<<qkv_grid, 256, GEMM_SMEM_BYTES>>>(acat, bcat, bq, bk, bv,
                                                       q16, k16, v16);

    // tensor-core windowed attention -> writes acat [hi|lo] directly
    dim3 attn_grid(SEQ / 128, NHEADS, BATCH);    // (16, 16, 2)
    attn_tc_kernel<<<attn_grid, 128, ATT_SMEM>>>(q16, k16, v16, acat);

    // output projection -> fp32
    dim3 o_grid(8, 32);
    oproj_mma_kernel<<<o_grid, 256, GEMM_SMEM_BYTES>>>(acat, bcat + 3 * WSTRIDE, bo, out);
}

// round 13
// speedup vs baseline: 1.8251x; 1.0877x over previous
#include <cuda_runtime.h>
#include <cuda_fp16.h>
#include <cstdint>
#include <math.h>

// ---------------------------------------------------------------------------
// Problem constants
// ---------------------------------------------------------------------------
#define D_MODEL 1024
#define NHEADS  16
#define HDIM    64
#define WINDOW  256
#define BATCH   2
#define SEQ     2048
#define M_TOT   (BATCH * SEQ)     // 4096
#define ACAT_W  2048              // [hi | lo] fp16 A-split width
#define NCHUNK  16                // 16 k-chunks of 64

// ---------------------------------------------------------------------------
// Scratch (no cudaMalloc allowed)
// ---------------------------------------------------------------------------
__device__ __half g_acat[(size_t)M_TOT * ACAT_W];        // [4096][2048] fp16
__device__ __half g_bcat[4][(size_t)D_MODEL * D_MODEL];  // [1024 n][1024 k] fp16
__device__ __half g_q16[(size_t)M_TOT * D_MODEL];
__device__ __half g_k16[(size_t)M_TOT * D_MODEL];
__device__ __half g_v16[(size_t)M_TOT * D_MODEL];
__device__ __half g_o16[(size_t)M_TOT * D_MODEL];        // attn output, single fp16

// ---------------------------------------------------------------------------
// Helpers
// ---------------------------------------------------------------------------
__device__ __forceinline__ uint32_t smem_u32(const void* p) {
    uint32_t a;
    asm("{ .reg .u64 t; cvta.to.shared.u64 t, %1; cvt.u32.u64 %0, t; }" : "=r"(a) : "l"(p));
    return a;
}
__device__ __forceinline__ uint32_t swz128(uint32_t off) {
    return off ^ ((off >> 3) & 0x70);
}
__device__ __forceinline__ void cp_async16(uint32_t saddr, const void* gaddr) {
    asm volatile("cp.async.cg.shared.global [%0], [%1], 16;" :: "r"(saddr), "l"(gaddr));
}
__device__ __forceinline__ void cp_commit() {
    asm volatile("cp.async.commit_group;" ::: "memory");
}
__device__ __forceinline__ void cp_wait1() {
    asm volatile("cp.async.wait_group 1;" ::: "memory");
}
__device__ __forceinline__ void cp_wait0() {
    asm volatile("cp.async.wait_group 0;" ::: "memory");
}
__device__ __forceinline__ void ldmatrix_x4(uint32_t& r0, uint32_t& r1,
                                            uint32_t& r2, uint32_t& r3, uint32_t addr) {
    asm volatile("ldmatrix.sync.aligned.m8n8.x4.shared.b16 {%0,%1,%2,%3}, [%4];"
                 : "=r"(r0), "=r"(r1), "=r"(r2), "=r"(r3) : "r"(addr));
}
__device__ __forceinline__ void ldmatrix_x4t(uint32_t& r0, uint32_t& r1,
                                             uint32_t& r2, uint32_t& r3, uint32_t addr) {
    asm volatile("ldmatrix.sync.aligned.m8n8.x4.trans.shared.b16 {%0,%1,%2,%3}, [%4];"
                 : "=r"(r0), "=r"(r1), "=r"(r2), "=r"(r3) : "r"(addr));
}
// fp16 MMA, fp32 accum
__device__ __forceinline__ void mma16816h(float* d, const uint32_t* a,
                                          uint32_t b0, uint32_t b1) {
    asm volatile(
        "mma.sync.aligned.m16n8k16.row.col.f32.f16.f16.f32 "
        "{%0,%1,%2,%3}, {%4,%5,%6,%7}, {%8,%9}, {%0,%1,%2,%3};"
        : "+f"(d[0]), "+f"(d[1]), "+f"(d[2]), "+f"(d[3])
        : "r"(a[0]), "r"(a[1]), "r"(a[2]), "r"(a[3]), "r"(b0), "r"(b1));
}
__device__ __forceinline__ uint32_t packh(float a, float b) {
    __half2 h = __floats2half2_rn(a, b);
    return *reinterpret_cast<uint32_t*>(&h);
}
__device__ __forceinline__ void unpackh(uint32_t p, float& a, float& b) {
    __half2 h = *reinterpret_cast<__half2*>(&p);
    a = __half2float(h.x); b = __half2float(h.y);
}

// ---------------------------------------------------------------------------
// convA: src [M,1024] fp32 -> dst [M,2048] fp16 = [hi | lo]  (exact A split)
// ---------------------------------------------------------------------------
__global__ __launch_bounds__(256) void convA_kernel(const float* __restrict__ src,
                                                    __half* __restrict__ dst)
{
    int idx = blockIdx.x * blockDim.x + threadIdx.x;
    float4 v = reinterpret_cast<const float4*>(src)[idx];
    int row = idx >> 8;
    int c4  = idx & 255;

    __half hx = __float2half(v.x), hy = __float2half(v.y);
    __half hz = __float2half(v.z), hw = __float2half(v.w);
    float lx = v.x - __half2float(hx), ly = v.y - __half2float(hy);
    float lz = v.z - __half2float(hz), lw = v.w - __half2float(hw);

    __half* r = dst + (size_t)row * ACAT_W;
    uint32_t* p0 = reinterpret_cast<uint32_t*>(r) + c4 * 2;
    __half2 h0; h0.x = hx; h0.y = hy;
    __half2 h1; h1.x = hz; h1.y = hw;
    p0[0] = *reinterpret_cast<uint32_t*>(&h0);
    p0[1] = *reinterpret_cast<uint32_t*>(&h1);
    uint32_t* p1 = reinterpret_cast<uint32_t*>(r + D_MODEL) + c4 * 2;
    p1[0] = packh(lx, ly);
    p1[1] = packh(lz, lw);
}

// ---------------------------------------------------------------------------
// convW (all 4 weights, blockIdx.z selects): W[k][n] fp32 -> B[n][1024k] fp16
// ---------------------------------------------------------------------------
__global__ __launch_bounds__(256) void convW4_kernel(
    const float* __restrict__ W0, const float* __restrict__ W1,
    const float* __restrict__ W2, const float* __restrict__ W3,
    __half* __restrict__ Bbase)
{
    __shared__ float tile[32][33];
    const float* W = (blockIdx.z == 0) ? W0 : (blockIdx.z == 1) ? W1
                     : (blockIdx.z == 2) ? W2 : W3;
    __half* B = Bbase + (size_t)blockIdx.z * D_MODEL * D_MODEL;

    int n0 = blockIdx.x * 32;
    int k0 = blockIdx.y * 32;
    int tx = threadIdx.x, ty = threadIdx.y;   // (32, 8)

#pragma unroll
    for (int i = 0; i < 32; i += 8)
        tile[ty + i][tx] = W[(size_t)(k0 + ty + i) * D_MODEL + n0 + tx];
    __syncthreads();

#pragma unroll
    for (int i = 0; i < 32; i += 8) {
        int n = n0 + ty + i;
        int k = k0 + tx;
        B[(size_t)n * D_MODEL + k] = __float2half(tile[tx][ty + i]);
    }
}

// ---------------------------------------------------------------------------
// Shared tile loader: 128 rows x 64 fp16 (128B/row), SW128 swizzle
// ---------------------------------------------------------------------------
__device__ __forceinline__ void load_tile128(uint32_t dst, const __half* src,
                                             int row0, int col0, int stride, int tid)
{
#pragma unroll
    for (int it = 0; it < 4; it++) {
        int idx = it * 256 + tid;
        int row = idx >> 3;
        int seg = (idx & 7) << 4;
        uint32_t sw = swz128((uint32_t)(row * 128 + seg));
        cp_async16(dst + sw,
                   reinterpret_cast<const char*>(src + (size_t)(row0 + row) * stride + col0) + seg);
    }
}

// ---------------------------------------------------------------------------
// QKV GEMM: fused 2-term fp16 (Ah*W + Al*W sharing W fragments).
// CTA tile 128x128, 8 warps (2m x 4n). SMEM 2 sets x (Ah|Al|W = 48K).
// blockIdx.x: [0..23] -> matid = x>>3, n-tile = x&7. fp16 single output.
// ---------------------------------------------------------------------------
#define GSET 49152
#define QKV_SMEM_BYTES (2 * GSET + 1024)

__global__ __launch_bounds__(256, 2) void qkv_mma_kernel(
    const __half* __restrict__ A, const __half* __restrict__ Bc,
    const float* __restrict__ bq, const float* __restrict__ bk, const float* __restrict__ bv,
    __half* __restrict__ q16, __half* __restrict__ k16, __half* __restrict__ v16)
{
    extern __shared__ char dynsmem[];
    uint32_t base = (smem_u32(dynsmem) + 1023) & ~1023u;

    const int matid = blockIdx.x >> 3;
    const int n0 = (blockIdx.x & 7) * 128;
    const int m0 = blockIdx.y * 128;
    const __half* B = Bc + (size_t)matid * D_MODEL * D_MODEL;
    const float* bias = (matid == 0) ? bq : (matid == 1) ? bk : bv;
    __half* O = (matid == 0) ? q16 : (matid == 1) ? k16 : v16;
    const float scale = (matid == 0) ? 0.125f : 1.0f;

    const int tid = threadIdx.x;
    const int lane = tid & 31;
    const int wid = tid >> 5;
    const int warp_m = wid >> 2;
    const int warp_n = wid & 3;

    float acc[4][4][4];
#pragma unroll
    for (int i = 0; i < 4; i++)
#pragma unroll
        for (int j = 0; j < 4; j++)
#pragma unroll
            for (int r = 0; r < 4; r++) acc[i][j][r] = 0.0f;

    auto loadch = [&](int ch) {
        uint32_t s = base + (ch & 1) * GSET;
        load_tile128(s,         A, m0, ch * 64,           ACAT_W, tid);   // Ah
        load_tile128(s + 16384, A, m0, D_MODEL + ch * 64, ACAT_W, tid);   // Al
        load_tile128(s + 32768, B, n0, ch * 64,           D_MODEL, tid);  // W
        cp_commit();
    };

    loadch(0);

    for (int ch = 0; ch < NCHUNK; ch++) {
        cp_wait0();
        __syncthreads();
        if (ch + 1 < NCHUNK) loadch(ch + 1);

        const uint32_t sa = base + (ch & 1) * GSET;
        const uint32_t sl = sa + 16384;
        const uint32_t sw = sa + 32768;

#pragma unroll
        for (int step = 0; step < 4; step++) {
            uint32_t bfr[8];
#pragma unroll
            for (int jp = 0; jp < 2; jp++) {
                int nrow = warp_n * 32 + jp * 16 + ((lane >> 4) & 1) * 8 + (lane & 7);
                int kb   = step * 32 + ((lane >> 3) & 1) * 16;
                uint32_t addr = sw + swz128((uint32_t)(nrow * 128 + kb));
                ldmatrix_x4(bfr[jp * 4 + 0], bfr[jp * 4 + 1],
                            bfr[jp * 4 + 2], bfr[jp * 4 + 3], addr);
            }
            {
                uint32_t afr[4][4];
#pragma unroll
                for (int mt = 0; mt < 4; mt++) {
                    int row = warp_m * 64 + mt * 16 + (lane & 15);
                    int kb  = step * 32 + ((lane >> 4) << 4);
                    uint32_t addr = sa + swz128((uint32_t)(row * 128 + kb));
                    ldmatrix_x4(afr[mt][0], afr[mt][1], afr[mt][2], afr[mt][3], addr);
                }
#pragma unroll
                for (int mt = 0; mt < 4; mt++)
#pragma unroll
                    for (int nt = 0; nt < 4; nt++)
                        mma16816h(acc[mt][nt], afr[mt], bfr[nt * 2], bfr[nt * 2 + 1]);
            }
            {
                uint32_t afr[4][4];
#pragma unroll
                for (int mt = 0; mt < 4; mt++) {
                    int row = warp_m * 64 + mt * 16 + (lane & 15);
                    int kb  = step * 32 + ((lane >> 4) << 4);
                    uint32_t addr = sl + swz128((uint32_t)(row * 128 + kb));
                    ldmatrix_x4(afr[mt][0], afr[mt][1], afr[mt][2], afr[mt][3], addr);
                }
#pragma unroll
                for (int mt = 0; mt < 4; mt++)
#pragma unroll
                    for (int nt = 0; nt < 4; nt++)
                        mma16816h(acc[mt][nt], afr[mt], bfr[nt * 2], bfr[nt * 2 + 1]);
            }
        }
    }

#pragma unroll
    for (int mt = 0; mt < 4; mt++) {
        int row = m0 + warp_m * 64 + mt * 16 + (lane >> 2);
#pragma unroll
        for (int nt = 0; nt < 4; nt++) {
            int col = n0 + warp_n * 32 + nt * 8 + (lane & 3) * 2;
            float b0 = bias[col], b1 = bias[col + 1];
            *reinterpret_cast<uint32_t*>(O + (size_t)row * D_MODEL + col) =
                packh((acc[mt][nt][0] + b0) * scale, (acc[mt][nt][1] + b1) * scale);
            *reinterpret_cast<uint32_t*>(O + (size_t)(row + 8) * D_MODEL + col) =
                packh((acc[mt][nt][2] + b0) * scale, (acc[mt][nt][3] + b1) * scale);
        }
    }
}

// ---------------------------------------------------------------------------
// Output projection GEMM: SINGLE-term fp16 (O is fp16-rounded attention out).
// 3-stage cp.async pipeline (distance 2), 3 sets x (A 16K | W 16K) = 96KB.
// ---------------------------------------------------------------------------
#define OSET 32768
#define OPJ_SMEM_BYTES (3 * OSET + 1024)

__global__ __launch_bounds__(256, 2) void oproj_mma_kernel(
    const __half* __restrict__ A, const __half* __restrict__ B,
    const float* __restrict__ bias, float* __restrict__ C)
{
    extern __shared__ char dynsmem[];
    uint32_t base = (smem_u32(dynsmem) + 1023) & ~1023u;

    const int n0 = blockIdx.x * 128;
    const int m0 = blockIdx.y * 128;

    const int tid = threadIdx.x;
    const int lane = tid & 31;
    const int wid = tid >> 5;
    const int warp_m = wid >> 2;
    const int warp_n = wid & 3;

    float acc[4][4][4];
#pragma unroll
    for (int i = 0; i < 4; i++)
#pragma unroll
        for (int j = 0; j < 4; j++)
#pragma unroll
            for (int r = 0; r < 4; r++) acc[i][j][r] = 0.0f;

    auto loadch = [&](int ch, int s) {
        uint32_t sb = base + s * OSET;
        load_tile128(sb,         A, m0, ch * 64, D_MODEL, tid);
        load_tile128(sb + 16384, B, n0, ch * 64, D_MODEL, tid);
        cp_commit();
    };

    loadch(0, 0);
    loadch(1, 1);

    int scur = 0, snext = 2;
    for (int ch = 0; ch < NCHUNK; ch++) {
        if (ch + 1 < NCHUNK) cp_wait1(); else cp_wait0();
        __syncthreads();
        if (ch + 2 < NCHUNK) loadch(ch + 2, snext);

        const uint32_t sa = base + scur * OSET;
        const uint32_t sw = sa + 16384;

#pragma unroll
        for (int step = 0; step < 4; step++) {
            uint32_t afr[4][4];
#pragma unroll
            for (int mt = 0; mt < 4; mt++) {
                int row = warp_m * 64 + mt * 16 + (lane & 15);
                int kb  = step * 32 + ((lane >> 4) << 4);
                uint32_t addr = sa + swz128((uint32_t)(row * 128 + kb));
                ldmatrix_x4(afr[mt][0], afr[mt][1], afr[mt][2], afr[mt][3], addr);
            }
            uint32_t bfr[8];
#pragma unroll
            for (int jp = 0; jp < 2; jp++) {
                int nrow = warp_n * 32 + jp * 16 + ((lane >> 4) & 1) * 8 + (lane & 7);
                int kb   = step * 32 + ((lane >> 3) & 1) * 16;
                uint32_t addr = sw + swz128((uint32_t)(nrow * 128 + kb));
                ldmatrix_x4(bfr[jp * 4 + 0], bfr[jp * 4 + 1],
                            bfr[jp * 4 + 2], bfr[jp * 4 + 3], addr);
            }
#pragma unroll
            for (int mt = 0; mt < 4; mt++)
#pragma unroll
                for (int nt = 0; nt < 4; nt++)
                    mma16816h(acc[mt][nt], afr[mt], bfr[nt * 2], bfr[nt * 2 + 1]);
        }

        scur = (scur == 2) ? 0 : scur + 1;
        snext = (snext == 2) ? 0 : snext + 1;
    }

#pragma unroll
    for (int mt = 0; mt < 4; mt++) {
        int row = m0 + warp_m * 64 + mt * 16 + (lane >> 2);
#pragma unroll
        for (int nt = 0; nt < 4; nt++) {
            int col = n0 + warp_n * 32 + nt * 8 + (lane & 3) * 2;
            float b0 = bias[col], b1 = bias[col + 1];
            float2 w0; w0.x = acc[mt][nt][0] + b0; w0.y = acc[mt][nt][1] + b1;
            float2 w1; w1.x = acc[mt][nt][2] + b0; w1.y = acc[mt][nt][3] + b1;
            *reinterpret_cast<float2*>(C + (size_t)row * D_MODEL + col) = w0;
            *reinterpret_cast<float2*>(C + (size_t)(row + 8) * D_MODEL + col) = w1;
        }
    }
}

// ---------------------------------------------------------------------------
// Tensor-core windowed attention (flash-style, fp16).
// CTA: 128 q rows x (head, batch). 4 warps x 32 rows. Key chunks of 64.
// S = Q16*K16. PV = Phi * V16. Masks applied only on boundary chunks.
// Output: single fp16 into o16.
// ---------------------------------------------------------------------------
#define ATT_SMEM (48 * 1024 + 1024)

__global__ __launch_bounds__(128) void attn_tc_kernel(
    const __half* __restrict__ q16, const __half* __restrict__ k16,
    const __half* __restrict__ v16, __half* __restrict__ o16)
{
    extern __shared__ char dynsmem[];
    uint32_t base = (smem_u32(dynsmem) + 1023) & ~1023u;
    const uint32_t Qs  = base;                 // 16KB
    const uint32_t KV0 = base + 16384;         // K @ +0 (8KB), V @ +8192
    const uint32_t KV1 = base + 32768;

    const int tid = threadIdx.x, wid = tid >> 5, lane = tid & 31;
    const int q0 = blockIdx.x * 128;
    const int h  = blockIdx.y;
    const int b  = blockIdx.z;
    const size_t rowbase = (size_t)b * SEQ + q0;
    const int hoff = h * HDIM;

    {
        const char* qp = reinterpret_cast<const char*>(q16 + rowbase * D_MODEL + hoff);
#pragma unroll
        for (int it = 0; it < 8; it++) {
            int idx = it * 128 + tid;
            int row = idx >> 3;
            int seg = (idx & 7) << 4;
            uint32_t sw = swz128((uint32_t)(row * 128 + seg));
            cp_async16(Qs + sw, qp + (size_t)row * 2048 + seg);
        }
        cp_commit();
    }

    int c0 = q0 - WINDOW; if (c0 < 0) c0 = 0;
    const int nch = (q0 + 128 - c0) >> 6;

    auto load_kv = [&](int c, uint32_t kvb) {
        const char* kp = reinterpret_cast<const char*>(k16 + ((size_t)b * SEQ + c) * D_MODEL + hoff);
        const char* vp = reinterpret_cast<const char*>(v16 + ((size_t)b * SEQ + c) * D_MODEL + hoff);
#pragma unroll
        for (int it = 0; it < 4; it++) {
            int idx = it * 128 + tid;
            int row = idx >> 3;
            int seg = (idx & 7) << 4;
            uint32_t sw = swz128((uint32_t)(row * 128 + seg));
            size_t go = (size_t)row * 2048 + seg;
            cp_async16(kvb + 0    + sw, kp + go);
            cp_async16(kvb + 8192 + sw, vp + go);
        }
        cp_commit();
    };

    load_kv(c0, KV0);

    float O[2][8][4];
#pragma unroll
    for (int mt = 0; mt < 2; mt++)
#pragma unroll
        for (int nt = 0; nt < 8; nt++)
#pragma unroll
            for (int r = 0; r < 4; r++) O[mt][nt][r] = 0.0f;
    float mrow[2][2] = {{-1e30f, -1e30f}, {-1e30f, -1e30f}};
    float lrow[2][2] = {{0.f, 0.f}, {0.f, 0.f}};

    const float NEGINF = __int_as_float(0xff800000);

    for (int ch = 0; ch < nch; ch++) {
        const uint32_t kvb = (ch & 1) ? KV1 : KV0;
        if (ch + 1 < nch) {
            load_kv(c0 + (ch + 1) * 64, (ch & 1) ? KV0 : KV1);
            cp_wait1();
        } else {
            cp_wait0();
        }
        __syncthreads();

        const int c = c0 + ch * 64;
        // mask needed only on boundary chunks
        const bool needMask = (c + 63 >= q0) || (c < q0 + 128 - WINDOW);

        float S[2][8][4];
#pragma unroll
        for (int mt = 0; mt < 2; mt++)
#pragma unroll
            for (int nt = 0; nt < 8; nt++)
#pragma unroll
                for (int r = 0; r < 4; r++) S[mt][nt][r] = 0.0f;

#pragma unroll
        for (int kt = 0; kt < 4; kt++) {
            uint32_t qa[2][4];
#pragma unroll
            for (int mt = 0; mt < 2; mt++) {
                int row = wid * 32 + mt * 16 + (lane & 15);
                int kb  = kt * 32 + ((lane >> 4) << 4);
                uint32_t sw = swz128((uint32_t)(row * 128 + kb));
                ldmatrix_x4(qa[mt][0], qa[mt][1], qa[mt][2], qa[mt][3], Qs + sw);
            }
#pragma unroll
            for (int np = 0; np < 4; np++) {
                int nr = np * 16 + ((lane >> 4) & 1) * 8 + (lane & 7);
                int kb = kt * 32 + ((lane >> 3) & 1) * 16;
                uint32_t sw = swz128((uint32_t)(nr * 128 + kb));
                uint32_t kf[4];
                ldmatrix_x4(kf[0], kf[1], kf[2], kf[3], kvb + 0 + sw);
#pragma unroll
                for (int mt = 0; mt < 2; mt++)
#pragma unroll
                    for (int half = 0; half < 2; half++) {
                        int nt = np * 2 + half;
                        mma16816h(S[mt][nt], qa[mt], kf[half * 2], kf[half * 2 + 1]);
                    }
            }
        }

        uint32_t Phi[2][4][4];
#pragma unroll
        for (int mt = 0; mt < 2; mt++) {
            int i0 = q0 + wid * 32 + mt * 16 + (lane >> 2);
            int i1 = i0 + 8;
            if (needMask) {
#pragma unroll
                for (int nt = 0; nt < 8; nt++) {
                    int j = c + nt * 8 + (lane & 3) * 2;
                    if (j     > i0 || j     < i0 - WINDOW) S[mt][nt][0] = NEGINF;
                    if (j + 1 > i0 || j + 1 < i0 - WINDOW) S[mt][nt][1] = NEGINF;
                    if (j     > i1 || j     < i1 - WINDOW) S[mt][nt][2] = NEGINF;
                    if (j + 1 > i1 || j + 1 < i1 - WINDOW) S[mt][nt][3] = NEGINF;
                }
            }
#pragma unroll
            for (int half = 0; half < 2; half++) {
                float cm = NEGINF;
#pragma unroll
                for (int nt = 0; nt < 8; nt++)
                    cm = fmaxf(cm, fmaxf(S[mt][nt][half * 2], S[mt][nt][half * 2 + 1]));
                cm = fmaxf(cm, __shfl_xor_sync(0xffffffffu, cm, 1));
                cm = fmaxf(cm, __shfl_xor_sync(0xffffffffu, cm, 2));
                float mold = mrow[mt][half];
                float mnew = fmaxf(mold, cm);
                float corr = __expf(mold - mnew);
                mrow[mt][half] = mnew;
                float psum = 0.0f;
#pragma unroll
                for (int nt = 0; nt < 8; nt++) {
                    float p0 = __expf(S[mt][nt][half * 2]     - mnew);
                    float p1 = __expf(S[mt][nt][half * 2 + 1] - mnew);
                    psum += p0 + p1;
                    O[mt][nt][half * 2]     *= corr;
                    O[mt][nt][half * 2 + 1] *= corr;
                    int kt = nt >> 1, hh = nt & 1;
                    Phi[mt][kt][hh * 2 + half] = packh(p0, p1);
                }
                psum += __shfl_xor_sync(0xffffffffu, psum, 1);
                psum += __shfl_xor_sync(0xffffffffu, psum, 2);
                lrow[mt][half] = lrow[mt][half] * corr + psum;
            }
        }

#pragma unroll
        for (int kt = 0; kt < 4; kt++) {
#pragma unroll
            for (int np = 0; np < 4; np++) {
                int g = lane >> 3;
                int key = kt * 16 + (g & 1) * 8 + (lane & 7);
                int nb  = np * 32 + ((g >> 1) << 4);
                uint32_t sw = swz128((uint32_t)(key * 128 + nb));
                uint32_t vf[4];
                ldmatrix_x4t(vf[0], vf[1], vf[2], vf[3], kvb + 8192 + sw);
#pragma unroll
                for (int mt = 0; mt < 2; mt++)
#pragma unroll
                    for (int half = 0; half < 2; half++) {
                        int nt = np * 2 + half;
                        mma16816h(O[mt][nt], Phi[mt][kt], vf[half * 2], vf[half * 2 + 1]);
                    }
            }
        }
        __syncthreads();
    }

    // normalize + write o16 (single fp16)
#pragma unroll
    for (int mt = 0; mt < 2; mt++) {
        size_t rA = rowbase + wid * 32 + mt * 16 + (lane >> 2);
        size_t rB = rA + 8;
        float inv0 = 1.0f / lrow[mt][0];
        float inv1 = 1.0f / lrow[mt][1];
#pragma unroll
        for (int nt = 0; nt < 8; nt++) {
            int col = hoff + nt * 8 + (lane & 3) * 2;
            *reinterpret_cast<uint32_t*>(o16 + rA * D_MODEL + col) =
                packh(O[mt][nt][0] * inv0, O[mt][nt][1] * inv0);
            *reinterpret_cast<uint32_t*>(o16 + rB * D_MODEL + col) =
                packh(O[mt][nt][2] * inv1, O[mt][nt][3] * inv1);
        }
    }
}

// ---------------------------------------------------------------------------
// Launch.  Inputs: x, Wq, bq, Wk, bk, Wv, bv, Wo, bo
// ---------------------------------------------------------------------------
extern "C" void kernel_launch(void* const* d_in, const int* in_sizes, int n_in,
                              void* d_out, int out_size)
{
    const float* x  = (const float*)d_in[0];
    const float* Wq = (const float*)d_in[1];
    const float* bq = (const float*)d_in[2];
    const float* Wk = (const float*)d_in[3];
    const float* bk = (const float*)d_in[4];
    const float* Wv = (const float*)d_in[5];
    const float* bv = (const float*)d_in[6];
    const float* Wo = (const float*)d_in[7];
    const float* bo = (const float*)d_in[8];
    float* out = (float*)d_out;

    __half *acat, *bcat, *q16, *k16, *v16, *o16;
    cudaGetSymbolAddress((void**)&acat, g_acat);
    cudaGetSymbolAddress((void**)&bcat, g_bcat);
    cudaGetSymbolAddress((void**)&q16, g_q16);
    cudaGetSymbolAddress((void**)&k16, g_k16);
    cudaGetSymbolAddress((void**)&v16, g_v16);
    cudaGetSymbolAddress((void**)&o16, g_o16);

    cudaFuncSetAttribute(qkv_mma_kernel,
                         cudaFuncAttributeMaxDynamicSharedMemorySize, QKV_SMEM_BYTES);
    cudaFuncSetAttribute(oproj_mma_kernel,
                         cudaFuncAttributeMaxDynamicSharedMemorySize, OPJ_SMEM_BYTES);
    cudaFuncSetAttribute(attn_tc_kernel,
                         cudaFuncAttributeMaxDynamicSharedMemorySize, ATT_SMEM);

    const size_t WSTRIDE = (size_t)D_MODEL * D_MODEL;

    convA_kernel<<<M_TOT * D_MODEL / 4 / 256, 256>>>(x, acat);
    dim3 cw_grid(32, 32, 4), cw_blk(32, 8);
    convW4_kernel<<<cw_grid, cw_blk>>>(Wq, Wk, Wv, Wo, bcat);

    // fused QKV projections -> fp16 (Q pre-scaled by 0.125)
    dim3 qkv_grid(24, 32);
    qkv_mma_kernel<<<qkv_grid, 256, QKV_SMEM_BYTES>>>(acat, bcat, bq, bk, bv,
                                                      q16, k16, v16);

    // tensor-core windowed attention -> single-fp16 o16
    dim3 attn_grid(SEQ / 128, NHEADS, BATCH);    // (16, 16, 2)
    attn_tc_kernel<<<attn_grid, 128, ATT_SMEM>>>(q16, k16, v16, o16);

    // output projection (single-term) -> fp32
    dim3 o_grid(8, 32);
    oproj_mma_kernel<<<o_grid, 256, OPJ_SMEM_BYTES>>>(o16, bcat + 3 * WSTRIDE, bo, out);
}

// round 14
// speedup vs baseline: 2.1431x; 1.1742x over previous
#include <cuda_runtime.h>
#include <cuda_fp16.h>
#include <cstdint>
#include <math.h>

// ---------------------------------------------------------------------------
// Problem constants
// ---------------------------------------------------------------------------
#define D_MODEL 1024
#define NHEADS  16
#define HDIM    64
#define WINDOW  256
#define BATCH   2
#define SEQ     2048
#define M_TOT   (BATCH * SEQ)     // 4096
#define ACAT_W  2048              // [hi | lo] fp16 A-split width
#define NCHUNK  16                // 16 k-chunks of 64

// ---------------------------------------------------------------------------
// Scratch (no cudaMalloc allowed)
// ---------------------------------------------------------------------------
__device__ __half g_acat[(size_t)M_TOT * ACAT_W];        // [4096][2048] fp16
__device__ __half g_bcat[4][(size_t)D_MODEL * D_MODEL];  // [1024 n][1024 k] fp16
__device__ __half g_q16[(size_t)M_TOT * D_MODEL];
__device__ __half g_k16[(size_t)M_TOT * D_MODEL];
__device__ __half g_v16[(size_t)M_TOT * D_MODEL];
__device__ __half g_o16[(size_t)M_TOT * D_MODEL];        // attn output, single fp16

// ---------------------------------------------------------------------------
// Helpers
// ---------------------------------------------------------------------------
__device__ __forceinline__ uint32_t smem_u32(const void* p) {
    uint32_t a;
    asm("{ .reg .u64 t; cvta.to.shared.u64 t, %1; cvt.u32.u64 %0, t; }" : "=r"(a) : "l"(p));
    return a;
}
__device__ __forceinline__ uint32_t swz128(uint32_t off) {
    return off ^ ((off >> 3) & 0x70);
}
__device__ __forceinline__ void cp_async16(uint32_t saddr, const void* gaddr) {
    asm volatile("cp.async.cg.shared.global [%0], [%1], 16;" :: "r"(saddr), "l"(gaddr));
}
__device__ __forceinline__ void cp_commit() {
    asm volatile("cp.async.commit_group;" ::: "memory");
}
__device__ __forceinline__ void cp_wait1() {
    asm volatile("cp.async.wait_group 1;" ::: "memory");
}
__device__ __forceinline__ void cp_wait0() {
    asm volatile("cp.async.wait_group 0;" ::: "memory");
}
__device__ __forceinline__ void ldmatrix_x4(uint32_t& r0, uint32_t& r1,
                                            uint32_t& r2, uint32_t& r3, uint32_t addr) {
    asm volatile("ldmatrix.sync.aligned.m8n8.x4.shared.b16 {%0,%1,%2,%3}, [%4];"
                 : "=r"(r0), "=r"(r1), "=r"(r2), "=r"(r3) : "r"(addr));
}
__device__ __forceinline__ void ldmatrix_x4t(uint32_t& r0, uint32_t& r1,
                                             uint32_t& r2, uint32_t& r3, uint32_t addr) {
    asm volatile("ldmatrix.sync.aligned.m8n8.x4.trans.shared.b16 {%0,%1,%2,%3}, [%4];"
                 : "=r"(r0), "=r"(r1), "=r"(r2), "=r"(r3) : "r"(addr));
}
// fp16 MMA, fp32 accum
__device__ __forceinline__ void mma16816h(float* d, const uint32_t* a,
                                          uint32_t b0, uint32_t b1) {
    asm volatile(
        "mma.sync.aligned.m16n8k16.row.col.f32.f16.f16.f32 "
        "{%0,%1,%2,%3}, {%4,%5,%6,%7}, {%8,%9}, {%0,%1,%2,%3};"
        : "+f"(d[0]), "+f"(d[1]), "+f"(d[2]), "+f"(d[3])
        : "r"(a[0]), "r"(a[1]), "r"(a[2]), "r"(a[3]), "r"(b0), "r"(b1));
}
__device__ __forceinline__ uint32_t packh(float a, float b) {
    __half2 h = __floats2half2_rn(a, b);
    return *reinterpret_cast<uint32_t*>(&h);
}

// ---------------------------------------------------------------------------
// convA: src [M,1024] fp32 -> dst [M,2048] fp16 = [hi | lo]  (exact A split)
// ---------------------------------------------------------------------------
__global__ __launch_bounds__(256) void convA_kernel(const float* __restrict__ src,
                                                    __half* __restrict__ dst)
{
    int idx = blockIdx.x * blockDim.x + threadIdx.x;
    float4 v = reinterpret_cast<const float4*>(src)[idx];
    int row = idx >> 8;
    int c4  = idx & 255;

    __half hx = __float2half(v.x), hy = __float2half(v.y);
    __half hz = __float2half(v.z), hw = __float2half(v.w);
    float lx = v.x - __half2float(hx), ly = v.y - __half2float(hy);
    float lz = v.z - __half2float(hz), lw = v.w - __half2float(hw);

    __half* r = dst + (size_t)row * ACAT_W;
    uint32_t* p0 = reinterpret_cast<uint32_t*>(r) + c4 * 2;
    __half2 h0; h0.x = hx; h0.y = hy;
    __half2 h1; h1.x = hz; h1.y = hw;
    p0[0] = *reinterpret_cast<uint32_t*>(&h0);
    p0[1] = *reinterpret_cast<uint32_t*>(&h1);
    uint32_t* p1 = reinterpret_cast<uint32_t*>(r + D_MODEL) + c4 * 2;
    p1[0] = packh(lx, ly);
    p1[1] = packh(lz, lw);
}

// ---------------------------------------------------------------------------
// convW (all 4 weights, blockIdx.z selects): W[k][n] fp32 -> B[n][1024k] fp16
// ---------------------------------------------------------------------------
__global__ __launch_bounds__(256) void convW4_kernel(
    const float* __restrict__ W0, const float* __restrict__ W1,
    const float* __restrict__ W2, const float* __restrict__ W3,
    __half* __restrict__ Bbase)
{
    __shared__ float tile[32][33];
    const float* W = (blockIdx.z == 0) ? W0 : (blockIdx.z == 1) ? W1
                     : (blockIdx.z == 2) ? W2 : W3;
    __half* B = Bbase + (size_t)blockIdx.z * D_MODEL * D_MODEL;

    int n0 = blockIdx.x * 32;
    int k0 = blockIdx.y * 32;
    int tx = threadIdx.x, ty = threadIdx.y;   // (32, 8)

#pragma unroll
    for (int i = 0; i < 32; i += 8)
        tile[ty + i][tx] = W[(size_t)(k0 + ty + i) * D_MODEL + n0 + tx];
    __syncthreads();

#pragma unroll
    for (int i = 0; i < 32; i += 8) {
        int n = n0 + ty + i;
        int k = k0 + tx;
        B[(size_t)n * D_MODEL + k] = __float2half(tile[tx][ty + i]);
    }
}

// ---------------------------------------------------------------------------
// Shared tile loader: 128 rows x 64 fp16 (128B/row), SW128 swizzle
// ---------------------------------------------------------------------------
__device__ __forceinline__ void load_tile128(uint32_t dst, const __half* src,
                                             int row0, int col0, int stride, int tid)
{
#pragma unroll
    for (int it = 0; it < 4; it++) {
        int idx = it * 256 + tid;
        int row = idx >> 3;
        int seg = (idx & 7) << 4;
        uint32_t sw = swz128((uint32_t)(row * 128 + seg));
        cp_async16(dst + sw,
                   reinterpret_cast<const char*>(src + (size_t)(row0 + row) * stride + col0) + seg);
    }
}

// ---------------------------------------------------------------------------
// QKV GEMM: fused fp16.
//   matid 0 (Q), 1 (K): SINGLE-term (Ah*W) — q/k logit errors wash in softmax.
//   matid 2 (V): 2-term (Ah*W + Al*W) — V passes straight to output.
// CTA tile 128x128, 8 warps (2m x 4n). SMEM 2 sets x (Ah|Al|W = 48K).
// blockIdx.x: [0..23] -> matid = x>>3, n-tile = x&7. fp16 output.
// ---------------------------------------------------------------------------
#define GSET 49152
#define QKV_SMEM_BYTES (2 * GSET + 1024)

__global__ __launch_bounds__(256, 2) void qkv_mma_kernel(
    const __half* __restrict__ A, const __half* __restrict__ Bc,
    const float* __restrict__ bq, const float* __restrict__ bk, const float* __restrict__ bv,
    __half* __restrict__ q16, __half* __restrict__ k16, __half* __restrict__ v16)
{
    extern __shared__ char dynsmem[];
    uint32_t base = (smem_u32(dynsmem) + 1023) & ~1023u;

    const int matid = blockIdx.x >> 3;
    const int n0 = (blockIdx.x & 7) * 128;
    const int m0 = blockIdx.y * 128;
    const __half* B = Bc + (size_t)matid * D_MODEL * D_MODEL;
    const float* bias = (matid == 0) ? bq : (matid == 1) ? bk : bv;
    __half* O = (matid == 0) ? q16 : (matid == 1) ? k16 : v16;
    const float scale = (matid == 0) ? 0.125f : 1.0f;
    const bool twoTerm = (matid == 2);

    const int tid = threadIdx.x;
    const int lane = tid & 31;
    const int wid = tid >> 5;
    const int warp_m = wid >> 2;
    const int warp_n = wid & 3;

    float acc[4][4][4];
#pragma unroll
    for (int i = 0; i < 4; i++)
#pragma unroll
        for (int j = 0; j < 4; j++)
#pragma unroll
            for (int r = 0; r < 4; r++) acc[i][j][r] = 0.0f;

    auto loadch = [&](int ch) {
        uint32_t s = base + (ch & 1) * GSET;
        load_tile128(s,         A, m0, ch * 64,           ACAT_W, tid);       // Ah
        if (twoTerm)
            load_tile128(s + 16384, A, m0, D_MODEL + ch * 64, ACAT_W, tid);   // Al
        load_tile128(s + 32768, B, n0, ch * 64,           D_MODEL, tid);      // W
        cp_commit();
    };

    loadch(0);

    for (int ch = 0; ch < NCHUNK; ch++) {
        cp_wait0();
        __syncthreads();
        if (ch + 1 < NCHUNK) loadch(ch + 1);

        const uint32_t sa = base + (ch & 1) * GSET;
        const uint32_t sl = sa + 16384;
        const uint32_t sw = sa + 32768;

#pragma unroll
        for (int step = 0; step < 4; step++) {
            uint32_t bfr[8];
#pragma unroll
            for (int jp = 0; jp < 2; jp++) {
                int nrow = warp_n * 32 + jp * 16 + ((lane >> 4) & 1) * 8 + (lane & 7);
                int kb   = step * 32 + ((lane >> 3) & 1) * 16;
                uint32_t addr = sw + swz128((uint32_t)(nrow * 128 + kb));
                ldmatrix_x4(bfr[jp * 4 + 0], bfr[jp * 4 + 1],
                            bfr[jp * 4 + 2], bfr[jp * 4 + 3], addr);
            }
            {
                uint32_t afr[4][4];
#pragma unroll
                for (int mt = 0; mt < 4; mt++) {
                    int row = warp_m * 64 + mt * 16 + (lane & 15);
                    int kb  = step * 32 + ((lane >> 4) << 4);
                    uint32_t addr = sa + swz128((uint32_t)(row * 128 + kb));
                    ldmatrix_x4(afr[mt][0], afr[mt][1], afr[mt][2], afr[mt][3], addr);
                }
#pragma unroll
                for (int mt = 0; mt < 4; mt++)
#pragma unroll
                    for (int nt = 0; nt < 4; nt++)
                        mma16816h(acc[mt][nt], afr[mt], bfr[nt * 2], bfr[nt * 2 + 1]);
            }
            if (twoTerm) {
                uint32_t afr[4][4];
#pragma unroll
                for (int mt = 0; mt < 4; mt++) {
                    int row = warp_m * 64 + mt * 16 + (lane & 15);
                    int kb  = step * 32 + ((lane >> 4) << 4);
                    uint32_t addr = sl + swz128((uint32_t)(row * 128 + kb));
                    ldmatrix_x4(afr[mt][0], afr[mt][1], afr[mt][2], afr[mt][3], addr);
                }
#pragma unroll
                for (int mt = 0; mt < 4; mt++)
#pragma unroll
                    for (int nt = 0; nt < 4; nt++)
                        mma16816h(acc[mt][nt], afr[mt], bfr[nt * 2], bfr[nt * 2 + 1]);
            }
        }
    }

#pragma unroll
    for (int mt = 0; mt < 4; mt++) {
        int row = m0 + warp_m * 64 + mt * 16 + (lane >> 2);
#pragma unroll
        for (int nt = 0; nt < 4; nt++) {
            int col = n0 + warp_n * 32 + nt * 8 + (lane & 3) * 2;
            float b0 = bias[col], b1 = bias[col + 1];
            *reinterpret_cast<uint32_t*>(O + (size_t)row * D_MODEL + col) =
                packh((acc[mt][nt][0] + b0) * scale, (acc[mt][nt][1] + b1) * scale);
            *reinterpret_cast<uint32_t*>(O + (size_t)(row + 8) * D_MODEL + col) =
                packh((acc[mt][nt][2] + b0) * scale, (acc[mt][nt][3] + b1) * scale);
        }
    }
}

// ---------------------------------------------------------------------------
// Output projection GEMM: SINGLE-term fp16, 3-stage cp.async pipeline.
// ---------------------------------------------------------------------------
#define OSET 32768
#define OPJ_SMEM_BYTES (3 * OSET + 1024)

__global__ __launch_bounds__(256, 2) void oproj_mma_kernel(
    const __half* __restrict__ A, const __half* __restrict__ B,
    const float* __restrict__ bias, float* __restrict__ C)
{
    extern __shared__ char dynsmem[];
    uint32_t base = (smem_u32(dynsmem) + 1023) & ~1023u;

    const int n0 = blockIdx.x * 128;
    const int m0 = blockIdx.y * 128;

    const int tid = threadIdx.x;
    const int lane = tid & 31;
    const int wid = tid >> 5;
    const int warp_m = wid >> 2;
    const int warp_n = wid & 3;

    float acc[4][4][4];
#pragma unroll
    for (int i = 0; i < 4; i++)
#pragma unroll
        for (int j = 0; j < 4; j++)
#pragma unroll
            for (int r = 0; r < 4; r++) acc[i][j][r] = 0.0f;

    auto loadch = [&](int ch, int s) {
        uint32_t sb = base + s * OSET;
        load_tile128(sb,         A, m0, ch * 64, D_MODEL, tid);
        load_tile128(sb + 16384, B, n0, ch * 64, D_MODEL, tid);
        cp_commit();
    };

    loadch(0, 0);
    loadch(1, 1);

    int scur = 0, snext = 2;
    for (int ch = 0; ch < NCHUNK; ch++) {
        if (ch + 1 < NCHUNK) cp_wait1(); else cp_wait0();
        __syncthreads();
        if (ch + 2 < NCHUNK) loadch(ch + 2, snext);

        const uint32_t sa = base + scur * OSET;
        const uint32_t sw = sa + 16384;

#pragma unroll
        for (int step = 0; step < 4; step++) {
            uint32_t afr[4][4];
#pragma unroll
            for (int mt = 0; mt < 4; mt++) {
                int row = warp_m * 64 + mt * 16 + (lane & 15);
                int kb  = step * 32 + ((lane >> 4) << 4);
                uint32_t addr = sa + swz128((uint32_t)(row * 128 + kb));
                ldmatrix_x4(afr[mt][0], afr[mt][1], afr[mt][2], afr[mt][3], addr);
            }
            uint32_t bfr[8];
#pragma unroll
            for (int jp = 0; jp < 2; jp++) {
                int nrow = warp_n * 32 + jp * 16 + ((lane >> 4) & 1) * 8 + (lane & 7);
                int kb   = step * 32 + ((lane >> 3) & 1) * 16;
                uint32_t addr = sw + swz128((uint32_t)(nrow * 128 + kb));
                ldmatrix_x4(bfr[jp * 4 + 0], bfr[jp * 4 + 1],
                            bfr[jp * 4 + 2], bfr[jp * 4 + 3], addr);
            }
#pragma unroll
            for (int mt = 0; mt < 4; mt++)
#pragma unroll
                for (int nt = 0; nt < 4; nt++)
                    mma16816h(acc[mt][nt], afr[mt], bfr[nt * 2], bfr[nt * 2 + 1]);
        }

        scur = (scur == 2) ? 0 : scur + 1;
        snext = (snext == 2) ? 0 : snext + 1;
    }

#pragma unroll
    for (int mt = 0; mt < 4; mt++) {
        int row = m0 + warp_m * 64 + mt * 16 + (lane >> 2);
#pragma unroll
        for (int nt = 0; nt < 4; nt++) {
            int col = n0 + warp_n * 32 + nt * 8 + (lane & 3) * 2;
            float b0 = bias[col], b1 = bias[col + 1];
            float2 w0; w0.x = acc[mt][nt][0] + b0; w0.y = acc[mt][nt][1] + b1;
            float2 w1; w1.x = acc[mt][nt][2] + b0; w1.y = acc[mt][nt][3] + b1;
            *reinterpret_cast<float2*>(C + (size_t)row * D_MODEL + col) = w0;
            *reinterpret_cast<float2*>(C + (size_t)(row + 8) * D_MODEL + col) = w1;
        }
    }
}

// ---------------------------------------------------------------------------
// Tensor-core windowed attention (flash-style, fp16).
// CTA: 128 q rows x (head, batch). 4 warps x 32 rows. Key chunks of 64.
// S = Q16*K16. PV = Phi * V16. Masks applied only on boundary chunks.
// Output: single fp16 into o16.
// ---------------------------------------------------------------------------
#define ATT_SMEM (48 * 1024 + 1024)

__global__ __launch_bounds__(128) void attn_tc_kernel(
    const __half* __restrict__ q16, const __half* __restrict__ k16,
    const __half* __restrict__ v16, __half* __restrict__ o16)
{
    extern __shared__ char dynsmem[];
    uint32_t base = (smem_u32(dynsmem) + 1023) & ~1023u;
    const uint32_t Qs  = base;                 // 16KB
    const uint32_t KV0 = base + 16384;         // K @ +0 (8KB), V @ +8192
    const uint32_t KV1 = base + 32768;

    const int tid = threadIdx.x, wid = tid >> 5, lane = tid & 31;
    const int q0 = blockIdx.x * 128;
    const int h  = blockIdx.y;
    const int b  = blockIdx.z;
    const size_t rowbase = (size_t)b * SEQ + q0;
    const int hoff = h * HDIM;

    {
        const char* qp = reinterpret_cast<const char*>(q16 + rowbase * D_MODEL + hoff);
#pragma unroll
        for (int it = 0; it < 8; it++) {
            int idx = it * 128 + tid;
            int row = idx >> 3;
            int seg = (idx & 7) << 4;
            uint32_t sw = swz128((uint32_t)(row * 128 + seg));
            cp_async16(Qs + sw, qp + (size_t)row * 2048 + seg);
        }
        cp_commit();
    }

    int c0 = q0 - WINDOW; if (c0 < 0) c0 = 0;
    const int nch = (q0 + 128 - c0) >> 6;

    auto load_kv = [&](int c, uint32_t kvb) {
        const char* kp = reinterpret_cast<const char*>(k16 + ((size_t)b * SEQ + c) * D_MODEL + hoff);
        const char* vp = reinterpret_cast<const char*>(v16 + ((size_t)b * SEQ + c) * D_MODEL + hoff);
#pragma unroll
        for (int it = 0; it < 4; it++) {
            int idx = it * 128 + tid;
            int row = idx >> 3;
            int seg = (idx & 7) << 4;
            uint32_t sw = swz128((uint32_t)(row * 128 + seg));
            size_t go = (size_t)row * 2048 + seg;
            cp_async16(kvb + 0    + sw, kp + go);
            cp_async16(kvb + 8192 + sw, vp + go);
        }
        cp_commit();
    };

    load_kv(c0, KV0);

    float O[2][8][4];
#pragma unroll
    for (int mt = 0; mt < 2; mt++)
#pragma unroll
        for (int nt = 0; nt < 8; nt++)
#pragma unroll
            for (int r = 0; r < 4; r++) O[mt][nt][r] = 0.0f;
    float mrow[2][2] = {{-1e30f, -1e30f}, {-1e30f, -1e30f}};
    float lrow[2][2] = {{0.f, 0.f}, {0.f, 0.f}};

    const float NEGINF = __int_as_float(0xff800000);

    for (int ch = 0; ch < nch; ch++) {
        const uint32_t kvb = (ch & 1) ? KV1 : KV0;
        if (ch + 1 < nch) {
            load_kv(c0 + (ch + 1) * 64, (ch & 1) ? KV0 : KV1);
            cp_wait1();
        } else {
            cp_wait0();
        }
        __syncthreads();

        const int c = c0 + ch * 64;
        const bool needMask = (c + 63 >= q0) || (c < q0 + 128 - WINDOW);

        float S[2][8][4];
#pragma unroll
        for (int mt = 0; mt < 2; mt++)
#pragma unroll
            for (int nt = 0; nt < 8; nt++)
#pragma unroll
                for (int r = 0; r < 4; r++) S[mt][nt][r] = 0.0f;

#pragma unroll
        for (int kt = 0; kt < 4; kt++) {
            uint32_t qa[2][4];
#pragma unroll
            for (int mt = 0; mt < 2; mt++) {
                int row = wid * 32 + mt * 16 + (lane & 15);
                int kb  = kt * 32 + ((lane >> 4) << 4);
                uint32_t sw = swz128((uint32_t)(row * 128 + kb));
                ldmatrix_x4(qa[mt][0], qa[mt][1], qa[mt][2], qa[mt][3], Qs + sw);
            }
#pragma unroll
            for (int np = 0; np < 4; np++) {
                int nr = np * 16 + ((lane >> 4) & 1) * 8 + (lane & 7);
                int kb = kt * 32 + ((lane >> 3) & 1) * 16;
                uint32_t sw = swz128((uint32_t)(nr * 128 + kb));
                uint32_t kf[4];
                ldmatrix_x4(kf[0], kf[1], kf[2], kf[3], kvb + 0 + sw);
#pragma unroll
                for (int mt = 0; mt < 2; mt++)
#pragma unroll
                    for (int half = 0; half < 2; half++) {
                        int nt = np * 2 + half;
                        mma16816h(S[mt][nt], qa[mt], kf[half * 2], kf[half * 2 + 1]);
                    }
            }
        }

        uint32_t Phi[2][4][4];
#pragma unroll
        for (int mt = 0; mt < 2; mt++) {
            int i0 = q0 + wid * 32 + mt * 16 + (lane >> 2);
            int i1 = i0 + 8;
            if (needMask) {
#pragma unroll
                for (int nt = 0; nt < 8; nt++) {
                    int j = c + nt * 8 + (lane & 3) * 2;
                    if (j     > i0 || j     < i0 - WINDOW) S[mt][nt][0] = NEGINF;
                    if (j + 1 > i0 || j + 1 < i0 - WINDOW) S[mt][nt][1] = NEGINF;
                    if (j     > i1 || j     < i1 - WINDOW) S[mt][nt][2] = NEGINF;
                    if (j + 1 > i1 || j + 1 < i1 - WINDOW) S[mt][nt][3] = NEGINF;
                }
            }
#pragma unroll
            for (int half = 0; half < 2; half++) {
                float cm = NEGINF;
#pragma unroll
                for (int nt = 0; nt < 8; nt++)
                    cm = fmaxf(cm, fmaxf(S[mt][nt][half * 2], S[mt][nt][half * 2 + 1]));
                cm = fmaxf(cm, __shfl_xor_sync(0xffffffffu, cm, 1));
                cm = fmaxf(cm, __shfl_xor_sync(0xffffffffu, cm, 2));
                float mold = mrow[mt][half];
                float mnew = fmaxf(mold, cm);
                float corr = __expf(mold - mnew);
                mrow[mt][half] = mnew;
                float psum = 0.0f;
#pragma unroll
                for (int nt = 0; nt < 8; nt++) {
                    float p0 = __expf(S[mt][nt][half * 2]     - mnew);
                    float p1 = __expf(S[mt][nt][half * 2 + 1] - mnew);
                    psum += p0 + p1;
                    O[mt][nt][half * 2]     *= corr;
                    O[mt][nt][half * 2 + 1] *= corr;
                    int kt = nt >> 1, hh = nt & 1;
                    Phi[mt][kt][hh * 2 + half] = packh(p0, p1);
                }
                psum += __shfl_xor_sync(0xffffffffu, psum, 1);
                psum += __shfl_xor_sync(0xffffffffu, psum, 2);
                lrow[mt][half] = lrow[mt][half] * corr + psum;
            }
        }

#pragma unroll
        for (int kt = 0; kt < 4; kt++) {
#pragma unroll
            for (int np = 0; np < 4; np++) {
                int g = lane >> 3;
                int key = kt * 16 + (g & 1) * 8 + (lane & 7);
                int nb  = np * 32 + ((g >> 1) << 4);
                uint32_t sw = swz128((uint32_t)(key * 128 + nb));
                uint32_t vf[4];
                ldmatrix_x4t(vf[0], vf[1], vf[2], vf[3], kvb + 8192 + sw);
#pragma unroll
                for (int mt = 0; mt < 2; mt++)
#pragma unroll
                    for (int half = 0; half < 2; half++) {
                        int nt = np * 2 + half;
                        mma16816h(O[mt][nt], Phi[mt][kt], vf[half * 2], vf[half * 2 + 1]);
                    }
            }
        }
        __syncthreads();
    }

    // normalize + write o16 (single fp16)
#pragma unroll
    for (int mt = 0; mt < 2; mt++) {
        size_t rA = rowbase + wid * 32 + mt * 16 + (lane >> 2);
        size_t rB = rA + 8;
        float inv0 = 1.0f / lrow[mt][0];
        float inv1 = 1.0f / lrow[mt][1];
#pragma unroll
        for (int nt = 0; nt < 8; nt++) {
            int col = hoff + nt * 8 + (lane & 3) * 2;
            *reinterpret_cast<uint32_t*>(o16 + rA * D_MODEL + col) =
                packh(O[mt][nt][0] * inv0, O[mt][nt][1] * inv0);
            *reinterpret_cast<uint32_t*>(o16 + rB * D_MODEL + col) =
                packh(O[mt][nt][2] * inv1, O[mt][nt][3] * inv1);
        }
    }
}

// ---------------------------------------------------------------------------
// Launch.  Inputs: x, Wq, bq, Wk, bk, Wv, bv, Wo, bo
// ---------------------------------------------------------------------------
extern "C" void kernel_launch(void* const* d_in, const int* in_sizes, int n_in,
                              void* d_out, int out_size)
{
    const float* x  = (const float*)d_in[0];
    const float* Wq = (const float*)d_in[1];
    const float* bq = (const float*)d_in[2];
    const float* Wk = (const float*)d_in[3];
    const float* bk = (const float*)d_in[4];
    const float* Wv = (const float*)d_in[5];
    const float* bv = (const float*)d_in[6];
    const float* Wo = (const float*)d_in[7];
    const float* bo = (const float*)d_in[8];
    float* out = (float*)d_out;

    __half *acat, *bcat, *q16, *k16, *v16, *o16;
    cudaGetSymbolAddress((void**)&acat, g_acat);
    cudaGetSymbolAddress((void**)&bcat, g_bcat);
    cudaGetSymbolAddress((void**)&q16, g_q16);
    cudaGetSymbolAddress((void**)&k16, g_k16);
    cudaGetSymbolAddress((void**)&v16, g_v16);
    cudaGetSymbolAddress((void**)&o16, g_o16);

    cudaFuncSetAttribute(qkv_mma_kernel,
                         cudaFuncAttributeMaxDynamicSharedMemorySize, QKV_SMEM_BYTES);
    cudaFuncSetAttribute(oproj_mma_kernel,
                         cudaFuncAttributeMaxDynamicSharedMemorySize, OPJ_SMEM_BYTES);
    cudaFuncSetAttribute(attn_tc_kernel,
                         cudaFuncAttributeMaxDynamicSharedMemorySize, ATT_SMEM);

    const size_t WSTRIDE = (size_t)D_MODEL * D_MODEL;

    convA_kernel<<<M_TOT * D_MODEL / 4 / 256, 256>>>(x, acat);
    dim3 cw_grid(32, 32, 4), cw_blk(32, 8);
    convW4_kernel<<<cw_grid, cw_blk>>>(Wq, Wk, Wv, Wo, bcat);

    // fused QKV projections -> fp16 (Q pre-scaled by 0.125)
    dim3 qkv_grid(24, 32);
    qkv_mma_kernel<<<qkv_grid, 256, QKV_SMEM_BYTES>>>(acat, bcat, bq, bk, bv,
                                                      q16, k16, v16);

    // tensor-core windowed attention -> single-fp16 o16
    dim3 attn_grid(SEQ / 128, NHEADS, BATCH);    // (16, 16, 2)
    attn_tc_kernel<<<attn_grid, 128, ATT_SMEM>>>(q16, k16, v16, o16);

    // output projection (single-term) -> fp32
    dim3 o_grid(8, 32);
    oproj_mma_kernel<<<o_grid, 256, OPJ_SMEM_BYTES>>>(o16, bcat + 3 * WSTRIDE, bo, out);
}

// round 16
// speedup vs baseline: 2.2528x; 1.0512x over previous
#include <cuda_runtime.h>
#include <cuda_fp16.h>
#include <cstdint>
#include <math.h>

// ---------------------------------------------------------------------------
// Problem constants
// ---------------------------------------------------------------------------
#define D_MODEL 1024
#define NHEADS  16
#define HDIM    64
#define WINDOW  256
#define BATCH   2
#define SEQ     2048
#define M_TOT   (BATCH * SEQ)     // 4096
#define ACAT_W  2048              // [hi | lo] fp16 A-split width
#define NCHUNK  16                // 16 k-chunks of 64

// ---------------------------------------------------------------------------
// Scratch (no cudaMalloc allowed)
// ---------------------------------------------------------------------------
__device__ __half g_acat[(size_t)M_TOT * ACAT_W];        // [4096][2048] fp16
__device__ __half g_bcat[4][(size_t)D_MODEL * D_MODEL];  // [1024 n][1024 k] fp16
__device__ __half g_q16[(size_t)M_TOT * D_MODEL];
__device__ __half g_k16[(size_t)M_TOT * D_MODEL];
__device__ __half g_v16[(size_t)M_TOT * D_MODEL];
__device__ __half g_o16[(size_t)M_TOT * D_MODEL];        // attn output, single fp16

// ---------------------------------------------------------------------------
// Helpers
// ---------------------------------------------------------------------------
__device__ __forceinline__ uint32_t smem_u32(const void* p) {
    uint32_t a;
    asm("{ .reg .u64 t; cvta.to.shared.u64 t, %1; cvt.u32.u64 %0, t; }" : "=r"(a) : "l"(p));
    return a;
}
__device__ __forceinline__ uint32_t swz128(uint32_t off) {
    return off ^ ((off >> 3) & 0x70);
}
__device__ __forceinline__ void cp_async16(uint32_t saddr, const void* gaddr) {
    asm volatile("cp.async.cg.shared.global [%0], [%1], 16;" :: "r"(saddr), "l"(gaddr));
}
__device__ __forceinline__ void cp_commit() {
    asm volatile("cp.async.commit_group;" ::: "memory");
}
__device__ __forceinline__ void cp_wait1() {
    asm volatile("cp.async.wait_group 1;" ::: "memory");
}
__device__ __forceinline__ void cp_wait0() {
    asm volatile("cp.async.wait_group 0;" ::: "memory");
}
__device__ __forceinline__ void ldmatrix_x4(uint32_t& r0, uint32_t& r1,
                                            uint32_t& r2, uint32_t& r3, uint32_t addr) {
    asm volatile("ldmatrix.sync.aligned.m8n8.x4.shared.b16 {%0,%1,%2,%3}, [%4];"
                 : "=r"(r0), "=r"(r1), "=r"(r2), "=r"(r3) : "r"(addr));
}
__device__ __forceinline__ void ldmatrix_x4t(uint32_t& r0, uint32_t& r1,
                                             uint32_t& r2, uint32_t& r3, uint32_t addr) {
    asm volatile("ldmatrix.sync.aligned.m8n8.x4.trans.shared.b16 {%0,%1,%2,%3}, [%4];"
                 : "=r"(r0), "=r"(r1), "=r"(r2), "=r"(r3) : "r"(addr));
}
// fp16 MMA, fp32 accum
__device__ __forceinline__ void mma16816h(float* d, const uint32_t* a,
                                          uint32_t b0, uint32_t b1) {
    asm volatile(
        "mma.sync.aligned.m16n8k16.row.col.f32.f16.f16.f32 "
        "{%0,%1,%2,%3}, {%4,%5,%6,%7}, {%8,%9}, {%0,%1,%2,%3};"
        : "+f"(d[0]), "+f"(d[1]), "+f"(d[2]), "+f"(d[3])
        : "r"(a[0]), "r"(a[1]), "r"(a[2]), "r"(a[3]), "r"(b0), "r"(b1));
}
__device__ __forceinline__ uint32_t packh(float a, float b) {
    __half2 h = __floats2half2_rn(a, b);
    return *reinterpret_cast<uint32_t*>(&h);
}
__device__ __forceinline__ float ex2(float x) {
    float y;
    asm("ex2.approx.f32 %0, %1;" : "=f"(y) : "f"(x));
    return y;
}

// ---------------------------------------------------------------------------
// Fused conversion kernel (one launch):
//   blocks [0, 4096): convA — x [M,1024] fp32 -> acat [M,2048] = [hi | lo]
//   blocks [4096, 8192): convW — W_z [k][n] fp32 -> B_z [n][1024k] fp16
// ---------------------------------------------------------------------------
__global__ __launch_bounds__(256) void conv_fused_kernel(
    const float* __restrict__ x,
    const float* __restrict__ W0, const float* __restrict__ W1,
    const float* __restrict__ W2, const float* __restrict__ W3,
    __half* __restrict__ acat, __half* __restrict__ Bbase)
{
    __shared__ float tile[32][33];
    const int tid = threadIdx.x;
    const int bx = blockIdx.x;

    if (bx < 4096) {
        int idx = bx * 256 + tid;
        float4 v = reinterpret_cast<const float4*>(x)[idx];
        int row = idx >> 8;
        int c4  = idx & 255;

        __half hx = __float2half(v.x), hy = __float2half(v.y);
        __half hz = __float2half(v.z), hw = __float2half(v.w);
        float lx = v.x - __half2float(hx), ly = v.y - __half2float(hy);
        float lz = v.z - __half2float(hz), lw = v.w - __half2float(hw);

        __half* r = acat + (size_t)row * ACAT_W;
        uint32_t* p0 = reinterpret_cast<uint32_t*>(r) + c4 * 2;
        __half2 h0; h0.x = hx; h0.y = hy;
        __half2 h1; h1.x = hz; h1.y = hw;
        p0[0] = *reinterpret_cast<uint32_t*>(&h0);
        p0[1] = *reinterpret_cast<uint32_t*>(&h1);
        uint32_t* p1 = reinterpret_cast<uint32_t*>(r + D_MODEL) + c4 * 2;
        p1[0] = packh(lx, ly);
        p1[1] = packh(lz, lw);
    } else {
        int rr = bx - 4096;           // 0..4095
        int w  = rr >> 10;            // matrix id 0..3
        int rem = rr & 1023;
        int n0 = (rem & 31) * 32;
        int k0 = (rem >> 5) * 32;
        const float* W = (w == 0) ? W0 : (w == 1) ? W1 : (w == 2) ? W2 : W3;
        __half* B = Bbase + (size_t)w * D_MODEL * D_MODEL;

        int tx = tid & 31, ty = tid >> 5;   // (32, 8)
#pragma unroll
        for (int i = 0; i < 32; i += 8)
            tile[ty + i][tx] = W[(size_t)(k0 + ty + i) * D_MODEL + n0 + tx];
        __syncthreads();
#pragma unroll
        for (int i = 0; i < 32; i += 8) {
            int n = n0 + ty + i;
            int k = k0 + tx;
            B[(size_t)n * D_MODEL + k] = __float2half(tile[tx][ty + i]);
        }
    }
}

// ---------------------------------------------------------------------------
// Shared tile loader: 128 rows x 64 fp16 (128B/row), SW128 swizzle
// ---------------------------------------------------------------------------
__device__ __forceinline__ void load_tile128(uint32_t dst, const __half* src,
                                             int row0, int col0, int stride, int tid)
{
#pragma unroll
    for (int it = 0; it < 4; it++) {
        int idx = it * 256 + tid;
        int row = idx >> 3;
        int seg = (idx & 7) << 4;
        uint32_t sw = swz128((uint32_t)(row * 128 + seg));
        cp_async16(dst + sw,
                   reinterpret_cast<const char*>(src + (size_t)(row0 + row) * stride + col0) + seg);
    }
}

// ---------------------------------------------------------------------------
// QKV GEMM: fused fp16.
//   matid 0 (Q), 1 (K): SINGLE-term (Ah*W).  matid 2 (V): 2-term.
// Q epilogue scale folds 1/sqrt(hd) AND log2(e) so attention can use exp2.
// ---------------------------------------------------------------------------
#define GSET 49152
#define QKV_SMEM_BYTES (2 * GSET + 1024)
#define QSCALE (0.125f * 1.44269504088896f)

__global__ __launch_bounds__(256, 2) void qkv_mma_kernel(
    const __half* __restrict__ A, const __half* __restrict__ Bc,
    const float* __restrict__ bq, const float* __restrict__ bk, const float* __restrict__ bv,
    __half* __restrict__ q16, __half* __restrict__ k16, __half* __restrict__ v16)
{
    extern __shared__ char dynsmem[];
    uint32_t base = (smem_u32(dynsmem) + 1023) & ~1023u;

    const int matid = blockIdx.x >> 3;
    const int n0 = (blockIdx.x & 7) * 128;
    const int m0 = blockIdx.y * 128;
    const __half* B = Bc + (size_t)matid * D_MODEL * D_MODEL;
    const float* bias = (matid == 0) ? bq : (matid == 1) ? bk : bv;
    __half* O = (matid == 0) ? q16 : (matid == 1) ? k16 : v16;
    const float scale = (matid == 0) ? QSCALE : 1.0f;
    const bool twoTerm = (matid == 2);

    const int tid = threadIdx.x;
    const int lane = tid & 31;
    const int wid = tid >> 5;
    const int warp_m = wid >> 2;
    const int warp_n = wid & 3;

    float acc[4][4][4];
#pragma unroll
    for (int i = 0; i < 4; i++)
#pragma unroll
        for (int j = 0; j < 4; j++)
#pragma unroll
            for (int r = 0; r < 4; r++) acc[i][j][r] = 0.0f;

    auto loadch = [&](int ch) {
        uint32_t s = base + (ch & 1) * GSET;
        load_tile128(s,         A, m0, ch * 64,           ACAT_W, tid);       // Ah
        if (twoTerm)
            load_tile128(s + 16384, A, m0, D_MODEL + ch * 64, ACAT_W, tid);   // Al
        load_tile128(s + 32768, B, n0, ch * 64,           D_MODEL, tid);      // W
        cp_commit();
    };

    loadch(0);

    for (int ch = 0; ch < NCHUNK; ch++) {
        cp_wait0();
        __syncthreads();
        if (ch + 1 < NCHUNK) loadch(ch + 1);

        const uint32_t sa = base + (ch & 1) * GSET;
        const uint32_t sl = sa + 16384;
        const uint32_t sw = sa + 32768;

#pragma unroll
        for (int step = 0; step < 4; step++) {
            uint32_t bfr[8];
#pragma unroll
            for (int jp = 0; jp < 2; jp++) {
                int nrow = warp_n * 32 + jp * 16 + ((lane >> 4) & 1) * 8 + (lane & 7);
                int kb   = step * 32 + ((lane >> 3) & 1) * 16;
                uint32_t addr = sw + swz128((uint32_t)(nrow * 128 + kb));
                ldmatrix_x4(bfr[jp * 4 + 0], bfr[jp * 4 + 1],
                            bfr[jp * 4 + 2], bfr[jp * 4 + 3], addr);
            }
            {
                uint32_t afr[4][4];
#pragma unroll
                for (int mt = 0; mt < 4; mt++) {
                    int row = warp_m * 64 + mt * 16 + (lane & 15);
                    int kb  = step * 32 + ((lane >> 4) << 4);
                    uint32_t addr = sa + swz128((uint32_t)(row * 128 + kb));
                    ldmatrix_x4(afr[mt][0], afr[mt][1], afr[mt][2], afr[mt][3], addr);
                }
#pragma unroll
                for (int mt = 0; mt < 4; mt++)
#pragma unroll
                    for (int nt = 0; nt < 4; nt++)
                        mma16816h(acc[mt][nt], afr[mt], bfr[nt * 2], bfr[nt * 2 + 1]);
            }
            if (twoTerm) {
                uint32_t afr[4][4];
#pragma unroll
                for (int mt = 0; mt < 4; mt++) {
                    int row = warp_m * 64 + mt * 16 + (lane & 15);
                    int kb  = step * 32 + ((lane >> 4) << 4);
                    uint32_t addr = sl + swz128((uint32_t)(row * 128 + kb));
                    ldmatrix_x4(afr[mt][0], afr[mt][1], afr[mt][2], afr[mt][3], addr);
                }
#pragma unroll
                for (int mt = 0; mt < 4; mt++)
#pragma unroll
                    for (int nt = 0; nt < 4; nt++)
                        mma16816h(acc[mt][nt], afr[mt], bfr[nt * 2], bfr[nt * 2 + 1]);
            }
        }
    }

#pragma unroll
    for (int mt = 0; mt < 4; mt++) {
        int row = m0 + warp_m * 64 + mt * 16 + (lane >> 2);
#pragma unroll
        for (int nt = 0; nt < 4; nt++) {
            int col = n0 + warp_n * 32 + nt * 8 + (lane & 3) * 2;
            float b0 = bias[col], b1 = bias[col + 1];
            *reinterpret_cast<uint32_t*>(O + (size_t)row * D_MODEL + col) =
                packh((acc[mt][nt][0] + b0) * scale, (acc[mt][nt][1] + b1) * scale);
            *reinterpret_cast<uint32_t*>(O + (size_t)(row + 8) * D_MODEL + col) =
                packh((acc[mt][nt][2] + b0) * scale, (acc[mt][nt][3] + b1) * scale);
        }
    }
}

// ---------------------------------------------------------------------------
// Output projection GEMM: SINGLE-term fp16, 3-stage cp.async pipeline.
// ---------------------------------------------------------------------------
#define OSET 32768
#define OPJ_SMEM_BYTES (3 * OSET + 1024)

__global__ __launch_bounds__(256, 2) void oproj_mma_kernel(
    const __half* __restrict__ A, const __half* __restrict__ B,
    const float* __restrict__ bias, float* __restrict__ C)
{
    extern __shared__ char dynsmem[];
    uint32_t base = (smem_u32(dynsmem) + 1023) & ~1023u;

    const int n0 = blockIdx.x * 128;
    const int m0 = blockIdx.y * 128;

    const int tid = threadIdx.x;
    const int lane = tid & 31;
    const int wid = tid >> 5;
    const int warp_m = wid >> 2;
    const int warp_n = wid & 3;

    float acc[4][4][4];
#pragma unroll
    for (int i = 0; i < 4; i++)
#pragma unroll
        for (int j = 0; j < 4; j++)
#pragma unroll
            for (int r = 0; r < 4; r++) acc[i][j][r] = 0.0f;

    auto loadch = [&](int ch, int s) {
        uint32_t sb = base + s * OSET;
        load_tile128(sb,         A, m0, ch * 64, D_MODEL, tid);
        load_tile128(sb + 16384, B, n0, ch * 64, D_MODEL, tid);
        cp_commit();
    };

    loadch(0, 0);
    loadch(1, 1);

    int scur = 0, snext = 2;
    for (int ch = 0; ch < NCHUNK; ch++) {
        if (ch + 1 < NCHUNK) cp_wait1(); else cp_wait0();
        __syncthreads();
        if (ch + 2 < NCHUNK) loadch(ch + 2, snext);

        const uint32_t sa = base + scur * OSET;
        const uint32_t sw = sa + 16384;

#pragma unroll
        for (int step = 0; step < 4; step++) {
            uint32_t afr[4][4];
#pragma unroll
            for (int mt = 0; mt < 4; mt++) {
                int row = warp_m * 64 + mt * 16 + (lane & 15);
                int kb  = step * 32 + ((lane >> 4) << 4);
                uint32_t addr = sa + swz128((uint32_t)(row * 128 + kb));
                ldmatrix_x4(afr[mt][0], afr[mt][1], afr[mt][2], afr[mt][3], addr);
            }
            uint32_t bfr[8];
#pragma unroll
            for (int jp = 0; jp < 2; jp++) {
                int nrow = warp_n * 32 + jp * 16 + ((lane >> 4) & 1) * 8 + (lane & 7);
                int kb   = step * 32 + ((lane >> 3) & 1) * 16;
                uint32_t addr = sw + swz128((uint32_t)(nrow * 128 + kb));
                ldmatrix_x4(bfr[jp * 4 + 0], bfr[jp * 4 + 1],
                            bfr[jp * 4 + 2], bfr[jp * 4 + 3], addr);
            }
#pragma unroll
            for (int mt = 0; mt < 4; mt++)
#pragma unroll
                for (int nt = 0; nt < 4; nt++)
                    mma16816h(acc[mt][nt], afr[mt], bfr[nt * 2], bfr[nt * 2 + 1]);
        }

        scur = (scur == 2) ? 0 : scur + 1;
        snext = (snext == 2) ? 0 : snext + 1;
    }

#pragma unroll
    for (int mt = 0; mt < 4; mt++) {
        int row = m0 + warp_m * 64 + mt * 16 + (lane >> 2);
#pragma unroll
        for (int nt = 0; nt < 4; nt++) {
            int col = n0 + warp_n * 32 + nt * 8 + (lane & 3) * 2;
            float b0 = bias[col], b1 = bias[col + 1];
            float2 w0; w0.x = acc[mt][nt][0] + b0; w0.y = acc[mt][nt][1] + b1;
            float2 w1; w1.x = acc[mt][nt][2] + b0; w1.y = acc[mt][nt][3] + b1;
            *reinterpret_cast<float2*>(C + (size_t)row * D_MODEL + col) = w0;
            *reinterpret_cast<float2*>(C + (size_t)(row + 8) * D_MODEL + col) = w1;
        }
    }
}

// ---------------------------------------------------------------------------
// Tensor-core windowed attention, STATIC-SCALE softmax (no running max):
// logits come pre-scaled by log2(e)/8 (folded into Q), so p = exp2(S) directly.
// Bounded logits => no overflow; masked entries are -inf => exp2 gives 0.
// l accumulated per-thread, reduced once at the end. Output: fp16 o16.
// ---------------------------------------------------------------------------
#define ATT_SMEM (48 * 1024 + 1024)

__global__ __launch_bounds__(128) void attn_tc_kernel(
    const __half* __restrict__ q16, const __half* __restrict__ k16,
    const __half* __restrict__ v16, __half* __restrict__ o16)
{
    extern __shared__ char dynsmem[];
    uint32_t base = (smem_u32(dynsmem) + 1023) & ~1023u;
    const uint32_t Qs  = base;                 // 16KB
    const uint32_t KV0 = base + 16384;         // K @ +0 (8KB), V @ +8192
    const uint32_t KV1 = base + 32768;

    const int tid = threadIdx.x, wid = tid >> 5, lane = tid & 31;
    const int q0 = blockIdx.x * 128;
    const int h  = blockIdx.y;
    const int b  = blockIdx.z;
    const size_t rowbase = (size_t)b * SEQ + q0;
    const int hoff = h * HDIM;

    {
        const char* qp = reinterpret_cast<const char*>(q16 + rowbase * D_MODEL + hoff);
#pragma unroll
        for (int it = 0; it < 8; it++) {
            int idx = it * 128 + tid;
            int row = idx >> 3;
            int seg = (idx & 7) << 4;
            uint32_t sw = swz128((uint32_t)(row * 128 + seg));
            cp_async16(Qs + sw, qp + (size_t)row * 2048 + seg);
        }
        cp_commit();
    }

    int c0 = q0 - WINDOW; if (c0 < 0) c0 = 0;
    const int nch = (q0 + 128 - c0) >> 6;

    auto load_kv = [&](int c, uint32_t kvb) {
        const char* kp = reinterpret_cast<const char*>(k16 + ((size_t)b * SEQ + c) * D_MODEL + hoff);
        const char* vp = reinterpret_cast<const char*>(v16 + ((size_t)b * SEQ + c) * D_MODEL + hoff);
#pragma unroll
        for (int it = 0; it < 4; it++) {
            int idx = it * 128 + tid;
            int row = idx >> 3;
            int seg = (idx & 7) << 4;
            uint32_t sw = swz128((uint32_t)(row * 128 + seg));
            size_t go = (size_t)row * 2048 + seg;
            cp_async16(kvb + 0    + sw, kp + go);
            cp_async16(kvb + 8192 + sw, vp + go);
        }
        cp_commit();
    };

    load_kv(c0, KV0);

    float O[2][8][4];
#pragma unroll
    for (int mt = 0; mt < 2; mt++)
#pragma unroll
        for (int nt = 0; nt < 8; nt++)
#pragma unroll
            for (int r = 0; r < 4; r++) O[mt][nt][r] = 0.0f;
    float lrow[2][2] = {{0.f, 0.f}, {0.f, 0.f}};

    const float NEGINF = __int_as_float(0xff800000);

    for (int ch = 0; ch < nch; ch++) {
        const uint32_t kvb = (ch & 1) ? KV1 : KV0;
        if (ch + 1 < nch) {
            load_kv(c0 + (ch + 1) * 64, (ch & 1) ? KV0 : KV1);
            cp_wait1();
        } else {
            cp_wait0();
        }
        __syncthreads();

        const int c = c0 + ch * 64;
        const bool needMask = (c + 63 >= q0) || (c < q0 + 128 - WINDOW);

        float S[2][8][4];
#pragma unroll
        for (int mt = 0; mt < 2; mt++)
#pragma unroll
            for (int nt = 0; nt < 8; nt++)
#pragma unroll
                for (int r = 0; r < 4; r++) S[mt][nt][r] = 0.0f;

#pragma unroll
        for (int kt = 0; kt < 4; kt++) {
            uint32_t qa[2][4];
#pragma unroll
            for (int mt = 0; mt < 2; mt++) {
                int row = wid * 32 + mt * 16 + (lane & 15);
                int kb  = kt * 32 + ((lane >> 4) << 4);
                uint32_t sw = swz128((uint32_t)(row * 128 + kb));
                ldmatrix_x4(qa[mt][0], qa[mt][1], qa[mt][2], qa[mt][3], Qs + sw);
            }
#pragma unroll
            for (int np = 0; np < 4; np++) {
                int nr = np * 16 + ((lane >> 4) & 1) * 8 + (lane & 7);
                int kb = kt * 32 + ((lane >> 3) & 1) * 16;
                uint32_t sw = swz128((uint32_t)(nr * 128 + kb));
                uint32_t kf[4];
                ldmatrix_x4(kf[0], kf[1], kf[2], kf[3], kvb + 0 + sw);
#pragma unroll
                for (int mt = 0; mt < 2; mt++)
#pragma unroll
                    for (int half = 0; half < 2; half++) {
                        int nt = np * 2 + half;
                        mma16816h(S[mt][nt], qa[mt], kf[half * 2], kf[half * 2 + 1]);
                    }
            }
        }

        // ---- static-scale softmax: p = exp2(S); masked -> -inf -> 0 ----
        uint32_t Phi[2][4][4];
#pragma unroll
        for (int mt = 0; mt < 2; mt++) {
            if (needMask) {
                int i0 = q0 + wid * 32 + mt * 16 + (lane >> 2);
                int i1 = i0 + 8;
#pragma unroll
                for (int nt = 0; nt < 8; nt++) {
                    int j = c + nt * 8 + (lane & 3) * 2;
                    if (j     > i0 || j     < i0 - WINDOW) S[mt][nt][0] = NEGINF;
                    if (j + 1 > i0 || j + 1 < i0 - WINDOW) S[mt][nt][1] = NEGINF;
                    if (j     > i1 || j     < i1 - WINDOW) S[mt][nt][2] = NEGINF;
                    if (j + 1 > i1 || j + 1 < i1 - WINDOW) S[mt][nt][3] = NEGINF;
                }
            }
#pragma unroll
            for (int half = 0; half < 2; half++) {
                float psum = 0.0f;
#pragma unroll
                for (int nt = 0; nt < 8; nt++) {
                    float p0 = ex2(S[mt][nt][half * 2]);
                    float p1 = ex2(S[mt][nt][half * 2 + 1]);
                    psum += p0 + p1;
                    int kt = nt >> 1, hh = nt & 1;
                    Phi[mt][kt][hh * 2 + half] = packh(p0, p1);
                }
                lrow[mt][half] += psum;
            }
        }

#pragma unroll
        for (int kt = 0; kt < 4; kt++) {
#pragma unroll
            for (int np = 0; np < 4; np++) {
                int g = lane >> 3;
                int key = kt * 16 + (g & 1) * 8 + (lane & 7);
                int nb  = np * 32 + ((g >> 1) << 4);
                uint32_t sw = swz128((uint32_t)(key * 128 + nb));
                uint32_t vf[4];
                ldmatrix_x4t(vf[0], vf[1], vf[2], vf[3], kvb + 8192 + sw);
#pragma unroll
                for (int mt = 0; mt < 2; mt++)
#pragma unroll
                    for (int half = 0; half < 2; half++) {
                        int nt = np * 2 + half;
                        mma16816h(O[mt][nt], Phi[mt][kt], vf[half * 2], vf[half * 2 + 1]);
                    }
            }
        }
        __syncthreads();
    }

    // final l reduction (once) + normalize + write o16
#pragma unroll
    for (int mt = 0; mt < 2; mt++) {
        float l0 = lrow[mt][0];
        l0 += __shfl_xor_sync(0xffffffffu, l0, 1);
        l0 += __shfl_xor_sync(0xffffffffu, l0, 2);
        float l1 = lrow[mt][1];
        l1 += __shfl_xor_sync(0xffffffffu, l1, 1);
        l1 += __shfl_xor_sync(0xffffffffu, l1, 2);
        float inv0 = 1.0f / l0;
        float inv1 = 1.0f / l1;

        size_t rA = rowbase + wid * 32 + mt * 16 + (lane >> 2);
        size_t rB = rA + 8;
#pragma unroll
        for (int nt = 0; nt < 8; nt++) {
            int col = hoff + nt * 8 + (lane & 3) * 2;
            *reinterpret_cast<uint32_t*>(o16 + rA * D_MODEL + col) =
                packh(O[mt][nt][0] * inv0, O[mt][nt][1] * inv0);
            *reinterpret_cast<uint32_t*>(o16 + rB * D_MODEL + col) =
                packh(O[mt][nt][2] * inv1, O[mt][nt][3] * inv1);
        }
    }
}

// ---------------------------------------------------------------------------
// Launch.  Inputs: x, Wq, bq, Wk, bk, Wv, bv, Wo, bo
// ---------------------------------------------------------------------------
extern "C" void kernel_launch(void* const* d_in, const int* in_sizes, int n_in,
                              void* d_out, int out_size)
{
    const float* x  = (const float*)d_in[0];
    const float* Wq = (const float*)d_in[1];
    const float* bq = (const float*)d_in[2];
    const float* Wk = (const float*)d_in[3];
    const float* bk = (const float*)d_in[4];
    const float* Wv = (const float*)d_in[5];
    const float* bv = (const float*)d_in[6];
    const float* Wo = (const float*)d_in[7];
    const float* bo = (const float*)d_in[8];
    float* out = (float*)d_out;

    __half *acat, *bcat, *q16, *k16, *v16, *o16;
    cudaGetSymbolAddress((void**)&acat, g_acat);
    cudaGetSymbolAddress((void**)&bcat, g_bcat);
    cudaGetSymbolAddress((void**)&q16, g_q16);
    cudaGetSymbolAddress((void**)&k16, g_k16);
    cudaGetSymbolAddress((void**)&v16, g_v16);
    cudaGetSymbolAddress((void**)&o16, g_o16);

    cudaFuncSetAttribute(qkv_mma_kernel,
                         cudaFuncAttributeMaxDynamicSharedMemorySize, QKV_SMEM_BYTES);
    cudaFuncSetAttribute(oproj_mma_kernel,
                         cudaFuncAttributeMaxDynamicSharedMemorySize, OPJ_SMEM_BYTES);
    cudaFuncSetAttribute(attn_tc_kernel,
                         cudaFuncAttributeMaxDynamicSharedMemorySize, ATT_SMEM);

    const size_t WSTRIDE = (size_t)D_MODEL * D_MODEL;

    // fused conversions (x-split + 4 weight transposes) in one launch
    conv_fused_kernel<<<8192, 256>>>(x, Wq, Wk, Wv, Wo, acat, bcat);

    // fused QKV projections -> fp16 (Q pre-scaled by 0.125*log2e)
    dim3 qkv_grid(24, 32);
    qkv_mma_kernel<<<qkv_grid, 256, QKV_SMEM_BYTES>>>(acat, bcat, bq, bk, bv,
                                                      q16, k16, v16);

    // tensor-core windowed attention -> single-fp16 o16
    dim3 attn_grid(SEQ / 128, NHEADS, BATCH);    // (16, 16, 2)
    attn_tc_kernel<<<attn_grid, 128, ATT_SMEM>>>(q16, k16, v16, o16);

    // output projection (single-term) -> fp32
    dim3 o_grid(8, 32);
    oproj_mma_kernel<<<o_grid, 256, OPJ_SMEM_BYTES>>>(o16, bcat + 3 * WSTRIDE, bo, out);
}